// round 2
// baseline (speedup 1.0000x reference)
#include <cuda_runtime.h>
#include <math.h>

// Problem dims
#define NB 8
#define NL 1024
#define ND 512
#define NH 8
#define NDH 64

#define TOK (NB * NL)                 // 8192 rows
#define ACT_ELEMS ((size_t)TOK * ND)  // 4,194,304
#define ATT_ELEMS ((size_t)NB * NH * NL * NL) // 67,108,864

// Scratch (static device arrays — no allocation at runtime)
__device__ float g_Q[ACT_ELEMS];
__device__ float g_K[ACT_ELEMS];
__device__ float g_V[ACT_ELEMS];
__device__ float g_ctx[ACT_ELEMS];
__device__ float g_proj[ACT_ELEMS];
__device__ int   g_mask_mode; // 0 = uint8, 1 = int32, 2 = float32

// ---------------------------------------------------------------------------
// Mask dtype detection: jax bool may arrive as u8 / i32 / f32. Inspect words.
// f32 1.0f = 0x3f800000; i32 words are only 0/1; u8-packed words show bytes
// set above byte0 with overwhelming probability over 4096 words @10% density.
// ---------------------------------------------------------------------------
__global__ void detect_mask_kernel(const unsigned int* __restrict__ m) {
    __shared__ int f32flag, u8flag;
    if (threadIdx.x == 0) { f32flag = 0; u8flag = 0; }
    __syncthreads();
    int lf = 0, lu = 0;
    for (int i = threadIdx.x; i < 4096; i += blockDim.x) {
        unsigned w = m[i];
        if (w == 0x3f800000u) lf = 1;
        else if (w > 1u) lu = 1;
    }
    if (lf) atomicOr(&f32flag, 1);
    if (lu) atomicOr(&u8flag, 1);
    __syncthreads();
    if (threadIdx.x == 0) g_mask_mode = f32flag ? 2 : (u8flag ? 0 : 1);
}

__device__ __forceinline__ bool mask_at(const void* m, size_t idx, int mode) {
    if (mode == 0) return ((const unsigned char*)m)[idx] != 0;
    if (mode == 1) return ((const int*)m)[idx] != 0;
    return ((const float*)m)[idx] != 0.0f;
}

// ---------------------------------------------------------------------------
// GEMM: C[M,512] = A[M,512] @ W[512,512]^T   (C[m,n] = sum_k A[m,k] W[n,k])
// 128x128 block tile, BK=16, 8x8 microtile, 256 threads.
// ---------------------------------------------------------------------------
__global__ void __launch_bounds__(256) gemm_xwt_kernel(
    const float* __restrict__ A, const float* __restrict__ W,
    float* __restrict__ C)
{
    __shared__ float As[16 * 132];
    __shared__ float Bs[16 * 132];
    const int m0 = blockIdx.x * 128;
    const int n0 = blockIdx.y * 128;
    const int tid = threadIdx.x;
    const int tx = tid & 15;
    const int ty = tid >> 4;
    const int lr = tid >> 2;         // 0..63
    const int lc = (tid & 3) << 2;   // 0,4,8,12

    float acc[8][8];
#pragma unroll
    for (int i = 0; i < 8; i++)
#pragma unroll
        for (int j = 0; j < 8; j++) acc[i][j] = 0.0f;

    for (int k0 = 0; k0 < 512; k0 += 16) {
        float4 a0 = *(const float4*)&A[(size_t)(m0 + lr) * 512 + k0 + lc];
        float4 a1 = *(const float4*)&A[(size_t)(m0 + lr + 64) * 512 + k0 + lc];
        float4 b0 = *(const float4*)&W[(size_t)(n0 + lr) * 512 + k0 + lc];
        float4 b1 = *(const float4*)&W[(size_t)(n0 + lr + 64) * 512 + k0 + lc];
        __syncthreads();
        As[(lc + 0) * 132 + lr] = a0.x;  As[(lc + 1) * 132 + lr] = a0.y;
        As[(lc + 2) * 132 + lr] = a0.z;  As[(lc + 3) * 132 + lr] = a0.w;
        As[(lc + 0) * 132 + lr + 64] = a1.x;  As[(lc + 1) * 132 + lr + 64] = a1.y;
        As[(lc + 2) * 132 + lr + 64] = a1.z;  As[(lc + 3) * 132 + lr + 64] = a1.w;
        Bs[(lc + 0) * 132 + lr] = b0.x;  Bs[(lc + 1) * 132 + lr] = b0.y;
        Bs[(lc + 2) * 132 + lr] = b0.z;  Bs[(lc + 3) * 132 + lr] = b0.w;
        Bs[(lc + 0) * 132 + lr + 64] = b1.x;  Bs[(lc + 1) * 132 + lr + 64] = b1.y;
        Bs[(lc + 2) * 132 + lr + 64] = b1.z;  Bs[(lc + 3) * 132 + lr + 64] = b1.w;
        __syncthreads();
#pragma unroll
        for (int k = 0; k < 16; k++) {
            float4 af0 = *(const float4*)&As[k * 132 + ty * 8];
            float4 af1 = *(const float4*)&As[k * 132 + ty * 8 + 4];
            float4 bf0 = *(const float4*)&Bs[k * 132 + tx * 8];
            float4 bf1 = *(const float4*)&Bs[k * 132 + tx * 8 + 4];
            float a[8] = {af0.x, af0.y, af0.z, af0.w, af1.x, af1.y, af1.z, af1.w};
            float b[8] = {bf0.x, bf0.y, bf0.z, bf0.w, bf1.x, bf1.y, bf1.z, bf1.w};
#pragma unroll
            for (int i = 0; i < 8; i++)
#pragma unroll
                for (int j = 0; j < 8; j++)
                    acc[i][j] += a[i] * b[j];
        }
    }
#pragma unroll
    for (int i = 0; i < 8; i++) {
        float4 v0 = make_float4(acc[i][0], acc[i][1], acc[i][2], acc[i][3]);
        float4 v1 = make_float4(acc[i][4], acc[i][5], acc[i][6], acc[i][7]);
        size_t off = (size_t)(m0 + ty * 8 + i) * 512 + n0 + tx * 8;
        *(float4*)&C[off] = v0;
        *(float4*)&C[off + 4] = v1;
    }
}

// ---------------------------------------------------------------------------
// Fused attention: per (b,h, 32-row q-tile):
//   scores (QK^T) -> smem [32 x 1024] -> masked softmax -> softmax_mask ->
//   write attention to gmem -> context = attn @ V -> g_ctx
// smem: sc 32*1025 + qs 32*65 + kv 128*68 floats = 174,336 bytes
// ---------------------------------------------------------------------------
#define SC_STR 1025
#define QK_STR 65
#define V_STR  68
#define ATTN_SMEM_FLOATS (32 * SC_STR + 32 * QK_STR + 128 * V_STR)

__global__ void __launch_bounds__(256) attn_kernel(
    const void* __restrict__ amask, const void* __restrict__ smask,
    float* __restrict__ att)
{
    extern __shared__ float sm[];
    float* sc = sm;                       // 32 x 1025
    float* qs = sm + 32 * SC_STR;         // 32 x 65
    float* kv = qs + 32 * QK_STR;         // 128 x 65 (K) / 128 x 68 (V)

    const int bh = blockIdx.x;            // 0..63
    const int b = bh >> 3, h = bh & 7;
    const int q0 = blockIdx.y * 32;
    const int tid = threadIdx.x;
    const int mode = g_mask_mode;
    const size_t head_base = ((size_t)b * NL) * ND + (size_t)h * NDH;

    // Q tile -> smem
    for (int i = tid; i < 32 * 64; i += 256) {
        int r = i >> 6, d = i & 63;
        qs[r * QK_STR + d] = g_Q[head_base + (size_t)(q0 + r) * ND + d];
    }

    // ---- scores: 4 qi x 4 kj microtile per thread, chunks of 128 k ----
    const int qb = (tid >> 5) * 4;   // warp id * 4 -> rows (broadcast in warp)
    const int kb = tid & 31;         // kj = kb + 32*j (conflict-free, pad 65)
    for (int kc = 0; kc < NL; kc += 128) {
        __syncthreads();
        for (int i = tid; i < 128 * 64; i += 256) {
            int r = i >> 6, d = i & 63;
            kv[r * QK_STR + d] = g_K[head_base + (size_t)(kc + r) * ND + d];
        }
        __syncthreads();
        float acc[4][4];
#pragma unroll
        for (int i = 0; i < 4; i++)
#pragma unroll
            for (int j = 0; j < 4; j++) acc[i][j] = 0.0f;
#pragma unroll 4
        for (int d = 0; d < 64; d++) {
            float a0 = qs[(qb + 0) * QK_STR + d];
            float a1 = qs[(qb + 1) * QK_STR + d];
            float a2 = qs[(qb + 2) * QK_STR + d];
            float a3 = qs[(qb + 3) * QK_STR + d];
            float bb0 = kv[(kb + 0)  * QK_STR + d];
            float bb1 = kv[(kb + 32) * QK_STR + d];
            float bb2 = kv[(kb + 64) * QK_STR + d];
            float bb3 = kv[(kb + 96) * QK_STR + d];
            acc[0][0] += a0 * bb0; acc[0][1] += a0 * bb1; acc[0][2] += a0 * bb2; acc[0][3] += a0 * bb3;
            acc[1][0] += a1 * bb0; acc[1][1] += a1 * bb1; acc[1][2] += a1 * bb2; acc[1][3] += a1 * bb3;
            acc[2][0] += a2 * bb0; acc[2][1] += a2 * bb1; acc[2][2] += a2 * bb2; acc[2][3] += a2 * bb3;
            acc[3][0] += a3 * bb0; acc[3][1] += a3 * bb1; acc[3][2] += a3 * bb2; acc[3][3] += a3 * bb3;
        }
#pragma unroll
        for (int i = 0; i < 4; i++)
#pragma unroll
            for (int j = 0; j < 4; j++)
                sc[(qb + i) * SC_STR + kc + kb + 32 * j] = acc[i][j];
    }
    __syncthreads();

    // ---- masked softmax + softmax_mask + attention write (warp per 4 rows) ----
    const int w = tid >> 5, lane = tid & 31;
#pragma unroll
    for (int rr = 0; rr < 4; rr++) {
        int r = w * 4 + rr;
        size_t mrow = ((size_t)b * NL + q0 + r) * NL;
        float mx = -1e30f;
        for (int c = lane; c < NL; c += 32) {
            float s = sc[r * SC_STR + c] * 0.125f;  // DH^-0.5 = 1/8
            if (mask_at(amask, mrow + c, mode)) s = -1e30f;
            sc[r * SC_STR + c] = s;
            mx = fmaxf(mx, s);
        }
#pragma unroll
        for (int o = 16; o > 0; o >>= 1) mx = fmaxf(mx, __shfl_xor_sync(0xffffffffu, mx, o));
        float sum = 0.0f;
        for (int c = lane; c < NL; c += 32) {
            float e = expf(sc[r * SC_STR + c] - mx);
            sc[r * SC_STR + c] = e;
            sum += e;
        }
#pragma unroll
        for (int o = 16; o > 0; o >>= 1) sum += __shfl_xor_sync(0xffffffffu, sum, o);
        float inv = 1.0f / sum;
        float* arow = att ? att + ((size_t)bh * NL + q0 + r) * NL : (float*)0;
        for (int c = lane; c < NL; c += 32) {
            float v = sc[r * SC_STR + c] * inv;
            if (mask_at(smask, mrow + c, mode)) v = 0.0f;
            sc[r * SC_STR + c] = v;
            if (arow) arow[c] = v;
        }
    }

    // ---- context = attn @ V : 2 qi x 4 d per thread ----
    const int qg = tid >> 4;   // 0..15 -> rows 2qg, 2qg+1
    const int dg = tid & 15;   // d = dg*4 .. dg*4+3
    float c0x = 0, c0y = 0, c0z = 0, c0w = 0;
    float c1x = 0, c1y = 0, c1z = 0, c1w = 0;
    for (int kc = 0; kc < NL; kc += 128) {
        __syncthreads();
        for (int i = tid; i < 128 * 64; i += 256) {
            int r = i >> 6, d = i & 63;
            kv[r * V_STR + d] = g_V[head_base + (size_t)(kc + r) * ND + d];
        }
        __syncthreads();
#pragma unroll 4
        for (int kk = 0; kk < 128; kk++) {
            float a0 = sc[(qg * 2 + 0) * SC_STR + kc + kk];
            float a1 = sc[(qg * 2 + 1) * SC_STR + kc + kk];
            float4 v = *(const float4*)&kv[kk * V_STR + dg * 4];
            c0x += a0 * v.x; c0y += a0 * v.y; c0z += a0 * v.z; c0w += a0 * v.w;
            c1x += a1 * v.x; c1y += a1 * v.y; c1z += a1 * v.z; c1w += a1 * v.w;
        }
    }
    size_t o0 = head_base + (size_t)(q0 + qg * 2) * ND + dg * 4;
    *(float4*)&g_ctx[o0]      = make_float4(c0x, c0y, c0z, c0w);
    *(float4*)&g_ctx[o0 + ND] = make_float4(c1x, c1y, c1z, c1w);
}

// ---------------------------------------------------------------------------
// Residual + LayerNorm (no affine), row = one token of 512
// ---------------------------------------------------------------------------
__global__ void __launch_bounds__(256) ln_kernel(
    const float* __restrict__ proj, const float* __restrict__ res,
    float* __restrict__ out)
{
    __shared__ float reds[8], redq[8];
    const int row = blockIdx.x;
    const int tid = threadIdx.x;
    const float* p = proj + (size_t)row * ND;
    const float* r = res + (size_t)row * ND;
    float x0 = r[tid] + p[tid];
    float x1 = r[tid + 256] + p[tid + 256];
    float s = x0 + x1;
    float q = x0 * x0 + x1 * x1;
#pragma unroll
    for (int o = 16; o > 0; o >>= 1) {
        s += __shfl_xor_sync(0xffffffffu, s, o);
        q += __shfl_xor_sync(0xffffffffu, q, o);
    }
    if ((tid & 31) == 0) { reds[tid >> 5] = s; redq[tid >> 5] = q; }
    __syncthreads();
    float ts = 0, tq = 0;
#pragma unroll
    for (int i = 0; i < 8; i++) { ts += reds[i]; tq += redq[i]; }
    float mean = ts * (1.0f / ND);
    float var = tq * (1.0f / ND) - mean * mean;
    float rr = rsqrtf(var + 1e-5f);
    out[(size_t)row * ND + tid] = (x0 - mean) * rr;
    out[(size_t)row * ND + tid + 256] = (x1 - mean) * rr;
}

// ---------------------------------------------------------------------------
extern "C" void kernel_launch(void* const* d_in, const int* in_sizes, int n_in,
                              void* d_out, int out_size)
{
    const float* query = (const float*)d_in[0];
    const float* key   = (const float*)d_in[1];
    const float* value = (const float*)d_in[2];
    const void*  amask = d_in[3];
    const void*  smask = d_in[4];
    const float* Wq = (const float*)d_in[5];
    const float* Wk = (const float*)d_in[6];
    const float* Wv = (const float*)d_in[7];
    const float* Wo = (const float*)d_in[8];

    float* out = (float*)d_out;
    // Assume outputs concatenated in return order: out [B,L,D] then attention
    // [B,H,L,L]. Only write attention if d_out is actually big enough.
    float* att = ((size_t)out_size >= ACT_ELEMS + ATT_ELEMS) ? out + ACT_ELEMS
                                                             : (float*)0;

    void *pQ, *pK, *pV, *pCtx, *pProj;
    cudaGetSymbolAddress(&pQ, g_Q);
    cudaGetSymbolAddress(&pK, g_K);
    cudaGetSymbolAddress(&pV, g_V);
    cudaGetSymbolAddress(&pCtx, g_ctx);
    cudaGetSymbolAddress(&pProj, g_proj);

    const size_t smem = ATTN_SMEM_FLOATS * sizeof(float);
    cudaFuncSetAttribute(attn_kernel, cudaFuncAttributeMaxDynamicSharedMemorySize,
                         (int)smem);

    detect_mask_kernel<<<1, 256>>>((const unsigned int*)amask);

    dim3 ggrid(TOK / 128, ND / 128);
    gemm_xwt_kernel<<<ggrid, 256>>>(query, Wq, (float*)pQ);
    gemm_xwt_kernel<<<ggrid, 256>>>(key,   Wk, (float*)pK);
    gemm_xwt_kernel<<<ggrid, 256>>>(value, Wv, (float*)pV);

    attn_kernel<<<dim3(NB * NH, NL / 32), 256, smem>>>(amask, smask, att);

    gemm_xwt_kernel<<<ggrid, 256>>>((const float*)pCtx, Wo, (float*)pProj);

    ln_kernel<<<TOK, 256>>>((const float*)pProj, query, out);
}

// round 3
// speedup vs baseline: 1.7235x; 1.7235x over previous
#include <cuda_runtime.h>
#include <math.h>

// Problem dims
#define NB 8
#define NL 1024
#define ND 512
#define NH 8
#define NDH 64

#define TOK (NB * NL)                 // 8192 rows
#define ACT_ELEMS ((size_t)TOK * ND)  // 4,194,304
#define ATT_ELEMS ((size_t)NB * NH * NL * NL) // 67,108,864

// Scratch (static device arrays — no allocation at runtime)
__device__ float g_Q[ACT_ELEMS];
__device__ float g_K[ACT_ELEMS];
__device__ float g_V[ACT_ELEMS];
__device__ float g_ctx[ACT_ELEMS];
__device__ float g_proj[ACT_ELEMS];
__device__ int   g_mask_mode; // 0 = uint8, 1 = int32, 2 = float32

typedef unsigned long long ull;

// ---- f32x2 packed math (FFMA2 — 2x fp32 FMA throughput, exact fp32) ----
__device__ __forceinline__ ull pack2(float lo, float hi) {
    ull r; asm("mov.b64 %0,{%1,%2};" : "=l"(r) : "f"(lo), "f"(hi)); return r;
}
__device__ __forceinline__ void unpack2(ull v, float& lo, float& hi) {
    asm("mov.b64 {%0,%1},%2;" : "=f"(lo), "=f"(hi) : "l"(v));
}
__device__ __forceinline__ ull ffma2(ull a, ull b, ull c) {
    ull d; asm("fma.rn.f32x2 %0,%1,%2,%3;" : "=l"(d) : "l"(a), "l"(b), "l"(c));
    return d;
}

// ---- fast exp2 on FMA pipe (avoids MUFU throughput wall), x <= 0 ----
__device__ __forceinline__ float fexp2(float x) {
    x = fmaxf(x, -126.0f);
    float fl = floorf(x);
    float f = x - fl;
    float p = 1.52527338e-5f;
    p = fmaf(p, f, 1.54035304e-4f);
    p = fmaf(p, f, 1.33335581e-3f);
    p = fmaf(p, f, 9.61812911e-3f);
    p = fmaf(p, f, 5.55041087e-2f);
    p = fmaf(p, f, 2.40226507e-1f);
    p = fmaf(p, f, 6.93147181e-1f);
    p = fmaf(p, f, 1.0f);
    return __int_as_float(__float_as_int(p) + (((int)fl) << 23));
}

// ---------------------------------------------------------------------------
// Mask dtype detection: jax bool may arrive as u8 / i32 / f32.
// ---------------------------------------------------------------------------
__global__ void detect_mask_kernel(const unsigned int* __restrict__ m) {
    __shared__ int f32flag, u8flag;
    if (threadIdx.x == 0) { f32flag = 0; u8flag = 0; }
    __syncthreads();
    int lf = 0, lu = 0;
    for (int i = threadIdx.x; i < 4096; i += blockDim.x) {
        unsigned w = m[i];
        if (w == 0x3f800000u) lf = 1;
        else if (w > 1u) lu = 1;
    }
    if (lf) atomicOr(&f32flag, 1);
    if (lu) atomicOr(&u8flag, 1);
    __syncthreads();
    if (threadIdx.x == 0) g_mask_mode = f32flag ? 2 : (u8flag ? 0 : 1);
}

__device__ __forceinline__ bool mask_at(const void* m, size_t idx, int mode) {
    if (mode == 0) return ((const unsigned char*)m)[idx] != 0;
    if (mode == 1) return ((const int*)m)[idx] != 0;
    return ((const float*)m)[idx] != 0.0f;
}

// ---------------------------------------------------------------------------
// GEMM: C[M,512] = A[M,512] @ W[512,512]^T  — FFMA2 inner loop
// 128x128 block tile, BK=16, 8x8 microtile (4 packed pairs), 256 threads.
// ---------------------------------------------------------------------------
__global__ void __launch_bounds__(256) gemm_xwt_kernel(
    const float* __restrict__ A, const float* __restrict__ W,
    float* __restrict__ C)
{
    __shared__ float As[16 * 132];
    __shared__ float Bs[16 * 132];
    const int m0 = blockIdx.x * 128;
    const int n0 = blockIdx.y * 128;
    const int tid = threadIdx.x;
    const int tx = tid & 15;
    const int ty = tid >> 4;
    const int lr = tid >> 2;         // 0..63
    const int lc = (tid & 3) << 2;   // 0,4,8,12

    ull acc[8][4];
#pragma unroll
    for (int i = 0; i < 8; i++)
#pragma unroll
        for (int j = 0; j < 4; j++) acc[i][j] = 0ull;

    for (int k0 = 0; k0 < 512; k0 += 16) {
        float4 a0 = *(const float4*)&A[(size_t)(m0 + lr) * 512 + k0 + lc];
        float4 a1 = *(const float4*)&A[(size_t)(m0 + lr + 64) * 512 + k0 + lc];
        float4 b0 = *(const float4*)&W[(size_t)(n0 + lr) * 512 + k0 + lc];
        float4 b1 = *(const float4*)&W[(size_t)(n0 + lr + 64) * 512 + k0 + lc];
        __syncthreads();
        As[(lc + 0) * 132 + lr] = a0.x;  As[(lc + 1) * 132 + lr] = a0.y;
        As[(lc + 2) * 132 + lr] = a0.z;  As[(lc + 3) * 132 + lr] = a0.w;
        As[(lc + 0) * 132 + lr + 64] = a1.x;  As[(lc + 1) * 132 + lr + 64] = a1.y;
        As[(lc + 2) * 132 + lr + 64] = a1.z;  As[(lc + 3) * 132 + lr + 64] = a1.w;
        Bs[(lc + 0) * 132 + lr] = b0.x;  Bs[(lc + 1) * 132 + lr] = b0.y;
        Bs[(lc + 2) * 132 + lr] = b0.z;  Bs[(lc + 3) * 132 + lr] = b0.w;
        Bs[(lc + 0) * 132 + lr + 64] = b1.x;  Bs[(lc + 1) * 132 + lr + 64] = b1.y;
        Bs[(lc + 2) * 132 + lr + 64] = b1.z;  Bs[(lc + 3) * 132 + lr + 64] = b1.w;
        __syncthreads();
#pragma unroll
        for (int k = 0; k < 16; k++) {
            float4 af0 = *(const float4*)&As[k * 132 + ty * 8];
            float4 af1 = *(const float4*)&As[k * 132 + ty * 8 + 4];
            float4 bf0 = *(const float4*)&Bs[k * 132 + tx * 8];
            float4 bf1 = *(const float4*)&Bs[k * 132 + tx * 8 + 4];
            ull pb0 = pack2(bf0.x, bf0.y), pb1 = pack2(bf0.z, bf0.w);
            ull pb2 = pack2(bf1.x, bf1.y), pb3 = pack2(bf1.z, bf1.w);
            float a[8] = {af0.x, af0.y, af0.z, af0.w, af1.x, af1.y, af1.z, af1.w};
#pragma unroll
            for (int i = 0; i < 8; i++) {
                ull pa = pack2(a[i], a[i]);
                acc[i][0] = ffma2(pa, pb0, acc[i][0]);
                acc[i][1] = ffma2(pa, pb1, acc[i][1]);
                acc[i][2] = ffma2(pa, pb2, acc[i][2]);
                acc[i][3] = ffma2(pa, pb3, acc[i][3]);
            }
        }
    }
#pragma unroll
    for (int i = 0; i < 8; i++) {
        float c0, c1, c2, c3, c4, c5, c6, c7;
        unpack2(acc[i][0], c0, c1); unpack2(acc[i][1], c2, c3);
        unpack2(acc[i][2], c4, c5); unpack2(acc[i][3], c6, c7);
        size_t off = (size_t)(m0 + ty * 8 + i) * 512 + n0 + tx * 8;
        *(float4*)&C[off]     = make_float4(c0, c1, c2, c3);
        *(float4*)&C[off + 4] = make_float4(c4, c5, c6, c7);
    }
}

// ---------------------------------------------------------------------------
// Fused attention per (b,h, 32-row q-tile), 256 threads.
// smem: sc[32][1028] scores/probs, qt[64][36] Q^T, kv (K^T 64x260 / V 256x68
//       / split-k reduction 4x2048), total 210,432 B.
// ---------------------------------------------------------------------------
#define CH 256
#define SC_STR 1028
#define QT_STR 36
#define KT_STR 260
#define VS_STR 68
#define SC_FLOATS (32 * SC_STR)
#define QT_FLOATS (64 * QT_STR)
#define KV_FLOATS (CH * VS_STR)
#define ATTN_SMEM_BYTES ((SC_FLOATS + QT_FLOATS + KV_FLOATS) * 4)

__global__ void __launch_bounds__(256) attn_kernel(
    const void* __restrict__ amask, const void* __restrict__ smask,
    float* __restrict__ att)
{
    extern __shared__ float sm[];
    float* sc = sm;
    float* qt = sm + SC_FLOATS;
    float* kv = qt + QT_FLOATS;

    const int bh = blockIdx.x;            // 0..63
    const int b = bh >> 3, h = bh & 7;
    const int q0 = blockIdx.y * 32;
    const int tid = threadIdx.x;
    const int lane = tid & 31;
    const int mode = g_mask_mode;
    const size_t head = ((size_t)b * NL) * ND + (size_t)h * NDH;

    // ---- Q tile, transposed: qt[d][r] ----
#pragma unroll
    for (int it = 0; it < 2; it++) {
        int idx = it * 256 + tid;
        int r = idx >> 4, db = (idx & 15) * 4;
        float4 q4 = *(const float4*)&g_Q[head + (size_t)(q0 + r) * ND + db];
        qt[(db + 0) * QT_STR + r] = q4.x;
        qt[(db + 1) * QT_STR + r] = q4.y;
        qt[(db + 2) * QT_STR + r] = q4.z;
        qt[(db + 3) * QT_STR + r] = q4.w;
    }

    // ---- scores = Q K^T : microtile 4 rows x 8 cols, FFMA2 ----
    const int rg = tid >> 5;   // warp id -> rows rg*4.. (q frag broadcast)
    const int cg = tid & 31;   // cols cg*8..cg*8+7 within 256-chunk
    for (int chunk = 0; chunk < 4; chunk++) {
        const int kc = chunk * CH;
        __syncthreads();
#pragma unroll
        for (int it = 0; it < 16; it++) {
            int idx = it * 256 + tid;
            int c = idx >> 4, db = (idx & 15) * 4;
            float4 k4 = *(const float4*)&g_K[head + (size_t)(kc + c) * ND + db];
            kv[(db + 0) * KT_STR + c] = k4.x;
            kv[(db + 1) * KT_STR + c] = k4.y;
            kv[(db + 2) * KT_STR + c] = k4.z;
            kv[(db + 3) * KT_STR + c] = k4.w;
        }
        __syncthreads();
        ull acc[4][4];
#pragma unroll
        for (int i = 0; i < 4; i++)
#pragma unroll
            for (int j = 0; j < 4; j++) acc[i][j] = 0ull;
        const float* qp = qt + rg * 4;
        const float* kp = kv + cg * 8;
#pragma unroll 4
        for (int d = 0; d < 64; d++) {
            float4 qf = *(const float4*)(qp + d * QT_STR);       // broadcast
            float4 k0 = *(const float4*)(kp + d * KT_STR);
            float4 k1 = *(const float4*)(kp + d * KT_STR + 4);
            ull b0 = pack2(k0.x, k0.y), b1 = pack2(k0.z, k0.w);
            ull b2 = pack2(k1.x, k1.y), b3 = pack2(k1.z, k1.w);
            ull a0 = pack2(qf.x, qf.x), a1 = pack2(qf.y, qf.y);
            ull a2 = pack2(qf.z, qf.z), a3 = pack2(qf.w, qf.w);
            acc[0][0] = ffma2(a0, b0, acc[0][0]); acc[0][1] = ffma2(a0, b1, acc[0][1]);
            acc[0][2] = ffma2(a0, b2, acc[0][2]); acc[0][3] = ffma2(a0, b3, acc[0][3]);
            acc[1][0] = ffma2(a1, b0, acc[1][0]); acc[1][1] = ffma2(a1, b1, acc[1][1]);
            acc[1][2] = ffma2(a1, b2, acc[1][2]); acc[1][3] = ffma2(a1, b3, acc[1][3]);
            acc[2][0] = ffma2(a2, b0, acc[2][0]); acc[2][1] = ffma2(a2, b1, acc[2][1]);
            acc[2][2] = ffma2(a2, b2, acc[2][2]); acc[2][3] = ffma2(a2, b3, acc[2][3]);
            acc[3][0] = ffma2(a3, b0, acc[3][0]); acc[3][1] = ffma2(a3, b1, acc[3][1]);
            acc[3][2] = ffma2(a3, b2, acc[3][2]); acc[3][3] = ffma2(a3, b3, acc[3][3]);
        }
#pragma unroll
        for (int i = 0; i < 4; i++) {
            float c0, c1, c2, c3, c4, c5, c6, c7;
            unpack2(acc[i][0], c0, c1); unpack2(acc[i][1], c2, c3);
            unpack2(acc[i][2], c4, c5); unpack2(acc[i][3], c6, c7);
            float* dst = &sc[(rg * 4 + i) * SC_STR + kc + cg * 8];
            *(float4*)dst       = make_float4(c0, c1, c2, c3);
            *(float4*)(dst + 4) = make_float4(c4, c5, c6, c7);
        }
    }
    __syncthreads();

    // ---- masked softmax + softmax_mask + attention write ----
    // warp w handles rows w*4..w*4+3; scores live in registers per row.
    const float SCL = 0.18033688011112042f;  // (1/8) * log2(e)
    {
        const int w = tid >> 5;
#pragma unroll
        for (int rr = 0; rr < 4; rr++) {
            int r = w * 4 + rr;
            size_t mrow = ((size_t)b * NL + q0 + r) * (size_t)NL;
            float* srow = sc + r * SC_STR;
            float4 v[8];
            float mx = -3.0e38f;
#pragma unroll
            for (int j = 0; j < 8; j++) {
                int c0 = (j * 32 + lane) * 4;
                float4 s = *(const float4*)&srow[c0];
                s.x *= SCL; s.y *= SCL; s.z *= SCL; s.w *= SCL;
                if (mode == 0) {
                    unsigned m = ((const unsigned*)amask)[(mrow >> 2) + j * 32 + lane];
                    if (m & 0x000000ffu) s.x = -1e30f;
                    if (m & 0x0000ff00u) s.y = -1e30f;
                    if (m & 0x00ff0000u) s.z = -1e30f;
                    if (m & 0xff000000u) s.w = -1e30f;
                } else {
                    if (mask_at(amask, mrow + c0 + 0, mode)) s.x = -1e30f;
                    if (mask_at(amask, mrow + c0 + 1, mode)) s.y = -1e30f;
                    if (mask_at(amask, mrow + c0 + 2, mode)) s.z = -1e30f;
                    if (mask_at(amask, mrow + c0 + 3, mode)) s.w = -1e30f;
                }
                mx = fmaxf(mx, fmaxf(fmaxf(s.x, s.y), fmaxf(s.z, s.w)));
                v[j] = s;
            }
#pragma unroll
            for (int o = 16; o > 0; o >>= 1)
                mx = fmaxf(mx, __shfl_xor_sync(0xffffffffu, mx, o));
            float sum = 0.0f;
#pragma unroll
            for (int j = 0; j < 8; j++) {
                v[j].x = fexp2(v[j].x - mx);
                v[j].y = fexp2(v[j].y - mx);
                v[j].z = fexp2(v[j].z - mx);
                v[j].w = fexp2(v[j].w - mx);
                sum += (v[j].x + v[j].y) + (v[j].z + v[j].w);
            }
#pragma unroll
            for (int o = 16; o > 0; o >>= 1)
                sum += __shfl_xor_sync(0xffffffffu, sum, o);
            float inv = 1.0f / sum;
            float* arow = att ? att + ((size_t)bh * NL + q0 + r) * NL : (float*)0;
#pragma unroll
            for (int j = 0; j < 8; j++) {
                int c0 = (j * 32 + lane) * 4;
                float4 a4 = v[j];
                a4.x *= inv; a4.y *= inv; a4.z *= inv; a4.w *= inv;
                if (mode == 0) {
                    unsigned m = ((const unsigned*)smask)[(mrow >> 2) + j * 32 + lane];
                    if (m & 0x000000ffu) a4.x = 0.0f;
                    if (m & 0x0000ff00u) a4.y = 0.0f;
                    if (m & 0x00ff0000u) a4.z = 0.0f;
                    if (m & 0xff000000u) a4.w = 0.0f;
                } else {
                    if (mask_at(smask, mrow + c0 + 0, mode)) a4.x = 0.0f;
                    if (mask_at(smask, mrow + c0 + 1, mode)) a4.y = 0.0f;
                    if (mask_at(smask, mrow + c0 + 2, mode)) a4.z = 0.0f;
                    if (mask_at(smask, mrow + c0 + 3, mode)) a4.w = 0.0f;
                }
                *(float4*)&srow[c0] = a4;
                if (arow) *(float4*)&arow[c0] = a4;
            }
        }
    }

    // ---- context = attn @ V : split-k over 4 thread groups, FFMA2 ----
    const int grp = tid >> 6;          // k-subrange group
    const int tt = tid & 63;
    const int rg2 = tt >> 3;           // rows rg2*4..+3
    const int dg = tt & 7;             // d cols dg*8..+7
    ull cacc[4][4];
#pragma unroll
    for (int i = 0; i < 4; i++)
#pragma unroll
        for (int j = 0; j < 4; j++) cacc[i][j] = 0ull;

    for (int chunk = 0; chunk < 4; chunk++) {
        const int kc = chunk * CH;
        __syncthreads();
#pragma unroll
        for (int it = 0; it < 16; it++) {
            int idx = it * 256 + tid;
            int c = idx >> 4, db = (idx & 15) * 4;
            float4 v4 = *(const float4*)&g_V[head + (size_t)(kc + c) * ND + db];
            *(float4*)&kv[c * VS_STR + db] = v4;
        }
        __syncthreads();
        const float* vp = kv + dg * 8;
#pragma unroll 4
        for (int kk = 0; kk < 64; kk++) {
            int k = grp * 64 + kk;
            float4 v0 = *(const float4*)(vp + k * VS_STR);
            float4 v1 = *(const float4*)(vp + k * VS_STR + 4);
            ull b0 = pack2(v0.x, v0.y), b1 = pack2(v0.z, v0.w);
            ull b2 = pack2(v1.x, v1.y), b3 = pack2(v1.z, v1.w);
#pragma unroll
            for (int i = 0; i < 4; i++) {
                float a = sc[(rg2 * 4 + i) * SC_STR + kc + k];
                ull pa = pack2(a, a);
                cacc[i][0] = ffma2(pa, b0, cacc[i][0]);
                cacc[i][1] = ffma2(pa, b1, cacc[i][1]);
                cacc[i][2] = ffma2(pa, b2, cacc[i][2]);
                cacc[i][3] = ffma2(pa, b3, cacc[i][3]);
            }
        }
    }
    __syncthreads();
    // partial store to kv region: [grp][row*64 + d]
#pragma unroll
    for (int i = 0; i < 4; i++) {
        float c0, c1, c2, c3, c4, c5, c6, c7;
        unpack2(cacc[i][0], c0, c1); unpack2(cacc[i][1], c2, c3);
        unpack2(cacc[i][2], c4, c5); unpack2(cacc[i][3], c6, c7);
        float* dst = &kv[grp * 2048 + (rg2 * 4 + i) * 64 + dg * 8];
        *(float4*)dst       = make_float4(c0, c1, c2, c3);
        *(float4*)(dst + 4) = make_float4(c4, c5, c6, c7);
    }
    __syncthreads();
    // final reduce + write
#pragma unroll
    for (int it = 0; it < 2; it++) {
        int idx = it * 256 + tid;
        int r = idx >> 4, d4 = (idx & 15) * 4;
        float4 s0 = *(const float4*)&kv[0 * 2048 + r * 64 + d4];
        float4 s1 = *(const float4*)&kv[1 * 2048 + r * 64 + d4];
        float4 s2 = *(const float4*)&kv[2 * 2048 + r * 64 + d4];
        float4 s3 = *(const float4*)&kv[3 * 2048 + r * 64 + d4];
        float4 o;
        o.x = (s0.x + s1.x) + (s2.x + s3.x);
        o.y = (s0.y + s1.y) + (s2.y + s3.y);
        o.z = (s0.z + s1.z) + (s2.z + s3.z);
        o.w = (s0.w + s1.w) + (s2.w + s3.w);
        *(float4*)&g_ctx[head + (size_t)(q0 + r) * ND + d4] = o;
    }
}

// ---------------------------------------------------------------------------
// Residual + LayerNorm (no affine), row = one token of 512
// ---------------------------------------------------------------------------
__global__ void __launch_bounds__(256) ln_kernel(
    const float* __restrict__ proj, const float* __restrict__ res,
    float* __restrict__ out)
{
    __shared__ float reds[8], redq[8];
    const int row = blockIdx.x;
    const int tid = threadIdx.x;
    const float* p = proj + (size_t)row * ND;
    const float* r = res + (size_t)row * ND;
    float x0 = r[tid] + p[tid];
    float x1 = r[tid + 256] + p[tid + 256];
    float s = x0 + x1;
    float q = x0 * x0 + x1 * x1;
#pragma unroll
    for (int o = 16; o > 0; o >>= 1) {
        s += __shfl_xor_sync(0xffffffffu, s, o);
        q += __shfl_xor_sync(0xffffffffu, q, o);
    }
    if ((tid & 31) == 0) { reds[tid >> 5] = s; redq[tid >> 5] = q; }
    __syncthreads();
    float ts = 0, tq = 0;
#pragma unroll
    for (int i = 0; i < 8; i++) { ts += reds[i]; tq += redq[i]; }
    float mean = ts * (1.0f / ND);
    float var = tq * (1.0f / ND) - mean * mean;
    float rr = rsqrtf(var + 1e-5f);
    out[(size_t)row * ND + tid] = (x0 - mean) * rr;
    out[(size_t)row * ND + tid + 256] = (x1 - mean) * rr;
}

// ---------------------------------------------------------------------------
extern "C" void kernel_launch(void* const* d_in, const int* in_sizes, int n_in,
                              void* d_out, int out_size)
{
    const float* query = (const float*)d_in[0];
    const float* key   = (const float*)d_in[1];
    const float* value = (const float*)d_in[2];
    const void*  amask = d_in[3];
    const void*  smask = d_in[4];
    const float* Wq = (const float*)d_in[5];
    const float* Wk = (const float*)d_in[6];
    const float* Wv = (const float*)d_in[7];
    const float* Wo = (const float*)d_in[8];

    float* out = (float*)d_out;
    float* att = ((size_t)out_size >= ACT_ELEMS + ATT_ELEMS) ? out + ACT_ELEMS
                                                             : (float*)0;

    void *pQ, *pK, *pV, *pCtx, *pProj;
    cudaGetSymbolAddress(&pQ, g_Q);
    cudaGetSymbolAddress(&pK, g_K);
    cudaGetSymbolAddress(&pV, g_V);
    cudaGetSymbolAddress(&pCtx, g_ctx);
    cudaGetSymbolAddress(&pProj, g_proj);

    cudaFuncSetAttribute(attn_kernel, cudaFuncAttributeMaxDynamicSharedMemorySize,
                         ATTN_SMEM_BYTES);

    detect_mask_kernel<<<1, 256>>>((const unsigned int*)amask);

    dim3 ggrid(TOK / 128, ND / 128);
    gemm_xwt_kernel<<<ggrid, 256>>>(query, Wq, (float*)pQ);
    gemm_xwt_kernel<<<ggrid, 256>>>(key,   Wk, (float*)pK);
    gemm_xwt_kernel<<<ggrid, 256>>>(value, Wv, (float*)pV);

    attn_kernel<<<dim3(NB * NH, NL / 32), 256, ATTN_SMEM_BYTES>>>(amask, smask, att);

    gemm_xwt_kernel<<<ggrid, 256>>>((const float*)pCtx, Wo, (float*)pProj);

    ln_kernel<<<TOK, 256>>>((const float*)pProj, query, out);
}

// round 4
// speedup vs baseline: 1.7276x; 1.0024x over previous
#include <cuda_runtime.h>
#include <math.h>

// Problem dims
#define NB 8
#define NL 1024
#define ND 512
#define NH 8
#define NDH 64

#define TOK (NB * NL)                 // 8192 rows
#define ACT_ELEMS ((size_t)TOK * ND)  // 4,194,304
#define ATT_ELEMS ((size_t)NB * NH * NL * NL) // 67,108,864

// Scratch (static device arrays — no allocation at runtime)
__device__ float g_Q[ACT_ELEMS];
__device__ float g_K[ACT_ELEMS];
__device__ float g_V[ACT_ELEMS];
__device__ float g_ctx[ACT_ELEMS];
__device__ float g_proj[ACT_ELEMS];
__device__ int   g_mask_mode; // 0 = uint8, 1 = int32, 2 = float32

typedef unsigned long long ull;

// ---- f32x2 packed math (FFMA2 — 2x fp32 FMA throughput, exact fp32) ----
__device__ __forceinline__ ull pack2(float lo, float hi) {
    ull r; asm("mov.b64 %0,{%1,%2};" : "=l"(r) : "f"(lo), "f"(hi)); return r;
}
__device__ __forceinline__ void unpack2(ull v, float& lo, float& hi) {
    asm("mov.b64 {%0,%1},%2;" : "=f"(lo), "=f"(hi) : "l"(v));
}
__device__ __forceinline__ ull ffma2(ull a, ull b, ull c) {
    ull d; asm("fma.rn.f32x2 %0,%1,%2,%3;" : "=l"(d) : "l"(a), "l"(b), "l"(c));
    return d;
}

// ---- fast exp2 on FMA pipe (avoids MUFU throughput wall), x <= 0 ----
__device__ __forceinline__ float fexp2(float x) {
    x = fmaxf(x, -126.0f);
    float fl = floorf(x);
    float f = x - fl;
    float p = 1.52527338e-5f;
    p = fmaf(p, f, 1.54035304e-4f);
    p = fmaf(p, f, 1.33335581e-3f);
    p = fmaf(p, f, 9.61812911e-3f);
    p = fmaf(p, f, 5.55041087e-2f);
    p = fmaf(p, f, 2.40226507e-1f);
    p = fmaf(p, f, 6.93147181e-1f);
    p = fmaf(p, f, 1.0f);
    return __int_as_float(__float_as_int(p) + (((int)fl) << 23));
}

// ---------------------------------------------------------------------------
// Mask dtype detection: jax bool may arrive as u8 / i32 / f32.
// ---------------------------------------------------------------------------
__global__ void detect_mask_kernel(const unsigned int* __restrict__ m) {
    __shared__ int f32flag, u8flag;
    if (threadIdx.x == 0) { f32flag = 0; u8flag = 0; }
    __syncthreads();
    int lf = 0, lu = 0;
    for (int i = threadIdx.x; i < 4096; i += blockDim.x) {
        unsigned w = m[i];
        if (w == 0x3f800000u) lf = 1;
        else if (w > 1u) lu = 1;
    }
    if (lf) atomicOr(&f32flag, 1);
    if (lu) atomicOr(&u8flag, 1);
    __syncthreads();
    if (threadIdx.x == 0) g_mask_mode = f32flag ? 2 : (u8flag ? 0 : 1);
}

__device__ __forceinline__ bool mask_at(const void* m, size_t idx, int mode) {
    if (mode == 0) return ((const unsigned char*)m)[idx] != 0;
    if (mode == 1) return ((const int*)m)[idx] != 0;
    return ((const float*)m)[idx] != 0.0f;
}

// ---------------------------------------------------------------------------
// GEMM: C[M,512] = A[M,512] @ W[512,512]^T  — FFMA2 inner loop
// 128x128 block tile, BK=16, 8x8 microtile (4 packed pairs), 256 threads.
// ---------------------------------------------------------------------------
__global__ void __launch_bounds__(256) gemm_xwt_kernel(
    const float* __restrict__ A, const float* __restrict__ W,
    float* __restrict__ C)
{
    __shared__ float As[16 * 132];
    __shared__ float Bs[16 * 132];
    const int m0 = blockIdx.x * 128;
    const int n0 = blockIdx.y * 128;
    const int tid = threadIdx.x;
    const int tx = tid & 15;
    const int ty = tid >> 4;
    const int lr = tid >> 2;         // 0..63
    const int lc = (tid & 3) << 2;   // 0,4,8,12

    ull acc[8][4];
#pragma unroll
    for (int i = 0; i < 8; i++)
#pragma unroll
        for (int j = 0; j < 4; j++) acc[i][j] = 0ull;

    for (int k0 = 0; k0 < 512; k0 += 16) {
        float4 a0 = *(const float4*)&A[(size_t)(m0 + lr) * 512 + k0 + lc];
        float4 a1 = *(const float4*)&A[(size_t)(m0 + lr + 64) * 512 + k0 + lc];
        float4 b0 = *(const float4*)&W[(size_t)(n0 + lr) * 512 + k0 + lc];
        float4 b1 = *(const float4*)&W[(size_t)(n0 + lr + 64) * 512 + k0 + lc];
        __syncthreads();
        As[(lc + 0) * 132 + lr] = a0.x;  As[(lc + 1) * 132 + lr] = a0.y;
        As[(lc + 2) * 132 + lr] = a0.z;  As[(lc + 3) * 132 + lr] = a0.w;
        As[(lc + 0) * 132 + lr + 64] = a1.x;  As[(lc + 1) * 132 + lr + 64] = a1.y;
        As[(lc + 2) * 132 + lr + 64] = a1.z;  As[(lc + 3) * 132 + lr + 64] = a1.w;
        Bs[(lc + 0) * 132 + lr] = b0.x;  Bs[(lc + 1) * 132 + lr] = b0.y;
        Bs[(lc + 2) * 132 + lr] = b0.z;  Bs[(lc + 3) * 132 + lr] = b0.w;
        Bs[(lc + 0) * 132 + lr + 64] = b1.x;  Bs[(lc + 1) * 132 + lr + 64] = b1.y;
        Bs[(lc + 2) * 132 + lr + 64] = b1.z;  Bs[(lc + 3) * 132 + lr + 64] = b1.w;
        __syncthreads();
#pragma unroll
        for (int k = 0; k < 16; k++) {
            float4 af0 = *(const float4*)&As[k * 132 + ty * 8];
            float4 af1 = *(const float4*)&As[k * 132 + ty * 8 + 4];
            float4 bf0 = *(const float4*)&Bs[k * 132 + tx * 8];
            float4 bf1 = *(const float4*)&Bs[k * 132 + tx * 8 + 4];
            ull pb0 = pack2(bf0.x, bf0.y), pb1 = pack2(bf0.z, bf0.w);
            ull pb2 = pack2(bf1.x, bf1.y), pb3 = pack2(bf1.z, bf1.w);
            float a[8] = {af0.x, af0.y, af0.z, af0.w, af1.x, af1.y, af1.z, af1.w};
#pragma unroll
            for (int i = 0; i < 8; i++) {
                ull pa = pack2(a[i], a[i]);
                acc[i][0] = ffma2(pa, pb0, acc[i][0]);
                acc[i][1] = ffma2(pa, pb1, acc[i][1]);
                acc[i][2] = ffma2(pa, pb2, acc[i][2]);
                acc[i][3] = ffma2(pa, pb3, acc[i][3]);
            }
        }
    }
#pragma unroll
    for (int i = 0; i < 8; i++) {
        float c0, c1, c2, c3, c4, c5, c6, c7;
        unpack2(acc[i][0], c0, c1); unpack2(acc[i][1], c2, c3);
        unpack2(acc[i][2], c4, c5); unpack2(acc[i][3], c6, c7);
        size_t off = (size_t)(m0 + ty * 8 + i) * 512 + n0 + tx * 8;
        *(float4*)&C[off]     = make_float4(c0, c1, c2, c3);
        *(float4*)&C[off + 4] = make_float4(c4, c5, c6, c7);
    }
}

// ---------------------------------------------------------------------------
// Fused attention per (b,h, 32-row q-tile), 256 threads.
// smem: sc[32][1028] scores/probs, qt[64][36] Q^T, kv (K^T 64x260 / V 256x68
//       / split-k reduction 4x2048), total 210,432 B.
// ---------------------------------------------------------------------------
#define CH 256
#define SC_STR 1028
#define QT_STR 36
#define KT_STR 260
#define VS_STR 68
#define SC_FLOATS (32 * SC_STR)
#define QT_FLOATS (64 * QT_STR)
#define KV_FLOATS (CH * VS_STR)
#define ATTN_SMEM_BYTES ((SC_FLOATS + QT_FLOATS + KV_FLOATS) * 4)

__global__ void __launch_bounds__(256) attn_kernel(
    const void* __restrict__ amask, const void* __restrict__ smask,
    float* __restrict__ att)
{
    extern __shared__ float sm[];
    float* sc = sm;
    float* qt = sm + SC_FLOATS;
    float* kv = qt + QT_FLOATS;

    const int bh = blockIdx.x;            // 0..63
    const int b = bh >> 3, h = bh & 7;
    const int q0 = blockIdx.y * 32;
    const int tid = threadIdx.x;
    const int lane = tid & 31;
    const int mode = g_mask_mode;
    const size_t head = ((size_t)b * NL) * ND + (size_t)h * NDH;

    // ---- Q tile, transposed: qt[d][r] ----
#pragma unroll
    for (int it = 0; it < 2; it++) {
        int idx = it * 256 + tid;
        int r = idx >> 4, db = (idx & 15) * 4;
        float4 q4 = *(const float4*)&g_Q[head + (size_t)(q0 + r) * ND + db];
        qt[(db + 0) * QT_STR + r] = q4.x;
        qt[(db + 1) * QT_STR + r] = q4.y;
        qt[(db + 2) * QT_STR + r] = q4.z;
        qt[(db + 3) * QT_STR + r] = q4.w;
    }

    // ---- scores = Q K^T : microtile 4 rows x 8 cols, FFMA2 ----
    const int rg = tid >> 5;   // warp id -> rows rg*4.. (q frag broadcast)
    const int cg = tid & 31;   // cols cg*8..cg*8+7 within 256-chunk
    for (int chunk = 0; chunk < 4; chunk++) {
        const int kc = chunk * CH;
        __syncthreads();
#pragma unroll
        for (int it = 0; it < 16; it++) {
            int idx = it * 256 + tid;
            int c = idx >> 4, db = (idx & 15) * 4;
            float4 k4 = *(const float4*)&g_K[head + (size_t)(kc + c) * ND + db];
            kv[(db + 0) * KT_STR + c] = k4.x;
            kv[(db + 1) * KT_STR + c] = k4.y;
            kv[(db + 2) * KT_STR + c] = k4.z;
            kv[(db + 3) * KT_STR + c] = k4.w;
        }
        __syncthreads();
        ull acc[4][4];
#pragma unroll
        for (int i = 0; i < 4; i++)
#pragma unroll
            for (int j = 0; j < 4; j++) acc[i][j] = 0ull;
        const float* qp = qt + rg * 4;
        const float* kp = kv + cg * 8;
#pragma unroll 4
        for (int d = 0; d < 64; d++) {
            float4 qf = *(const float4*)(qp + d * QT_STR);       // broadcast
            float4 k0 = *(const float4*)(kp + d * KT_STR);
            float4 k1 = *(const float4*)(kp + d * KT_STR + 4);
            ull b0 = pack2(k0.x, k0.y), b1 = pack2(k0.z, k0.w);
            ull b2 = pack2(k1.x, k1.y), b3 = pack2(k1.z, k1.w);
            ull a0 = pack2(qf.x, qf.x), a1 = pack2(qf.y, qf.y);
            ull a2 = pack2(qf.z, qf.z), a3 = pack2(qf.w, qf.w);
            acc[0][0] = ffma2(a0, b0, acc[0][0]); acc[0][1] = ffma2(a0, b1, acc[0][1]);
            acc[0][2] = ffma2(a0, b2, acc[0][2]); acc[0][3] = ffma2(a0, b3, acc[0][3]);
            acc[1][0] = ffma2(a1, b0, acc[1][0]); acc[1][1] = ffma2(a1, b1, acc[1][1]);
            acc[1][2] = ffma2(a1, b2, acc[1][2]); acc[1][3] = ffma2(a1, b3, acc[1][3]);
            acc[2][0] = ffma2(a2, b0, acc[2][0]); acc[2][1] = ffma2(a2, b1, acc[2][1]);
            acc[2][2] = ffma2(a2, b2, acc[2][2]); acc[2][3] = ffma2(a2, b3, acc[2][3]);
            acc[3][0] = ffma2(a3, b0, acc[3][0]); acc[3][1] = ffma2(a3, b1, acc[3][1]);
            acc[3][2] = ffma2(a3, b2, acc[3][2]); acc[3][3] = ffma2(a3, b3, acc[3][3]);
        }
#pragma unroll
        for (int i = 0; i < 4; i++) {
            float c0, c1, c2, c3, c4, c5, c6, c7;
            unpack2(acc[i][0], c0, c1); unpack2(acc[i][1], c2, c3);
            unpack2(acc[i][2], c4, c5); unpack2(acc[i][3], c6, c7);
            float* dst = &sc[(rg * 4 + i) * SC_STR + kc + cg * 8];
            *(float4*)dst       = make_float4(c0, c1, c2, c3);
            *(float4*)(dst + 4) = make_float4(c4, c5, c6, c7);
        }
    }
    __syncthreads();

    // ---- masked softmax + softmax_mask + attention write ----
    // warp w handles rows w*4..w*4+3; scores live in registers per row.
    const float SCL = 0.18033688011112042f;  // (1/8) * log2(e)
    {
        const int w = tid >> 5;
#pragma unroll
        for (int rr = 0; rr < 4; rr++) {
            int r = w * 4 + rr;
            size_t mrow = ((size_t)b * NL + q0 + r) * (size_t)NL;
            float* srow = sc + r * SC_STR;
            float4 v[8];
            float mx = -3.0e38f;
#pragma unroll
            for (int j = 0; j < 8; j++) {
                int c0 = (j * 32 + lane) * 4;
                float4 s = *(const float4*)&srow[c0];
                s.x *= SCL; s.y *= SCL; s.z *= SCL; s.w *= SCL;
                if (mode == 0) {
                    unsigned m = ((const unsigned*)amask)[(mrow >> 2) + j * 32 + lane];
                    if (m & 0x000000ffu) s.x = -1e30f;
                    if (m & 0x0000ff00u) s.y = -1e30f;
                    if (m & 0x00ff0000u) s.z = -1e30f;
                    if (m & 0xff000000u) s.w = -1e30f;
                } else {
                    if (mask_at(amask, mrow + c0 + 0, mode)) s.x = -1e30f;
                    if (mask_at(amask, mrow + c0 + 1, mode)) s.y = -1e30f;
                    if (mask_at(amask, mrow + c0 + 2, mode)) s.z = -1e30f;
                    if (mask_at(amask, mrow + c0 + 3, mode)) s.w = -1e30f;
                }
                mx = fmaxf(mx, fmaxf(fmaxf(s.x, s.y), fmaxf(s.z, s.w)));
                v[j] = s;
            }
#pragma unroll
            for (int o = 16; o > 0; o >>= 1)
                mx = fmaxf(mx, __shfl_xor_sync(0xffffffffu, mx, o));
            float sum = 0.0f;
#pragma unroll
            for (int j = 0; j < 8; j++) {
                v[j].x = fexp2(v[j].x - mx);
                v[j].y = fexp2(v[j].y - mx);
                v[j].z = fexp2(v[j].z - mx);
                v[j].w = fexp2(v[j].w - mx);
                sum += (v[j].x + v[j].y) + (v[j].z + v[j].w);
            }
#pragma unroll
            for (int o = 16; o > 0; o >>= 1)
                sum += __shfl_xor_sync(0xffffffffu, sum, o);
            float inv = 1.0f / sum;
            float* arow = att ? att + ((size_t)bh * NL + q0 + r) * NL : (float*)0;
#pragma unroll
            for (int j = 0; j < 8; j++) {
                int c0 = (j * 32 + lane) * 4;
                float4 a4 = v[j];
                a4.x *= inv; a4.y *= inv; a4.z *= inv; a4.w *= inv;
                if (mode == 0) {
                    unsigned m = ((const unsigned*)smask)[(mrow >> 2) + j * 32 + lane];
                    if (m & 0x000000ffu) a4.x = 0.0f;
                    if (m & 0x0000ff00u) a4.y = 0.0f;
                    if (m & 0x00ff0000u) a4.z = 0.0f;
                    if (m & 0xff000000u) a4.w = 0.0f;
                } else {
                    if (mask_at(smask, mrow + c0 + 0, mode)) a4.x = 0.0f;
                    if (mask_at(smask, mrow + c0 + 1, mode)) a4.y = 0.0f;
                    if (mask_at(smask, mrow + c0 + 2, mode)) a4.z = 0.0f;
                    if (mask_at(smask, mrow + c0 + 3, mode)) a4.w = 0.0f;
                }
                *(float4*)&srow[c0] = a4;
                if (arow) *(float4*)&arow[c0] = a4;
            }
        }
    }

    // ---- context = attn @ V : split-k over 4 thread groups, FFMA2 ----
    const int grp = tid >> 6;          // k-subrange group
    const int tt = tid & 63;
    const int rg2 = tt >> 3;           // rows rg2*4..+3
    const int dg = tt & 7;             // d cols dg*8..+7
    ull cacc[4][4];
#pragma unroll
    for (int i = 0; i < 4; i++)
#pragma unroll
        for (int j = 0; j < 4; j++) cacc[i][j] = 0ull;

    for (int chunk = 0; chunk < 4; chunk++) {
        const int kc = chunk * CH;
        __syncthreads();
#pragma unroll
        for (int it = 0; it < 16; it++) {
            int idx = it * 256 + tid;
            int c = idx >> 4, db = (idx & 15) * 4;
            float4 v4 = *(const float4*)&g_V[head + (size_t)(kc + c) * ND + db];
            *(float4*)&kv[c * VS_STR + db] = v4;
        }
        __syncthreads();
        const float* vp = kv + dg * 8;
#pragma unroll 4
        for (int kk = 0; kk < 64; kk++) {
            int k = grp * 64 + kk;
            float4 v0 = *(const float4*)(vp + k * VS_STR);
            float4 v1 = *(const float4*)(vp + k * VS_STR + 4);
            ull b0 = pack2(v0.x, v0.y), b1 = pack2(v0.z, v0.w);
            ull b2 = pack2(v1.x, v1.y), b3 = pack2(v1.z, v1.w);
#pragma unroll
            for (int i = 0; i < 4; i++) {
                float a = sc[(rg2 * 4 + i) * SC_STR + kc + k];
                ull pa = pack2(a, a);
                cacc[i][0] = ffma2(pa, b0, cacc[i][0]);
                cacc[i][1] = ffma2(pa, b1, cacc[i][1]);
                cacc[i][2] = ffma2(pa, b2, cacc[i][2]);
                cacc[i][3] = ffma2(pa, b3, cacc[i][3]);
            }
        }
    }
    __syncthreads();
    // partial store to kv region: [grp][row*64 + d]
#pragma unroll
    for (int i = 0; i < 4; i++) {
        float c0, c1, c2, c3, c4, c5, c6, c7;
        unpack2(cacc[i][0], c0, c1); unpack2(cacc[i][1], c2, c3);
        unpack2(cacc[i][2], c4, c5); unpack2(cacc[i][3], c6, c7);
        float* dst = &kv[grp * 2048 + (rg2 * 4 + i) * 64 + dg * 8];
        *(float4*)dst       = make_float4(c0, c1, c2, c3);
        *(float4*)(dst + 4) = make_float4(c4, c5, c6, c7);
    }
    __syncthreads();
    // final reduce + write
#pragma unroll
    for (int it = 0; it < 2; it++) {
        int idx = it * 256 + tid;
        int r = idx >> 4, d4 = (idx & 15) * 4;
        float4 s0 = *(const float4*)&kv[0 * 2048 + r * 64 + d4];
        float4 s1 = *(const float4*)&kv[1 * 2048 + r * 64 + d4];
        float4 s2 = *(const float4*)&kv[2 * 2048 + r * 64 + d4];
        float4 s3 = *(const float4*)&kv[3 * 2048 + r * 64 + d4];
        float4 o;
        o.x = (s0.x + s1.x) + (s2.x + s3.x);
        o.y = (s0.y + s1.y) + (s2.y + s3.y);
        o.z = (s0.z + s1.z) + (s2.z + s3.z);
        o.w = (s0.w + s1.w) + (s2.w + s3.w);
        *(float4*)&g_ctx[head + (size_t)(q0 + r) * ND + d4] = o;
    }
}

// ---------------------------------------------------------------------------
// Residual + LayerNorm (no affine), row = one token of 512
// ---------------------------------------------------------------------------
__global__ void __launch_bounds__(256) ln_kernel(
    const float* __restrict__ proj, const float* __restrict__ res,
    float* __restrict__ out)
{
    __shared__ float reds[8], redq[8];
    const int row = blockIdx.x;
    const int tid = threadIdx.x;
    const float* p = proj + (size_t)row * ND;
    const float* r = res + (size_t)row * ND;
    float x0 = r[tid] + p[tid];
    float x1 = r[tid + 256] + p[tid + 256];
    float s = x0 + x1;
    float q = x0 * x0 + x1 * x1;
#pragma unroll
    for (int o = 16; o > 0; o >>= 1) {
        s += __shfl_xor_sync(0xffffffffu, s, o);
        q += __shfl_xor_sync(0xffffffffu, q, o);
    }
    if ((tid & 31) == 0) { reds[tid >> 5] = s; redq[tid >> 5] = q; }
    __syncthreads();
    float ts = 0, tq = 0;
#pragma unroll
    for (int i = 0; i < 8; i++) { ts += reds[i]; tq += redq[i]; }
    float mean = ts * (1.0f / ND);
    float var = tq * (1.0f / ND) - mean * mean;
    float rr = rsqrtf(var + 1e-5f);
    out[(size_t)row * ND + tid] = (x0 - mean) * rr;
    out[(size_t)row * ND + tid + 256] = (x1 - mean) * rr;
}

// ---------------------------------------------------------------------------
extern "C" void kernel_launch(void* const* d_in, const int* in_sizes, int n_in,
                              void* d_out, int out_size)
{
    const float* query = (const float*)d_in[0];
    const float* key   = (const float*)d_in[1];
    const float* value = (const float*)d_in[2];
    const void*  amask = d_in[3];
    const void*  smask = d_in[4];
    const float* Wq = (const float*)d_in[5];
    const float* Wk = (const float*)d_in[6];
    const float* Wv = (const float*)d_in[7];
    const float* Wo = (const float*)d_in[8];

    float* out = (float*)d_out;
    float* att = ((size_t)out_size >= ACT_ELEMS + ATT_ELEMS) ? out + ACT_ELEMS
                                                             : (float*)0;

    void *pQ, *pK, *pV, *pCtx, *pProj;
    cudaGetSymbolAddress(&pQ, g_Q);
    cudaGetSymbolAddress(&pK, g_K);
    cudaGetSymbolAddress(&pV, g_V);
    cudaGetSymbolAddress(&pCtx, g_ctx);
    cudaGetSymbolAddress(&pProj, g_proj);

    cudaFuncSetAttribute(attn_kernel, cudaFuncAttributeMaxDynamicSharedMemorySize,
                         ATTN_SMEM_BYTES);

    detect_mask_kernel<<<1, 256>>>((const unsigned int*)amask);

    dim3 ggrid(TOK / 128, ND / 128);
    gemm_xwt_kernel<<<ggrid, 256>>>(query, Wq, (float*)pQ);
    gemm_xwt_kernel<<<ggrid, 256>>>(key,   Wk, (float*)pK);
    gemm_xwt_kernel<<<ggrid, 256>>>(value, Wv, (float*)pV);

    attn_kernel<<<dim3(NB * NH, NL / 32), 256, ATTN_SMEM_BYTES>>>(amask, smask, att);

    gemm_xwt_kernel<<<ggrid, 256>>>((const float*)pCtx, Wo, (float*)pProj);

    ln_kernel<<<TOK, 256>>>((const float*)pProj, query, out);
}

// round 7
// speedup vs baseline: 2.2824x; 1.3211x over previous
#include <cuda_runtime.h>
#include <cuda_bf16.h>
#include <math.h>
#include <stdint.h>

#define NB 8
#define NL 1024
#define ND 512
#define NH 8
#define NDH 64
#define TOK (NB * NL)
#define ACT_ELEMS ((size_t)TOK * ND)
#define W_ELEMS ((size_t)ND * ND)
#define ATT_ELEMS ((size_t)NB * NH * NL * NL)
#define MASK_WORDS (ATT_ELEMS / 32)

__device__ __nv_bfloat16 g_Ah[ACT_ELEMS], g_Al[ACT_ELEMS];
__device__ __nv_bfloat16 g_Wh[W_ELEMS],  g_Wl[W_ELEMS];
__device__ __nv_bfloat16 g_Qh[ACT_ELEMS], g_Ql[ACT_ELEMS];
__device__ __nv_bfloat16 g_Kh[ACT_ELEMS], g_Kl[ACT_ELEMS];
__device__ __nv_bfloat16 g_Vth[ACT_ELEMS], g_Vtl[ACT_ELEMS]; // [bh*64+d][1024]
__device__ __nv_bfloat16 g_Ch[ACT_ELEMS], g_Cl[ACT_ELEMS];
__device__ float        g_projf[ACT_ELEMS];
__device__ unsigned     g_am[MASK_WORDS], g_sm[MASK_WORDS];
__device__ int          g_mask_mode;

// ---------------- helpers ----------------
__device__ __forceinline__ uint32_t smem_u32(const void* p) {
    uint32_t a;
    asm("{ .reg .u64 t; cvta.to.shared.u64 t, %1; cvt.u32.u64 %0, t; }" : "=r"(a) : "l"(p));
    return a;
}
__device__ __forceinline__ void ldm_x4(unsigned r[4], uint32_t a) {
    asm volatile("ldmatrix.sync.aligned.m8n8.x4.shared.b16 {%0,%1,%2,%3}, [%4];"
                 : "=r"(r[0]), "=r"(r[1]), "=r"(r[2]), "=r"(r[3]) : "r"(a) : "memory");
}
__device__ __forceinline__ void ldm_x2(unsigned r[2], uint32_t a) {
    asm volatile("ldmatrix.sync.aligned.m8n8.x2.shared.b16 {%0,%1}, [%2];"
                 : "=r"(r[0]), "=r"(r[1]) : "r"(a) : "memory");
}
#define MMA(c, a, b) \
    asm volatile("mma.sync.aligned.m16n8k16.row.col.f32.bf16.bf16.f32 " \
                 "{%0,%1,%2,%3},{%4,%5,%6,%7},{%8,%9},{%0,%1,%2,%3};" \
                 : "+f"((c)[0]), "+f"((c)[1]), "+f"((c)[2]), "+f"((c)[3]) \
                 : "r"((a)[0]), "r"((a)[1]), "r"((a)[2]), "r"((a)[3]), \
                   "r"((b)[0]), "r"((b)[1]))

__device__ __forceinline__ void split2(float f0, float f1, unsigned& hp, unsigned& lp) {
    __nv_bfloat16 h0 = __float2bfloat16_rn(f0), h1 = __float2bfloat16_rn(f1);
    __nv_bfloat16 l0 = __float2bfloat16_rn(f0 - __bfloat162float(h0));
    __nv_bfloat16 l1 = __float2bfloat16_rn(f1 - __bfloat162float(h1));
    hp = (unsigned)__bfloat16_as_ushort(h0) | ((unsigned)__bfloat16_as_ushort(h1) << 16);
    lp = (unsigned)__bfloat16_as_ushort(l0) | ((unsigned)__bfloat16_as_ushort(l1) << 16);
}

__device__ __forceinline__ float fexp2(float x) {
    x = fmaxf(fminf(x, 120.0f), -126.0f);
    float fl = floorf(x);
    float f = x - fl;
    float p = 1.52527338e-5f;
    p = fmaf(p, f, 1.54035304e-4f);
    p = fmaf(p, f, 1.33335581e-3f);
    p = fmaf(p, f, 9.61812911e-3f);
    p = fmaf(p, f, 5.55041087e-2f);
    p = fmaf(p, f, 2.40226507e-1f);
    p = fmaf(p, f, 6.93147181e-1f);
    p = fmaf(p, f, 1.0f);
    return __int_as_float(__float_as_int(p) + (((int)fl) << 23));
}

// ---------------- prep kernels ----------------
__global__ void detect_mask_kernel(const unsigned* __restrict__ m) {
    __shared__ int f32flag, u8flag;
    if (threadIdx.x == 0) { f32flag = 0; u8flag = 0; }
    __syncthreads();
    int lf = 0, lu = 0;
    for (int i = threadIdx.x; i < 4096; i += blockDim.x) {
        unsigned w = m[i];
        if (w == 0x3f800000u) lf = 1;
        else if (w > 1u) lu = 1;
    }
    if (lf) atomicOr(&f32flag, 1);
    if (lu) atomicOr(&u8flag, 1);
    __syncthreads();
    if (threadIdx.x == 0) g_mask_mode = f32flag ? 2 : (u8flag ? 0 : 1);
}

__global__ void pack_mask_kernel(const void* __restrict__ m, unsigned* __restrict__ out) {
    int w = blockIdx.x * 256 + threadIdx.x;
    if (w >= (int)MASK_WORDS) return;
    int mode = g_mask_mode;
    unsigned bits = 0;
    if (mode == 0) {
        const unsigned* p = (const unsigned*)m + (size_t)w * 8;
#pragma unroll
        for (int j = 0; j < 8; j++) {
            unsigned v = __vcmpne4(p[j], 0u);
            bits |= ((((v & 0x01010101u) * 0x01020408u) >> 24) & 0xFu) << (j * 4);
        }
    } else if (mode == 1) {
        const int* p = (const int*)m + (size_t)w * 32;
#pragma unroll
        for (int j = 0; j < 32; j++) bits |= (unsigned)(p[j] != 0) << j;
    } else {
        const float* p = (const float*)m + (size_t)w * 32;
#pragma unroll
        for (int j = 0; j < 32; j++) bits |= (unsigned)(p[j] != 0.0f) << j;
    }
    out[w] = bits;
}

__global__ void conv_split_kernel(const float4* __restrict__ x,
                                  __nv_bfloat16* __restrict__ hi,
                                  __nv_bfloat16* __restrict__ lo, int n4) {
    int i = blockIdx.x * 256 + threadIdx.x;
    if (i >= n4) return;
    float4 v = x[i];
    unsigned h0, l0, h1, l1;
    split2(v.x, v.y, h0, l0);
    split2(v.z, v.w, h1, l1);
    ((uint2*)hi)[i] = make_uint2(h0, h1);
    ((uint2*)lo)[i] = make_uint2(l0, l1);
}

// ---------------- projection GEMM (mma.sync, 3-term split bf16) ------------
// C[8192,512] = A @ W^T. CTA tile 128x128, k-chunk 64, 8 warps (2m x 4n).
// mode 0: hi/lo row-major out; 1: V head-transposed out; 2: f32 out.
#define SPD 72          // smem row stride in bf16 (144 B)
#define PJ_AH 0
#define PJ_AL 18432
#define PJ_BH 36864
#define PJ_BL 55296
#define PJ_SMEM 73728

__global__ void __launch_bounds__(256) proj_kernel(
    const __nv_bfloat16* __restrict__ Ah, const __nv_bfloat16* __restrict__ Al,
    const __nv_bfloat16* __restrict__ Bh, const __nv_bfloat16* __restrict__ Bl,
    float* __restrict__ Cf, __nv_bfloat16* __restrict__ Oh,
    __nv_bfloat16* __restrict__ Ol, int mode)
{
    extern __shared__ char smem[];
    const uint32_t sb = smem_u32(smem);
    const int tid = threadIdx.x, w = tid >> 5, lane = tid & 31;
    const int gid = lane >> 2, tig = lane & 3;
    const int m0 = blockIdx.x * 128, n0 = blockIdx.y * 128;
    const int wm = (w >> 2) * 64, wn = (w & 3) * 32;

    float c[4][4][4];
#pragma unroll
    for (int mt = 0; mt < 4; mt++)
#pragma unroll
        for (int nt = 0; nt < 4; nt++)
#pragma unroll
            for (int j = 0; j < 4; j++) c[mt][nt][j] = 0.0f;

    const uint32_t aAddr = sb + ((unsigned)(wm + (lane & 15)) * SPD + (lane >> 4) * 8) * 2;
    const uint32_t bAddr = sb + ((unsigned)(wn + (lane & 7)) * SPD + ((lane >> 3) & 1) * 8) * 2;

    for (int kc = 0; kc < 512; kc += 64) {
#pragma unroll
        for (int it = 0; it < 4; it++) {
            int idx = it * 256 + tid, row = idx >> 3, cu = idx & 7;
            *(uint4*)(smem + PJ_AH + row * 144 + cu * 16) =
                *(const uint4*)(Ah + (size_t)(m0 + row) * 512 + kc + cu * 8);
            *(uint4*)(smem + PJ_AL + row * 144 + cu * 16) =
                *(const uint4*)(Al + (size_t)(m0 + row) * 512 + kc + cu * 8);
            *(uint4*)(smem + PJ_BH + row * 144 + cu * 16) =
                *(const uint4*)(Bh + (size_t)(n0 + row) * 512 + kc + cu * 8);
            *(uint4*)(smem + PJ_BL + row * 144 + cu * 16) =
                *(const uint4*)(Bl + (size_t)(n0 + row) * 512 + kc + cu * 8);
        }
        __syncthreads();
#pragma unroll
        for (int ks = 0; ks < 4; ks++) {
            unsigned ah[4][4], al[4][4], bh[4][2], bl[4][2];
#pragma unroll
            for (int mt = 0; mt < 4; mt++) {
                ldm_x4(ah[mt], aAddr + PJ_AH + (mt * 16 * SPD + ks * 16) * 2);
                ldm_x4(al[mt], aAddr + PJ_AL + (mt * 16 * SPD + ks * 16) * 2);
            }
#pragma unroll
            for (int nt = 0; nt < 4; nt++) {
                ldm_x2(bh[nt], bAddr + PJ_BH + (nt * 8 * SPD + ks * 16) * 2);
                ldm_x2(bl[nt], bAddr + PJ_BL + (nt * 8 * SPD + ks * 16) * 2);
            }
#pragma unroll
            for (int mt = 0; mt < 4; mt++)
#pragma unroll
                for (int nt = 0; nt < 4; nt++) {
                    MMA(c[mt][nt], ah[mt], bh[nt]);
                    MMA(c[mt][nt], ah[mt], bl[nt]);
                    MMA(c[mt][nt], al[mt], bh[nt]);
                }
        }
        __syncthreads();
    }

    if (mode == 1) {
        float* stage = (float*)smem;  // 128 x 129 f32
#pragma unroll
        for (int mt = 0; mt < 4; mt++)
#pragma unroll
            for (int nt = 0; nt < 4; nt++) {
                int r0 = wm + mt * 16 + gid, cc0 = wn + nt * 8 + 2 * tig;
                stage[r0 * 129 + cc0] = c[mt][nt][0];
                stage[r0 * 129 + cc0 + 1] = c[mt][nt][1];
                stage[(r0 + 8) * 129 + cc0] = c[mt][nt][2];
                stage[(r0 + 8) * 129 + cc0 + 1] = c[mt][nt][3];
            }
        __syncthreads();
        const int bb = m0 >> 10, seq0 = m0 & 1023;
        const int m_local = tid & 127, nsel = tid >> 7;
#pragma unroll 8
        for (int rep = 0; rep < 64; rep++) {
            int n_local = rep * 2 + nsel;
            int n = n0 + n_local;
            int hh = n >> 6, dh = n & 63;
            size_t ob = ((size_t)((bb * 8 + hh) * 64 + dh)) * 1024 + seq0 + m_local;
            float f = stage[m_local * 129 + n_local];
            __nv_bfloat16 hbf = __float2bfloat16_rn(f);
            Oh[ob] = hbf;
            Ol[ob] = __float2bfloat16_rn(f - __bfloat162float(hbf));
        }
    } else if (mode == 2) {
#pragma unroll
        for (int mt = 0; mt < 4; mt++)
#pragma unroll
            for (int nt = 0; nt < 4; nt++) {
                int r0 = m0 + wm + mt * 16 + gid, cc0 = n0 + wn + nt * 8 + 2 * tig;
                *(float2*)(Cf + (size_t)r0 * 512 + cc0) =
                    make_float2(c[mt][nt][0], c[mt][nt][1]);
                *(float2*)(Cf + (size_t)(r0 + 8) * 512 + cc0) =
                    make_float2(c[mt][nt][2], c[mt][nt][3]);
            }
    } else {
#pragma unroll
        for (int mt = 0; mt < 4; mt++)
#pragma unroll
            for (int nt = 0; nt < 4; nt++) {
                int r0 = m0 + wm + mt * 16 + gid, cc0 = n0 + wn + nt * 8 + 2 * tig;
                unsigned hp, lp;
                split2(c[mt][nt][0], c[mt][nt][1], hp, lp);
                *(unsigned*)(Oh + (size_t)r0 * 512 + cc0) = hp;
                *(unsigned*)(Ol + (size_t)r0 * 512 + cc0) = lp;
                split2(c[mt][nt][2], c[mt][nt][3], hp, lp);
                *(unsigned*)(Oh + (size_t)(r0 + 8) * 512 + cc0) = hp;
                *(unsigned*)(Ol + (size_t)(r0 + 8) * 512 + cc0) = lp;
            }
    }
}

// ---------------- fused attention (mma.sync) ----------------
// CTA: (bh, 128 q rows). 8 warps, warp = 16 q rows. K chunks of 128.
#define VSPD 136        // Vt smem row stride bf16 (272 B)
#define AT_SUMS 0
#define AT_QH 1024
#define AT_QL 19456
#define AT_KH 37888
#define AT_KL 56320
#define AT_VH 74752
#define AT_VL 92160
#define AT_SMEM 109568

__global__ void __launch_bounds__(256) attn_kernel(float* __restrict__ att)
{
    extern __shared__ char smem[];
    const uint32_t sb = smem_u32(smem);
    float* sums = (float*)(smem + AT_SUMS);
    const int tid = threadIdx.x, w = tid >> 5, lane = tid & 31;
    const int gid = lane >> 2, tig = lane & 3;
    const int bh = blockIdx.x, b = bh >> 3, h = bh & 7;
    const int q0 = blockIdx.y * 128;
    const float SCL = 0.18033688011112042f; // 0.125 * log2(e)

    // ---- load Q tile (hi/lo) ----
    {
        const size_t qoff = ((size_t)(b * 1024 + q0)) * 512 + h * 64;
#pragma unroll
        for (int it = 0; it < 4; it++) {
            int idx = it * 256 + tid, row = idx >> 3, cu = idx & 7;
            *(uint4*)(smem + AT_QH + row * 144 + cu * 16) =
                *(const uint4*)(g_Qh + qoff + (size_t)row * 512 + cu * 8);
            *(uint4*)(smem + AT_QL + row * 144 + cu * 16) =
                *(const uint4*)(g_Ql + qoff + (size_t)row * 512 + cu * 8);
        }
    }
    __syncthreads();

    // ---- Q fragments (persistent) ----
    unsigned aqh[4][4], aql[4][4];
    {
        const uint32_t qa = sb + ((unsigned)(w * 16 + (lane & 15)) * SPD + (lane >> 4) * 8) * 2;
#pragma unroll
        for (int ks = 0; ks < 4; ks++) {
            ldm_x4(aqh[ks], qa + AT_QH + ks * 32);
            ldm_x4(aql[ks], qa + AT_QL + ks * 32);
        }
    }

    const size_t rb0 = (size_t)(b * 1024 + q0 + w * 16 + gid) * 32;
    const size_t rb1 = rb0 + 8 * 32;
    const uint32_t kAddr = sb + ((unsigned)(lane & 7) * SPD + ((lane >> 3) & 1) * 8) * 2;
    const uint32_t vAddr = sb + ((unsigned)(lane & 7) * VSPD + ((lane >> 3) & 1) * 8) * 2;

    // ================ PASS 1: exp row sums ================
    float rs0 = 0.0f, rs1 = 0.0f;
    for (int kc = 0; kc < 1024; kc += 128) {
        const size_t koff = ((size_t)(b * 1024 + kc)) * 512 + h * 64;
#pragma unroll
        for (int it = 0; it < 4; it++) {
            int idx = it * 256 + tid, row = idx >> 3, cu = idx & 7;
            *(uint4*)(smem + AT_KH + row * 144 + cu * 16) =
                *(const uint4*)(g_Kh + koff + (size_t)row * 512 + cu * 8);
            *(uint4*)(smem + AT_KL + row * 144 + cu * 16) =
                *(const uint4*)(g_Kl + koff + (size_t)row * 512 + cu * 8);
        }
        __syncthreads();
        unsigned aw0[4], aw1[4];
#pragma unroll
        for (int j = 0; j < 4; j++) {
            aw0[j] = g_am[rb0 + (kc >> 5) + j];
            aw1[j] = g_am[rb1 + (kc >> 5) + j];
        }
#pragma unroll
        for (int nt = 0; nt < 16; nt++) {
            float cc[4] = {0, 0, 0, 0};
#pragma unroll
            for (int ks = 0; ks < 4; ks++) {
                unsigned bhf[2], blf[2];
                ldm_x2(bhf, kAddr + AT_KH + (nt * 8 * SPD + ks * 16) * 2);
                ldm_x2(blf, kAddr + AT_KL + (nt * 8 * SPD + ks * 16) * 2);
                MMA(cc, aqh[ks], bhf);
                MMA(cc, aqh[ks], blf);
                MMA(cc, aql[ks], bhf);
            }
            int bidx = nt * 8 + 2 * tig;
            unsigned w0 = aw0[bidx >> 5], w1 = aw1[bidx >> 5];
            int bo = bidx & 31;
            float t0 = cc[0] * SCL, t1 = cc[1] * SCL;
            float t2 = cc[2] * SCL, t3 = cc[3] * SCL;
            if ((w0 >> bo) & 1u) t0 = -1e30f;
            if ((w0 >> (bo + 1)) & 1u) t1 = -1e30f;
            if ((w1 >> bo) & 1u) t2 = -1e30f;
            if ((w1 >> (bo + 1)) & 1u) t3 = -1e30f;
            rs0 += fexp2(t0) + fexp2(t1);
            rs1 += fexp2(t2) + fexp2(t3);
        }
        __syncthreads();
    }
    rs0 += __shfl_xor_sync(0xffffffffu, rs0, 1);
    rs0 += __shfl_xor_sync(0xffffffffu, rs0, 2);
    rs1 += __shfl_xor_sync(0xffffffffu, rs1, 1);
    rs1 += __shfl_xor_sync(0xffffffffu, rs1, 2);
    if (tig == 0) {
        sums[w * 16 + gid] = rs0;
        sums[w * 16 + gid + 8] = rs1;
    }
    __syncthreads();
    const float inv0 = 1.0f / sums[w * 16 + gid];
    const float inv1 = 1.0f / sums[w * 16 + gid + 8];
    float* arow0 = att ? att + ((size_t)(bh * 1024 + q0 + w * 16 + gid)) * 1024 : (float*)0;
    float* arow1 = arow0 ? arow0 + (size_t)8 * 1024 : (float*)0;

    // ================ PASS 2: normalize + write att + P.V ================
    float ctx[8][4];
#pragma unroll
    for (int dt = 0; dt < 8; dt++)
#pragma unroll
        for (int j = 0; j < 4; j++) ctx[dt][j] = 0.0f;

    const size_t vbase = (size_t)(bh * 64) * 1024;
    for (int kc = 0; kc < 1024; kc += 128) {
        const size_t koff = ((size_t)(b * 1024 + kc)) * 512 + h * 64;
#pragma unroll
        for (int it = 0; it < 4; it++) {
            int idx = it * 256 + tid, row = idx >> 3, cu = idx & 7;
            *(uint4*)(smem + AT_KH + row * 144 + cu * 16) =
                *(const uint4*)(g_Kh + koff + (size_t)row * 512 + cu * 8);
            *(uint4*)(smem + AT_KL + row * 144 + cu * 16) =
                *(const uint4*)(g_Kl + koff + (size_t)row * 512 + cu * 8);
        }
#pragma unroll
        for (int it = 0; it < 4; it++) {
            int idx = it * 256 + tid, row = idx >> 4, cu = idx & 15;
            *(uint4*)(smem + AT_VH + row * 272 + cu * 16) =
                *(const uint4*)(g_Vth + vbase + (size_t)row * 1024 + kc + cu * 8);
            *(uint4*)(smem + AT_VL + row * 272 + cu * 16) =
                *(const uint4*)(g_Vtl + vbase + (size_t)row * 1024 + kc + cu * 8);
        }
        __syncthreads();
        unsigned aw0[4], aw1[4], sw0[4], sw1[4];
#pragma unroll
        for (int j = 0; j < 4; j++) {
            aw0[j] = g_am[rb0 + (kc >> 5) + j];
            aw1[j] = g_am[rb1 + (kc >> 5) + j];
            sw0[j] = g_sm[rb0 + (kc >> 5) + j];
            sw1[j] = g_sm[rb1 + (kc >> 5) + j];
        }
#pragma unroll
        for (int nt2 = 0; nt2 < 8; nt2++) {
            unsigned ph[4], pl[4];
#pragma unroll
            for (int half = 0; half < 2; half++) {
                int nt = nt2 * 2 + half;
                float cc[4] = {0, 0, 0, 0};
#pragma unroll
                for (int ks = 0; ks < 4; ks++) {
                    unsigned bhf[2], blf[2];
                    ldm_x2(bhf, kAddr + AT_KH + (nt * 8 * SPD + ks * 16) * 2);
                    ldm_x2(blf, kAddr + AT_KL + (nt * 8 * SPD + ks * 16) * 2);
                    MMA(cc, aqh[ks], bhf);
                    MMA(cc, aqh[ks], blf);
                    MMA(cc, aql[ks], bhf);
                }
                int bidx = nt * 8 + 2 * tig;
                unsigned w0 = aw0[bidx >> 5], w1 = aw1[bidx >> 5];
                unsigned s0 = sw0[bidx >> 5], s1 = sw1[bidx >> 5];
                int bo = bidx & 31;
                float t0 = cc[0] * SCL, t1 = cc[1] * SCL;
                float t2 = cc[2] * SCL, t3 = cc[3] * SCL;
                if ((w0 >> bo) & 1u) t0 = -1e30f;
                if ((w0 >> (bo + 1)) & 1u) t1 = -1e30f;
                if ((w1 >> bo) & 1u) t2 = -1e30f;
                if ((w1 >> (bo + 1)) & 1u) t3 = -1e30f;
                float p0 = fexp2(t0) * inv0, p1 = fexp2(t1) * inv0;
                float p2 = fexp2(t2) * inv1, p3 = fexp2(t3) * inv1;
                if ((s0 >> bo) & 1u) p0 = 0.0f;
                if ((s0 >> (bo + 1)) & 1u) p1 = 0.0f;
                if ((s1 >> bo) & 1u) p2 = 0.0f;
                if ((s1 >> (bo + 1)) & 1u) p3 = 0.0f;
                if (arow0) {
                    *(float2*)(arow0 + kc + bidx) = make_float2(p0, p1);
                    *(float2*)(arow1 + kc + bidx) = make_float2(p2, p3);
                }
                unsigned hp, lp;
                split2(p0, p1, hp, lp);
                ph[0 + half * 2] = hp; pl[0 + half * 2] = lp;
                split2(p2, p3, hp, lp);
                ph[1 + half * 2] = hp; pl[1 + half * 2] = lp;
            }
#pragma unroll
            for (int dt = 0; dt < 8; dt++) {
                unsigned bvh[2], bvl[2];
                ldm_x2(bvh, vAddr + AT_VH + (dt * 8 * VSPD + nt2 * 16) * 2);
                ldm_x2(bvl, vAddr + AT_VL + (dt * 8 * VSPD + nt2 * 16) * 2);
                MMA(ctx[dt], ph, bvh);
                MMA(ctx[dt], ph, bvl);
                MMA(ctx[dt], pl, bvh);
            }
        }
        __syncthreads();
    }

    // ---- ctx epilogue: hi/lo row-major ----
    {
        size_t r0 = (size_t)(b * 1024 + q0 + w * 16 + gid) * 512 + h * 64;
        size_t r1 = r0 + (size_t)8 * 512;
#pragma unroll
        for (int dt = 0; dt < 8; dt++) {
            int cc0 = dt * 8 + 2 * tig;
            unsigned hp, lp;
            split2(ctx[dt][0], ctx[dt][1], hp, lp);
            *(unsigned*)(g_Ch + r0 + cc0) = hp;
            *(unsigned*)(g_Cl + r0 + cc0) = lp;
            split2(ctx[dt][2], ctx[dt][3], hp, lp);
            *(unsigned*)(g_Ch + r1 + cc0) = hp;
            *(unsigned*)(g_Cl + r1 + cc0) = lp;
        }
    }
}

// ---------------- residual + LayerNorm ----------------
__global__ void __launch_bounds__(256) ln_kernel(
    const float* __restrict__ proj, const float* __restrict__ res,
    float* __restrict__ out)
{
    __shared__ float reds[8], redq[8];
    const int row = blockIdx.x, tid = threadIdx.x;
    const float* p = proj + (size_t)row * ND;
    const float* rr = res + (size_t)row * ND;
    float x0 = rr[tid] + p[tid];
    float x1 = rr[tid + 256] + p[tid + 256];
    float s = x0 + x1, q = x0 * x0 + x1 * x1;
#pragma unroll
    for (int o = 16; o > 0; o >>= 1) {
        s += __shfl_xor_sync(0xffffffffu, s, o);
        q += __shfl_xor_sync(0xffffffffu, q, o);
    }
    if ((tid & 31) == 0) { reds[tid >> 5] = s; redq[tid >> 5] = q; }
    __syncthreads();
    float ts = 0, tq = 0;
#pragma unroll
    for (int i = 0; i < 8; i++) { ts += reds[i]; tq += redq[i]; }
    float mean = ts * (1.0f / ND);
    float var = tq * (1.0f / ND) - mean * mean;
    float rsv = rsqrtf(var + 1e-5f);
    out[(size_t)row * ND + tid] = (x0 - mean) * rsv;
    out[(size_t)row * ND + tid + 256] = (x1 - mean) * rsv;
}

// ---------------------------------------------------------------------------
extern "C" void kernel_launch(void* const* d_in, const int* in_sizes, int n_in,
                              void* d_out, int out_size)
{
    const float* query = (const float*)d_in[0];
    const float* key   = (const float*)d_in[1];
    const float* value = (const float*)d_in[2];
    const void*  amask = d_in[3];
    const void*  smask = d_in[4];
    const float* Wq = (const float*)d_in[5];
    const float* Wk = (const float*)d_in[6];
    const float* Wv = (const float*)d_in[7];
    const float* Wo = (const float*)d_in[8];

    float* out = (float*)d_out;
    float* att = ((size_t)out_size >= ACT_ELEMS + ATT_ELEMS) ? out + ACT_ELEMS : (float*)0;

    void *pAh,*pAl,*pWh,*pWl,*pQh,*pQl,*pKh,*pKl,*pVth,*pVtl,*pCh,*pCl,*pPf,*pAm,*pSm;
    cudaGetSymbolAddress(&pAh, g_Ah);   cudaGetSymbolAddress(&pAl, g_Al);
    cudaGetSymbolAddress(&pWh, g_Wh);   cudaGetSymbolAddress(&pWl, g_Wl);
    cudaGetSymbolAddress(&pQh, g_Qh);   cudaGetSymbolAddress(&pQl, g_Ql);
    cudaGetSymbolAddress(&pKh, g_Kh);   cudaGetSymbolAddress(&pKl, g_Kl);
    cudaGetSymbolAddress(&pVth, g_Vth); cudaGetSymbolAddress(&pVtl, g_Vtl);
    cudaGetSymbolAddress(&pCh, g_Ch);   cudaGetSymbolAddress(&pCl, g_Cl);
    cudaGetSymbolAddress(&pPf, g_projf);
    cudaGetSymbolAddress(&pAm, g_am);   cudaGetSymbolAddress(&pSm, g_sm);

    cudaFuncSetAttribute(proj_kernel, cudaFuncAttributeMaxDynamicSharedMemorySize, PJ_SMEM);
    cudaFuncSetAttribute(attn_kernel, cudaFuncAttributeMaxDynamicSharedMemorySize, AT_SMEM);

    detect_mask_kernel<<<1, 256>>>((const unsigned*)amask);
    pack_mask_kernel<<<MASK_WORDS / 256, 256>>>(amask, (unsigned*)pAm);
    pack_mask_kernel<<<MASK_WORDS / 256, 256>>>(smask, (unsigned*)pSm);

    const int nA4 = (int)(ACT_ELEMS / 4), nW4 = (int)(W_ELEMS / 4);
    dim3 pgrid(TOK / 128, ND / 128);

    conv_split_kernel<<<nA4 / 256, 256>>>((const float4*)query,
        (__nv_bfloat16*)pAh, (__nv_bfloat16*)pAl, nA4);
    conv_split_kernel<<<nW4 / 256, 256>>>((const float4*)Wq,
        (__nv_bfloat16*)pWh, (__nv_bfloat16*)pWl, nW4);
    proj_kernel<<<pgrid, 256, PJ_SMEM>>>((const __nv_bfloat16*)pAh, (const __nv_bfloat16*)pAl,
        (const __nv_bfloat16*)pWh, (const __nv_bfloat16*)pWl,
        (float*)0, (__nv_bfloat16*)pQh, (__nv_bfloat16*)pQl, 0);

    conv_split_kernel<<<nA4 / 256, 256>>>((const float4*)key,
        (__nv_bfloat16*)pAh, (__nv_bfloat16*)pAl, nA4);
    conv_split_kernel<<<nW4 / 256, 256>>>((const float4*)Wk,
        (__nv_bfloat16*)pWh, (__nv_bfloat16*)pWl, nW4);
    proj_kernel<<<pgrid, 256, PJ_SMEM>>>((const __nv_bfloat16*)pAh, (const __nv_bfloat16*)pAl,
        (const __nv_bfloat16*)pWh, (const __nv_bfloat16*)pWl,
        (float*)0, (__nv_bfloat16*)pKh, (__nv_bfloat16*)pKl, 0);

    conv_split_kernel<<<nA4 / 256, 256>>>((const float4*)value,
        (__nv_bfloat16*)pAh, (__nv_bfloat16*)pAl, nA4);
    conv_split_kernel<<<nW4 / 256, 256>>>((const float4*)Wv,
        (__nv_bfloat16*)pWh, (__nv_bfloat16*)pWl, nW4);
    proj_kernel<<<pgrid, 256, PJ_SMEM>>>((const __nv_bfloat16*)pAh, (const __nv_bfloat16*)pAl,
        (const __nv_bfloat16*)pWh, (const __nv_bfloat16*)pWl,
        (float*)0, (__nv_bfloat16*)pVth, (__nv_bfloat16*)pVtl, 1);

    attn_kernel<<<dim3(NB * NH, NL / 128), 256, AT_SMEM>>>(att);

    conv_split_kernel<<<nW4 / 256, 256>>>((const float4*)Wo,
        (__nv_bfloat16*)pWh, (__nv_bfloat16*)pWl, nW4);
    proj_kernel<<<pgrid, 256, PJ_SMEM>>>((const __nv_bfloat16*)pCh, (const __nv_bfloat16*)pCl,
        (const __nv_bfloat16*)pWh, (const __nv_bfloat16*)pWl,
        (float*)pPf, (__nv_bfloat16*)0, (__nv_bfloat16*)0, 2);

    ln_kernel<<<TOK, 256>>>((const float*)pPf, query, out);
}

// round 8
// speedup vs baseline: 2.4601x; 1.0779x over previous
#include <cuda_runtime.h>
#include <cuda_bf16.h>
#include <math.h>
#include <stdint.h>

#define NB 8
#define NL 1024
#define ND 512
#define NH 8
#define NDH 64
#define TOK (NB * NL)
#define ACT_ELEMS ((size_t)TOK * ND)
#define W_ELEMS ((size_t)ND * ND)
#define ATT_ELEMS ((size_t)NB * NH * NL * NL)
#define MASK_WORDS (ATT_ELEMS / 32)

__device__ __nv_bfloat16 g_Ah[ACT_ELEMS], g_Al[ACT_ELEMS];
__device__ __nv_bfloat16 g_Wh[W_ELEMS],  g_Wl[W_ELEMS];
__device__ __nv_bfloat16 g_Qh[ACT_ELEMS], g_Ql[ACT_ELEMS];
__device__ __nv_bfloat16 g_Kh[ACT_ELEMS], g_Kl[ACT_ELEMS];
__device__ __nv_bfloat16 g_Vth[ACT_ELEMS], g_Vtl[ACT_ELEMS]; // [bh*64+d][1024]
__device__ __nv_bfloat16 g_Ch[ACT_ELEMS], g_Cl[ACT_ELEMS];
__device__ float        g_projf[ACT_ELEMS];
__device__ float        g_inv[(size_t)NB * NH * NL];
__device__ unsigned     g_am[MASK_WORDS], g_sm[MASK_WORDS];
__device__ int          g_mask_mode;

// ---------------- helpers ----------------
__device__ __forceinline__ uint32_t smem_u32(const void* p) {
    uint32_t a;
    asm("{ .reg .u64 t; cvta.to.shared.u64 t, %1; cvt.u32.u64 %0, t; }" : "=r"(a) : "l"(p));
    return a;
}
__device__ __forceinline__ void ldm_x4(unsigned r[4], uint32_t a) {
    asm volatile("ldmatrix.sync.aligned.m8n8.x4.shared.b16 {%0,%1,%2,%3}, [%4];"
                 : "=r"(r[0]), "=r"(r[1]), "=r"(r[2]), "=r"(r[3]) : "r"(a) : "memory");
}
#define MMA(c, a, b) \
    asm volatile("mma.sync.aligned.m16n8k16.row.col.f32.bf16.bf16.f32 " \
                 "{%0,%1,%2,%3},{%4,%5,%6,%7},{%8,%9},{%0,%1,%2,%3};" \
                 : "+f"((c)[0]), "+f"((c)[1]), "+f"((c)[2]), "+f"((c)[3]) \
                 : "r"((a)[0]), "r"((a)[1]), "r"((a)[2]), "r"((a)[3]), \
                   "r"((b)[0]), "r"((b)[1]))

#define CP16(dst, src) \
    asm volatile("cp.async.cg.shared.global [%0], [%1], 16;" :: "r"(dst), "l"(src) : "memory")
#define CP_COMMIT() asm volatile("cp.async.commit_group;" ::: "memory")
#define CP_WAIT(n)  asm volatile("cp.async.wait_group %0;" :: "n"(n) : "memory")

__device__ __forceinline__ void split2(float f0, float f1, unsigned& hp, unsigned& lp) {
    __nv_bfloat16 h0 = __float2bfloat16_rn(f0), h1 = __float2bfloat16_rn(f1);
    __nv_bfloat16 l0 = __float2bfloat16_rn(f0 - __bfloat162float(h0));
    __nv_bfloat16 l1 = __float2bfloat16_rn(f1 - __bfloat162float(h1));
    hp = (unsigned)__bfloat16_as_ushort(h0) | ((unsigned)__bfloat16_as_ushort(h1) << 16);
    lp = (unsigned)__bfloat16_as_ushort(l0) | ((unsigned)__bfloat16_as_ushort(l1) << 16);
}

__device__ __forceinline__ float fexp2(float x) {
    x = fmaxf(fminf(x, 120.0f), -126.0f);
    float fl = floorf(x);
    float f = x - fl;
    float p = 1.52527338e-5f;
    p = fmaf(p, f, 1.54035304e-4f);
    p = fmaf(p, f, 1.33335581e-3f);
    p = fmaf(p, f, 9.61812911e-3f);
    p = fmaf(p, f, 5.55041087e-2f);
    p = fmaf(p, f, 2.40226507e-1f);
    p = fmaf(p, f, 6.93147181e-1f);
    p = fmaf(p, f, 1.0f);
    return __int_as_float(__float_as_int(p) + (((int)fl) << 23));
}

// ---------------- prep kernels ----------------
__global__ void detect_mask_kernel(const unsigned* __restrict__ m) {
    __shared__ int f32flag, u8flag;
    if (threadIdx.x == 0) { f32flag = 0; u8flag = 0; }
    __syncthreads();
    int lf = 0, lu = 0;
    for (int i = threadIdx.x; i < 4096; i += blockDim.x) {
        unsigned w = m[i];
        if (w == 0x3f800000u) lf = 1;
        else if (w > 1u) lu = 1;
    }
    if (lf) atomicOr(&f32flag, 1);
    if (lu) atomicOr(&u8flag, 1);
    __syncthreads();
    if (threadIdx.x == 0) g_mask_mode = f32flag ? 2 : (u8flag ? 0 : 1);
}

__global__ void pack_mask_kernel(const void* __restrict__ m, unsigned* __restrict__ out) {
    int w = blockIdx.x * 256 + threadIdx.x;
    if (w >= (int)MASK_WORDS) return;
    int mode = g_mask_mode;
    unsigned bits = 0;
    if (mode == 0) {
        const unsigned* p = (const unsigned*)m + (size_t)w * 8;
#pragma unroll
        for (int j = 0; j < 8; j++) {
            unsigned v = __vcmpne4(p[j], 0u);
            bits |= ((((v & 0x01010101u) * 0x01020408u) >> 24) & 0xFu) << (j * 4);
        }
    } else if (mode == 1) {
        const int* p = (const int*)m + (size_t)w * 32;
#pragma unroll
        for (int j = 0; j < 32; j++) bits |= (unsigned)(p[j] != 0) << j;
    } else {
        const float* p = (const float*)m + (size_t)w * 32;
#pragma unroll
        for (int j = 0; j < 32; j++) bits |= (unsigned)(p[j] != 0.0f) << j;
    }
    out[w] = bits;
}

__global__ void conv_split_kernel(const float4* __restrict__ x,
                                  __nv_bfloat16* __restrict__ hi,
                                  __nv_bfloat16* __restrict__ lo, int n4) {
    int i = blockIdx.x * 256 + threadIdx.x;
    if (i >= n4) return;
    float4 v = x[i];
    unsigned h0, l0, h1, l1;
    split2(v.x, v.y, h0, l0);
    split2(v.z, v.w, h1, l1);
    ((uint2*)hi)[i] = make_uint2(h0, h1);
    ((uint2*)lo)[i] = make_uint2(l0, l1);
}

// ---------------- projection GEMM (mma.sync, 3-term split bf16) ------------
#define SPD 72
#define PJ_AH 0
#define PJ_AL 18432
#define PJ_BH 36864
#define PJ_BL 55296
#define PJ_SMEM 73728

__global__ void __launch_bounds__(256) proj_kernel(
    const __nv_bfloat16* __restrict__ Ah, const __nv_bfloat16* __restrict__ Al,
    const __nv_bfloat16* __restrict__ Bh, const __nv_bfloat16* __restrict__ Bl,
    float* __restrict__ Cf, __nv_bfloat16* __restrict__ Oh,
    __nv_bfloat16* __restrict__ Ol, int mode)
{
    extern __shared__ char smem[];
    const uint32_t sb = smem_u32(smem);
    const int tid = threadIdx.x, w = tid >> 5, lane = tid & 31;
    const int gid = lane >> 2, tig = lane & 3;
    const int m0 = blockIdx.x * 128, n0 = blockIdx.y * 128;
    const int wm = (w >> 2) * 64, wn = (w & 3) * 32;
    const int rowsel = (lane & 7) + ((lane >> 4) << 3);
    const int colsel = ((lane >> 3) & 1) * 8;

    float c[4][4][4];
#pragma unroll
    for (int mt = 0; mt < 4; mt++)
#pragma unroll
        for (int nt = 0; nt < 4; nt++)
#pragma unroll
            for (int j = 0; j < 4; j++) c[mt][nt][j] = 0.0f;

    const uint32_t aAddr = sb + ((unsigned)(wm + (lane & 15)) * SPD + (lane >> 4) * 8) * 2;
    const uint32_t bAddr4 = sb + ((unsigned)(wn + rowsel) * SPD + colsel) * 2;

    for (int kc = 0; kc < 512; kc += 64) {
#pragma unroll
        for (int it = 0; it < 4; it++) {
            int idx = it * 256 + tid, row = idx >> 3, cu = idx & 7;
            *(uint4*)(smem + PJ_AH + row * 144 + cu * 16) =
                *(const uint4*)(Ah + (size_t)(m0 + row) * 512 + kc + cu * 8);
            *(uint4*)(smem + PJ_AL + row * 144 + cu * 16) =
                *(const uint4*)(Al + (size_t)(m0 + row) * 512 + kc + cu * 8);
            *(uint4*)(smem + PJ_BH + row * 144 + cu * 16) =
                *(const uint4*)(Bh + (size_t)(n0 + row) * 512 + kc + cu * 8);
            *(uint4*)(smem + PJ_BL + row * 144 + cu * 16) =
                *(const uint4*)(Bl + (size_t)(n0 + row) * 512 + kc + cu * 8);
        }
        __syncthreads();
#pragma unroll
        for (int ks = 0; ks < 4; ks++) {
            unsigned ah[4][4], al[4][4], bh4[2][4], bl4[2][4];
#pragma unroll
            for (int mt = 0; mt < 4; mt++) {
                ldm_x4(ah[mt], aAddr + PJ_AH + (mt * 16 * SPD + ks * 16) * 2);
                ldm_x4(al[mt], aAddr + PJ_AL + (mt * 16 * SPD + ks * 16) * 2);
            }
#pragma unroll
            for (int p = 0; p < 2; p++) {
                ldm_x4(bh4[p], bAddr4 + PJ_BH + (p * 16 * SPD + ks * 16) * 2);
                ldm_x4(bl4[p], bAddr4 + PJ_BL + (p * 16 * SPD + ks * 16) * 2);
            }
#pragma unroll
            for (int mt = 0; mt < 4; mt++)
#pragma unroll
                for (int nt = 0; nt < 4; nt++) {
                    unsigned* bh = &bh4[nt >> 1][(nt & 1) * 2];
                    unsigned* bl = &bl4[nt >> 1][(nt & 1) * 2];
                    MMA(c[mt][nt], ah[mt], bh);
                    MMA(c[mt][nt], ah[mt], bl);
                    MMA(c[mt][nt], al[mt], bh);
                }
        }
        __syncthreads();
    }

    if (mode == 1) {
        float* stage = (float*)smem;  // 128 x 129 f32
#pragma unroll
        for (int mt = 0; mt < 4; mt++)
#pragma unroll
            for (int nt = 0; nt < 4; nt++) {
                int r0 = wm + mt * 16 + gid, cc0 = wn + nt * 8 + 2 * tig;
                stage[r0 * 129 + cc0] = c[mt][nt][0];
                stage[r0 * 129 + cc0 + 1] = c[mt][nt][1];
                stage[(r0 + 8) * 129 + cc0] = c[mt][nt][2];
                stage[(r0 + 8) * 129 + cc0 + 1] = c[mt][nt][3];
            }
        __syncthreads();
        const int bb = m0 >> 10, seq0 = m0 & 1023;
        const int m_local = tid & 127, nsel = tid >> 7;
#pragma unroll 8
        for (int rep = 0; rep < 64; rep++) {
            int n_local = rep * 2 + nsel;
            int n = n0 + n_local;
            int hh = n >> 6, dh = n & 63;
            size_t ob = ((size_t)((bb * 8 + hh) * 64 + dh)) * 1024 + seq0 + m_local;
            float f = stage[m_local * 129 + n_local];
            __nv_bfloat16 hbf = __float2bfloat16_rn(f);
            Oh[ob] = hbf;
            Ol[ob] = __float2bfloat16_rn(f - __bfloat162float(hbf));
        }
    } else if (mode == 2) {
#pragma unroll
        for (int mt = 0; mt < 4; mt++)
#pragma unroll
            for (int nt = 0; nt < 4; nt++) {
                int r0 = m0 + wm + mt * 16 + gid, cc0 = n0 + wn + nt * 8 + 2 * tig;
                *(float2*)(Cf + (size_t)r0 * 512 + cc0) =
                    make_float2(c[mt][nt][0], c[mt][nt][1]);
                *(float2*)(Cf + (size_t)(r0 + 8) * 512 + cc0) =
                    make_float2(c[mt][nt][2], c[mt][nt][3]);
            }
    } else {
#pragma unroll
        for (int mt = 0; mt < 4; mt++)
#pragma unroll
            for (int nt = 0; nt < 4; nt++) {
                int r0 = m0 + wm + mt * 16 + gid, cc0 = n0 + wn + nt * 8 + 2 * tig;
                unsigned hp, lp;
                split2(c[mt][nt][0], c[mt][nt][1], hp, lp);
                *(unsigned*)(Oh + (size_t)r0 * 512 + cc0) = hp;
                *(unsigned*)(Ol + (size_t)r0 * 512 + cc0) = lp;
                split2(c[mt][nt][2], c[mt][nt][3], hp, lp);
                *(unsigned*)(Oh + (size_t)(r0 + 8) * 512 + cc0) = hp;
                *(unsigned*)(Ol + (size_t)(r0 + 8) * 512 + cc0) = lp;
            }
    }
}

// ---------------- fused single-pass attention ----------------
// CTA: (bh, 128 q rows), 8 warps x 16 q rows. cp.async double-buffered K/V.
// ctx accumulated with UNNORMALIZED P; att written unnormalized; normalized
// by att_norm_kernel using g_inv.
#define VSPD 136
#define AT_QH 1024
#define AT_QL 19456
#define AT_BUF0 37888
#define AT_BUFSZ 71680
#define KH_OFF 0
#define KL_OFF 18432
#define VH_OFF 36864
#define VL_OFF 54272
#define AT_SMEM 181248

__global__ void __launch_bounds__(256) attn_kernel(float* __restrict__ att)
{
    extern __shared__ char smem[];
    const uint32_t sb = smem_u32(smem);
    float* sums = (float*)smem;
    const int tid = threadIdx.x, w = tid >> 5, lane = tid & 31;
    const int gid = lane >> 2, tig = lane & 3;
    const int bh = blockIdx.x, b = bh >> 3, h = bh & 7;
    const int q0 = blockIdx.y * 128;
    const float SCL = 0.18033688011112042f; // 0.125 * log2(e)
    const int rowsel = (lane & 7) + ((lane >> 4) << 3);
    const int colsel = ((lane >> 3) & 1) * 8;
    const unsigned klane = ((unsigned)rowsel * SPD + colsel) * 2;
    const unsigned vlane = ((unsigned)rowsel * VSPD + colsel) * 2;

    // ---- Q tile ----
    {
        const size_t qoff = ((size_t)(b * 1024 + q0)) * 512 + h * 64;
#pragma unroll
        for (int it = 0; it < 4; it++) {
            int idx = it * 256 + tid, row = idx >> 3, cu = idx & 7;
            *(uint4*)(smem + AT_QH + row * 144 + cu * 16) =
                *(const uint4*)(g_Qh + qoff + (size_t)row * 512 + cu * 8);
            *(uint4*)(smem + AT_QL + row * 144 + cu * 16) =
                *(const uint4*)(g_Ql + qoff + (size_t)row * 512 + cu * 8);
        }
    }
    __syncthreads();
    unsigned aqh[4][4], aql[4][4];
    {
        const uint32_t qa = sb + ((unsigned)(w * 16 + (lane & 15)) * SPD + (lane >> 4) * 8) * 2;
#pragma unroll
        for (int ks = 0; ks < 4; ks++) {
            ldm_x4(aqh[ks], qa + AT_QH + ks * 32);
            ldm_x4(aql[ks], qa + AT_QL + ks * 32);
        }
    }
    __syncthreads();

    const size_t rb0 = (size_t)(b * 1024 + q0 + w * 16 + gid) * 32;
    const size_t rb1 = rb0 + 8 * 32;
    const size_t vbase = (size_t)(bh * 64) * 1024;
    const size_t kbase = (size_t)(b * 1024) * 512 + h * 64;

    float rs0 = 0.0f, rs1 = 0.0f;
    float ctx[8][4];
#pragma unroll
    for (int dt = 0; dt < 8; dt++)
#pragma unroll
        for (int j = 0; j < 4; j++) ctx[dt][j] = 0.0f;

    float* arow0 = att ? att + ((size_t)(bh * 1024 + q0 + w * 16 + gid)) * 1024 : (float*)0;
    float* arow1 = arow0 ? arow0 + (size_t)8 * 1024 : (float*)0;

    // prologue loads for chunk 0
    {
        const uint32_t kb = sb + AT_BUF0;
        const size_t koff = kbase;
#pragma unroll
        for (int it = 0; it < 4; it++) {
            int idx = it * 256 + tid, row = idx >> 3, cu = idx & 7;
            CP16(kb + KH_OFF + row * 144 + cu * 16, g_Kh + koff + (size_t)row * 512 + cu * 8);
            CP16(kb + KL_OFF + row * 144 + cu * 16, g_Kl + koff + (size_t)row * 512 + cu * 8);
        }
#pragma unroll
        for (int it = 0; it < 4; it++) {
            int idx = it * 256 + tid, row = idx >> 4, cu = idx & 15;
            CP16(kb + VH_OFF + row * 272 + cu * 16, g_Vth + vbase + (size_t)row * 1024 + cu * 8);
            CP16(kb + VL_OFF + row * 272 + cu * 16, g_Vtl + vbase + (size_t)row * 1024 + cu * 8);
        }
        CP_COMMIT();
    }

    for (int c = 0; c < 8; c++) {
        const int kc = c * 128;
        if (c < 7) {
            const uint32_t kb = sb + AT_BUF0 + ((c + 1) & 1) * AT_BUFSZ;
            const size_t koff = kbase + (size_t)(kc + 128) * 512;
#pragma unroll
            for (int it = 0; it < 4; it++) {
                int idx = it * 256 + tid, row = idx >> 3, cu = idx & 7;
                CP16(kb + KH_OFF + row * 144 + cu * 16, g_Kh + koff + (size_t)row * 512 + cu * 8);
                CP16(kb + KL_OFF + row * 144 + cu * 16, g_Kl + koff + (size_t)row * 512 + cu * 8);
            }
#pragma unroll
            for (int it = 0; it < 4; it++) {
                int idx = it * 256 + tid, row = idx >> 4, cu = idx & 15;
                CP16(kb + VH_OFF + row * 272 + cu * 16,
                     g_Vth + vbase + (size_t)row * 1024 + kc + 128 + cu * 8);
                CP16(kb + VL_OFF + row * 272 + cu * 16,
                     g_Vtl + vbase + (size_t)row * 1024 + kc + 128 + cu * 8);
            }
            CP_COMMIT();
            CP_WAIT(1);
        } else {
            CP_WAIT(0);
        }
        __syncthreads();

        const uint32_t bb = sb + AT_BUF0 + (c & 1) * AT_BUFSZ;
        unsigned aw0[4], aw1[4], sw0[4], sw1[4];
#pragma unroll
        for (int j = 0; j < 4; j++) {
            aw0[j] = g_am[rb0 + (kc >> 5) + j];
            aw1[j] = g_am[rb1 + (kc >> 5) + j];
            sw0[j] = g_sm[rb0 + (kc >> 5) + j];
            sw1[j] = g_sm[rb1 + (kc >> 5) + j];
        }
#pragma unroll
        for (int nt2 = 0; nt2 < 8; nt2++) {
            float cc[2][4];
#pragma unroll
            for (int hh2 = 0; hh2 < 2; hh2++)
#pragma unroll
                for (int j = 0; j < 4; j++) cc[hh2][j] = 0.0f;
#pragma unroll
            for (int ks = 0; ks < 4; ks++) {
                unsigned kh4[4], kl4[4];
                ldm_x4(kh4, bb + KH_OFF + klane + (nt2 * 16 * SPD + ks * 16) * 2);
                ldm_x4(kl4, bb + KL_OFF + klane + (nt2 * 16 * SPD + ks * 16) * 2);
                MMA(cc[0], aqh[ks], &kh4[0]);
                MMA(cc[0], aqh[ks], &kl4[0]);
                MMA(cc[0], aql[ks], &kh4[0]);
                MMA(cc[1], aqh[ks], &kh4[2]);
                MMA(cc[1], aqh[ks], &kl4[2]);
                MMA(cc[1], aql[ks], &kh4[2]);
            }
            unsigned ph[4], pl[4];
#pragma unroll
            for (int half = 0; half < 2; half++) {
                int nt = nt2 * 2 + half;
                int bidx = nt * 8 + 2 * tig;
                unsigned w0 = aw0[bidx >> 5], w1 = aw1[bidx >> 5];
                unsigned s0 = sw0[bidx >> 5], s1 = sw1[bidx >> 5];
                int bo = bidx & 31;
                float t0 = cc[half][0] * SCL, t1 = cc[half][1] * SCL;
                float t2 = cc[half][2] * SCL, t3 = cc[half][3] * SCL;
                if ((w0 >> bo) & 1u) t0 = -1e30f;
                if ((w0 >> (bo + 1)) & 1u) t1 = -1e30f;
                if ((w1 >> bo) & 1u) t2 = -1e30f;
                if ((w1 >> (bo + 1)) & 1u) t3 = -1e30f;
                float p0 = fexp2(t0), p1 = fexp2(t1);
                float p2 = fexp2(t2), p3 = fexp2(t3);
                rs0 += p0 + p1;
                rs1 += p2 + p3;
                if ((s0 >> bo) & 1u) p0 = 0.0f;
                if ((s0 >> (bo + 1)) & 1u) p1 = 0.0f;
                if ((s1 >> bo) & 1u) p2 = 0.0f;
                if ((s1 >> (bo + 1)) & 1u) p3 = 0.0f;
                if (arow0) {
                    *(float2*)(arow0 + kc + bidx) = make_float2(p0, p1);
                    *(float2*)(arow1 + kc + bidx) = make_float2(p2, p3);
                }
                unsigned hp, lp;
                split2(p0, p1, hp, lp);
                ph[half * 2] = hp; pl[half * 2] = lp;
                split2(p2, p3, hp, lp);
                ph[half * 2 + 1] = hp; pl[half * 2 + 1] = lp;
            }
#pragma unroll
            for (int dt2 = 0; dt2 < 4; dt2++) {
                unsigned bvh[4], bvl[4];
                ldm_x4(bvh, bb + VH_OFF + vlane + (dt2 * 16 * VSPD + nt2 * 16) * 2);
                ldm_x4(bvl, bb + VL_OFF + vlane + (dt2 * 16 * VSPD + nt2 * 16) * 2);
                MMA(ctx[dt2 * 2], ph, &bvh[0]);
                MMA(ctx[dt2 * 2], ph, &bvl[0]);
                MMA(ctx[dt2 * 2], pl, &bvh[0]);
                MMA(ctx[dt2 * 2 + 1], ph, &bvh[2]);
                MMA(ctx[dt2 * 2 + 1], ph, &bvl[2]);
                MMA(ctx[dt2 * 2 + 1], pl, &bvh[2]);
            }
        }
        __syncthreads();
    }

    // ---- row sums -> inv, normalize ctx, store ----
    rs0 += __shfl_xor_sync(0xffffffffu, rs0, 1);
    rs0 += __shfl_xor_sync(0xffffffffu, rs0, 2);
    rs1 += __shfl_xor_sync(0xffffffffu, rs1, 1);
    rs1 += __shfl_xor_sync(0xffffffffu, rs1, 2);
    if (tig == 0) {
        sums[w * 16 + gid] = rs0;
        sums[w * 16 + gid + 8] = rs1;
    }
    __syncthreads();
    const float inv0 = 1.0f / sums[w * 16 + gid];
    const float inv1 = 1.0f / sums[w * 16 + gid + 8];
    if (tid < 128)
        g_inv[(size_t)bh * 1024 + q0 + tid] = 1.0f / sums[tid];

    {
        size_t r0 = (size_t)(b * 1024 + q0 + w * 16 + gid) * 512 + h * 64;
        size_t r1 = r0 + (size_t)8 * 512;
#pragma unroll
        for (int dt = 0; dt < 8; dt++) {
            int cc0 = dt * 8 + 2 * tig;
            unsigned hp, lp;
            split2(ctx[dt][0] * inv0, ctx[dt][1] * inv0, hp, lp);
            *(unsigned*)(g_Ch + r0 + cc0) = hp;
            *(unsigned*)(g_Cl + r0 + cc0) = lp;
            split2(ctx[dt][2] * inv1, ctx[dt][3] * inv1, hp, lp);
            *(unsigned*)(g_Ch + r1 + cc0) = hp;
            *(unsigned*)(g_Cl + r1 + cc0) = lp;
        }
    }
}

// ---------------- att normalization (x inv per row) ----------------
__global__ void __launch_bounds__(256) att_norm_kernel(float4* __restrict__ att)
{
    size_t i = (size_t)blockIdx.x * 256 + threadIdx.x;  // float4 index
    float4 v = att[i];
    float inv = g_inv[i >> 8];  // 256 float4 per 1024-col row
    v.x *= inv; v.y *= inv; v.z *= inv; v.w *= inv;
    att[i] = v;
}

// ---------------- residual + LayerNorm ----------------
__global__ void __launch_bounds__(256) ln_kernel(
    const float* __restrict__ proj, const float* __restrict__ res,
    float* __restrict__ out)
{
    __shared__ float reds[8], redq[8];
    const int row = blockIdx.x, tid = threadIdx.x;
    const float* p = proj + (size_t)row * ND;
    const float* rr = res + (size_t)row * ND;
    float x0 = rr[tid] + p[tid];
    float x1 = rr[tid + 256] + p[tid + 256];
    float s = x0 + x1, q = x0 * x0 + x1 * x1;
#pragma unroll
    for (int o = 16; o > 0; o >>= 1) {
        s += __shfl_xor_sync(0xffffffffu, s, o);
        q += __shfl_xor_sync(0xffffffffu, q, o);
    }
    if ((tid & 31) == 0) { reds[tid >> 5] = s; redq[tid >> 5] = q; }
    __syncthreads();
    float ts = 0, tq = 0;
#pragma unroll
    for (int i = 0; i < 8; i++) { ts += reds[i]; tq += redq[i]; }
    float mean = ts * (1.0f / ND);
    float var = tq * (1.0f / ND) - mean * mean;
    float rsv = rsqrtf(var + 1e-5f);
    out[(size_t)row * ND + tid] = (x0 - mean) * rsv;
    out[(size_t)row * ND + tid + 256] = (x1 - mean) * rsv;
}

// ---------------------------------------------------------------------------
extern "C" void kernel_launch(void* const* d_in, const int* in_sizes, int n_in,
                              void* d_out, int out_size)
{
    const float* query = (const float*)d_in[0];
    const float* key   = (const float*)d_in[1];
    const float* value = (const float*)d_in[2];
    const void*  amask = d_in[3];
    const void*  smask = d_in[4];
    const float* Wq = (const float*)d_in[5];
    const float* Wk = (const float*)d_in[6];
    const float* Wv = (const float*)d_in[7];
    const float* Wo = (const float*)d_in[8];

    float* out = (float*)d_out;
    float* att = ((size_t)out_size >= ACT_ELEMS + ATT_ELEMS) ? out + ACT_ELEMS : (float*)0;

    void *pAh,*pAl,*pWh,*pWl,*pQh,*pQl,*pKh,*pKl,*pVth,*pVtl,*pCh,*pCl,*pPf,*pAm,*pSm;
    cudaGetSymbolAddress(&pAh, g_Ah);   cudaGetSymbolAddress(&pAl, g_Al);
    cudaGetSymbolAddress(&pWh, g_Wh);   cudaGetSymbolAddress(&pWl, g_Wl);
    cudaGetSymbolAddress(&pQh, g_Qh);   cudaGetSymbolAddress(&pQl, g_Ql);
    cudaGetSymbolAddress(&pKh, g_Kh);   cudaGetSymbolAddress(&pKl, g_Kl);
    cudaGetSymbolAddress(&pVth, g_Vth); cudaGetSymbolAddress(&pVtl, g_Vtl);
    cudaGetSymbolAddress(&pCh, g_Ch);   cudaGetSymbolAddress(&pCl, g_Cl);
    cudaGetSymbolAddress(&pPf, g_projf);
    cudaGetSymbolAddress(&pAm, g_am);   cudaGetSymbolAddress(&pSm, g_sm);

    cudaFuncSetAttribute(proj_kernel, cudaFuncAttributeMaxDynamicSharedMemorySize, PJ_SMEM);
    cudaFuncSetAttribute(attn_kernel, cudaFuncAttributeMaxDynamicSharedMemorySize, AT_SMEM);

    detect_mask_kernel<<<1, 256>>>((const unsigned*)amask);
    pack_mask_kernel<<<MASK_WORDS / 256, 256>>>(amask, (unsigned*)pAm);
    pack_mask_kernel<<<MASK_WORDS / 256, 256>>>(smask, (unsigned*)pSm);

    const int nA4 = (int)(ACT_ELEMS / 4), nW4 = (int)(W_ELEMS / 4);
    dim3 pgrid(TOK / 128, ND / 128);

    conv_split_kernel<<<nA4 / 256, 256>>>((const float4*)query,
        (__nv_bfloat16*)pAh, (__nv_bfloat16*)pAl, nA4);
    conv_split_kernel<<<nW4 / 256, 256>>>((const float4*)Wq,
        (__nv_bfloat16*)pWh, (__nv_bfloat16*)pWl, nW4);
    proj_kernel<<<pgrid, 256, PJ_SMEM>>>((const __nv_bfloat16*)pAh, (const __nv_bfloat16*)pAl,
        (const __nv_bfloat16*)pWh, (const __nv_bfloat16*)pWl,
        (float*)0, (__nv_bfloat16*)pQh, (__nv_bfloat16*)pQl, 0);

    conv_split_kernel<<<nA4 / 256, 256>>>((const float4*)key,
        (__nv_bfloat16*)pAh, (__nv_bfloat16*)pAl, nA4);
    conv_split_kernel<<<nW4 / 256, 256>>>((const float4*)Wk,
        (__nv_bfloat16*)pWh, (__nv_bfloat16*)pWl, nW4);
    proj_kernel<<<pgrid, 256, PJ_SMEM>>>((const __nv_bfloat16*)pAh, (const __nv_bfloat16*)pAl,
        (const __nv_bfloat16*)pWh, (const __nv_bfloat16*)pWl,
        (float*)0, (__nv_bfloat16*)pKh, (__nv_bfloat16*)pKl, 0);

    conv_split_kernel<<<nA4 / 256, 256>>>((const float4*)value,
        (__nv_bfloat16*)pAh, (__nv_bfloat16*)pAl, nA4);
    conv_split_kernel<<<nW4 / 256, 256>>>((const float4*)Wv,
        (__nv_bfloat16*)pWh, (__nv_bfloat16*)pWl, nW4);
    proj_kernel<<<pgrid, 256, PJ_SMEM>>>((const __nv_bfloat16*)pAh, (const __nv_bfloat16*)pAl,
        (const __nv_bfloat16*)pWh, (const __nv_bfloat16*)pWl,
        (float*)0, (__nv_bfloat16*)pVth, (__nv_bfloat16*)pVtl, 1);

    attn_kernel<<<dim3(NB * NH, NL / 128), 256, AT_SMEM>>>(att);
    if (att)
        att_norm_kernel<<<(unsigned)(ATT_ELEMS / 4 / 256), 256>>>((float4*)att);

    conv_split_kernel<<<nW4 / 256, 256>>>((const float4*)Wo,
        (__nv_bfloat16*)pWh, (__nv_bfloat16*)pWl, nW4);
    proj_kernel<<<pgrid, 256, PJ_SMEM>>>((const __nv_bfloat16*)pCh, (const __nv_bfloat16*)pCl,
        (const __nv_bfloat16*)pWh, (const __nv_bfloat16*)pWl,
        (float*)pPf, (__nv_bfloat16*)0, (__nv_bfloat16*)0, 2);

    ln_kernel<<<TOK, 256>>>((const float*)pPf, query, out);
}

// round 9
// speedup vs baseline: 2.5090x; 1.0199x over previous
#include <cuda_runtime.h>
#include <cuda_bf16.h>
#include <math.h>
#include <stdint.h>

#define NB 8
#define NL 1024
#define ND 512
#define NH 8
#define NDH 64
#define TOK (NB * NL)
#define ACT_ELEMS ((size_t)TOK * ND)
#define W_ELEMS ((size_t)ND * ND)
#define ATT_ELEMS ((size_t)NB * NH * NL * NL)
#define MASK_WORDS (ATT_ELEMS / 32)

__device__ __nv_bfloat16 g_Ah[ACT_ELEMS], g_Al[ACT_ELEMS];
__device__ __nv_bfloat16 g_Wh[W_ELEMS],  g_Wl[W_ELEMS];
__device__ __nv_bfloat16 g_Qh[ACT_ELEMS], g_Ql[ACT_ELEMS];
__device__ __nv_bfloat16 g_Kh[ACT_ELEMS], g_Kl[ACT_ELEMS];
__device__ __nv_bfloat16 g_Vth[ACT_ELEMS], g_Vtl[ACT_ELEMS]; // [bh*64+d][1024]
__device__ __nv_bfloat16 g_Ch[ACT_ELEMS], g_Cl[ACT_ELEMS];
__device__ float        g_projf[ACT_ELEMS];
__device__ float        g_inv[(size_t)NB * NH * NL];
__device__ unsigned     g_am[MASK_WORDS], g_sm[MASK_WORDS];
__device__ int          g_mask_mode;

// ---------------- helpers ----------------
__device__ __forceinline__ uint32_t smem_u32(const void* p) {
    uint32_t a;
    asm("{ .reg .u64 t; cvta.to.shared.u64 t, %1; cvt.u32.u64 %0, t; }" : "=r"(a) : "l"(p));
    return a;
}
__device__ __forceinline__ void ldm_x4(unsigned r[4], uint32_t a) {
    asm volatile("ldmatrix.sync.aligned.m8n8.x4.shared.b16 {%0,%1,%2,%3}, [%4];"
                 : "=r"(r[0]), "=r"(r[1]), "=r"(r[2]), "=r"(r[3]) : "r"(a) : "memory");
}
#define MMA(c, a, b) \
    asm volatile("mma.sync.aligned.m16n8k16.row.col.f32.bf16.bf16.f32 " \
                 "{%0,%1,%2,%3},{%4,%5,%6,%7},{%8,%9},{%0,%1,%2,%3};" \
                 : "+f"((c)[0]), "+f"((c)[1]), "+f"((c)[2]), "+f"((c)[3]) \
                 : "r"((a)[0]), "r"((a)[1]), "r"((a)[2]), "r"((a)[3]), \
                   "r"((b)[0]), "r"((b)[1]))

#define CP16(dst, src) \
    asm volatile("cp.async.cg.shared.global [%0], [%1], 16;" :: "r"(dst), "l"(src) : "memory")
#define CP_COMMIT() asm volatile("cp.async.commit_group;" ::: "memory")
#define CP_WAIT(n)  asm volatile("cp.async.wait_group %0;" :: "n"(n) : "memory")

__device__ __forceinline__ void split2(float f0, float f1, unsigned& hp, unsigned& lp) {
    __nv_bfloat16 h0 = __float2bfloat16_rn(f0), h1 = __float2bfloat16_rn(f1);
    __nv_bfloat16 l0 = __float2bfloat16_rn(f0 - __bfloat162float(h0));
    __nv_bfloat16 l1 = __float2bfloat16_rn(f1 - __bfloat162float(h1));
    hp = (unsigned)__bfloat16_as_ushort(h0) | ((unsigned)__bfloat16_as_ushort(h1) << 16);
    lp = (unsigned)__bfloat16_as_ushort(l0) | ((unsigned)__bfloat16_as_ushort(l1) << 16);
}

// degree-4 exp2 on fma pipe; rel err ~3e-6 (fine vs 1e-3 tolerance)
__device__ __forceinline__ float fexp2(float x) {
    x = fmaxf(fminf(x, 120.0f), -126.0f);
    float fl = floorf(x);
    float f = x - fl;
    float p = 1.35557472e-2f;
    p = fmaf(p, f, 5.20323690e-2f);
    p = fmaf(p, f, 2.41379774e-1f);
    p = fmaf(p, f, 6.93018210e-1f);
    p = fmaf(p, f, 1.00000370f);
    return __int_as_float(__float_as_int(p) + (((int)fl) << 23));
}

// ---------------- prep kernels ----------------
__global__ void detect_mask_kernel(const unsigned* __restrict__ m) {
    __shared__ int f32flag, u8flag;
    if (threadIdx.x == 0) { f32flag = 0; u8flag = 0; }
    __syncthreads();
    int lf = 0, lu = 0;
    for (int i = threadIdx.x; i < 4096; i += blockDim.x) {
        unsigned w = m[i];
        if (w == 0x3f800000u) lf = 1;
        else if (w > 1u) lu = 1;
    }
    if (lf) atomicOr(&f32flag, 1);
    if (lu) atomicOr(&u8flag, 1);
    __syncthreads();
    if (threadIdx.x == 0) g_mask_mode = f32flag ? 2 : (u8flag ? 0 : 1);
}

__global__ void pack_mask_kernel(const void* __restrict__ m, unsigned* __restrict__ out) {
    int w = blockIdx.x * 256 + threadIdx.x;
    if (w >= (int)MASK_WORDS) return;
    int mode = g_mask_mode;
    unsigned bits = 0;
    if (mode == 0) {
        const unsigned* p = (const unsigned*)m + (size_t)w * 8;
#pragma unroll
        for (int j = 0; j < 8; j++) {
            unsigned v = __vcmpne4(p[j], 0u);
            bits |= ((((v & 0x01010101u) * 0x01020408u) >> 24) & 0xFu) << (j * 4);
        }
    } else if (mode == 1) {
        const int* p = (const int*)m + (size_t)w * 32;
#pragma unroll
        for (int j = 0; j < 32; j++) bits |= (unsigned)(p[j] != 0) << j;
    } else {
        const float* p = (const float*)m + (size_t)w * 32;
#pragma unroll
        for (int j = 0; j < 32; j++) bits |= (unsigned)(p[j] != 0.0f) << j;
    }
    out[w] = bits;
}

__global__ void conv_split_kernel(const float4* __restrict__ x,
                                  __nv_bfloat16* __restrict__ hi,
                                  __nv_bfloat16* __restrict__ lo, int n4) {
    int i = blockIdx.x * 256 + threadIdx.x;
    if (i >= n4) return;
    float4 v = x[i];
    unsigned h0, l0, h1, l1;
    split2(v.x, v.y, h0, l0);
    split2(v.z, v.w, h1, l1);
    ((uint2*)hi)[i] = make_uint2(h0, h1);
    ((uint2*)lo)[i] = make_uint2(l0, l1);
}

// ---------------- projection GEMM (mma.sync, 3-term split bf16) ------------
#define SPD 72
#define PJ_AH 0
#define PJ_AL 18432
#define PJ_BH 36864
#define PJ_BL 55296
#define PJ_SMEM 73728

__global__ void __launch_bounds__(256) proj_kernel(
    const __nv_bfloat16* __restrict__ Ah, const __nv_bfloat16* __restrict__ Al,
    const __nv_bfloat16* __restrict__ Bh, const __nv_bfloat16* __restrict__ Bl,
    float* __restrict__ Cf, __nv_bfloat16* __restrict__ Oh,
    __nv_bfloat16* __restrict__ Ol, int mode)
{
    extern __shared__ char smem[];
    const uint32_t sb = smem_u32(smem);
    const int tid = threadIdx.x, w = tid >> 5, lane = tid & 31;
    const int gid = lane >> 2, tig = lane & 3;
    const int m0 = blockIdx.x * 128, n0 = blockIdx.y * 128;
    const int wm = (w >> 2) * 64, wn = (w & 3) * 32;
    const int rowsel = (lane & 7) + ((lane >> 4) << 3);
    const int colsel = ((lane >> 3) & 1) * 8;

    float c[4][4][4];
#pragma unroll
    for (int mt = 0; mt < 4; mt++)
#pragma unroll
        for (int nt = 0; nt < 4; nt++)
#pragma unroll
            for (int j = 0; j < 4; j++) c[mt][nt][j] = 0.0f;

    const uint32_t aAddr = sb + ((unsigned)(wm + (lane & 15)) * SPD + (lane >> 4) * 8) * 2;
    const uint32_t bAddr4 = sb + ((unsigned)(wn + rowsel) * SPD + colsel) * 2;

    for (int kc = 0; kc < 512; kc += 64) {
#pragma unroll
        for (int it = 0; it < 4; it++) {
            int idx = it * 256 + tid, row = idx >> 3, cu = idx & 7;
            *(uint4*)(smem + PJ_AH + row * 144 + cu * 16) =
                *(const uint4*)(Ah + (size_t)(m0 + row) * 512 + kc + cu * 8);
            *(uint4*)(smem + PJ_AL + row * 144 + cu * 16) =
                *(const uint4*)(Al + (size_t)(m0 + row) * 512 + kc + cu * 8);
            *(uint4*)(smem + PJ_BH + row * 144 + cu * 16) =
                *(const uint4*)(Bh + (size_t)(n0 + row) * 512 + kc + cu * 8);
            *(uint4*)(smem + PJ_BL + row * 144 + cu * 16) =
                *(const uint4*)(Bl + (size_t)(n0 + row) * 512 + kc + cu * 8);
        }
        __syncthreads();
#pragma unroll
        for (int ks = 0; ks < 4; ks++) {
            unsigned ah[4][4], al[4][4], bh4[2][4], bl4[2][4];
#pragma unroll
            for (int mt = 0; mt < 4; mt++) {
                ldm_x4(ah[mt], aAddr + PJ_AH + (mt * 16 * SPD + ks * 16) * 2);
                ldm_x4(al[mt], aAddr + PJ_AL + (mt * 16 * SPD + ks * 16) * 2);
            }
#pragma unroll
            for (int p = 0; p < 2; p++) {
                ldm_x4(bh4[p], bAddr4 + PJ_BH + (p * 16 * SPD + ks * 16) * 2);
                ldm_x4(bl4[p], bAddr4 + PJ_BL + (p * 16 * SPD + ks * 16) * 2);
            }
#pragma unroll
            for (int mt = 0; mt < 4; mt++)
#pragma unroll
                for (int nt = 0; nt < 4; nt++) {
                    unsigned* bh = &bh4[nt >> 1][(nt & 1) * 2];
                    unsigned* bl = &bl4[nt >> 1][(nt & 1) * 2];
                    MMA(c[mt][nt], ah[mt], bh);
                    MMA(c[mt][nt], ah[mt], bl);
                    MMA(c[mt][nt], al[mt], bh);
                }
        }
        __syncthreads();
    }

    if (mode == 1) {
        float* stage = (float*)smem;  // 128 x 129 f32
#pragma unroll
        for (int mt = 0; mt < 4; mt++)
#pragma unroll
            for (int nt = 0; nt < 4; nt++) {
                int r0 = wm + mt * 16 + gid, cc0 = wn + nt * 8 + 2 * tig;
                stage[r0 * 129 + cc0] = c[mt][nt][0];
                stage[r0 * 129 + cc0 + 1] = c[mt][nt][1];
                stage[(r0 + 8) * 129 + cc0] = c[mt][nt][2];
                stage[(r0 + 8) * 129 + cc0 + 1] = c[mt][nt][3];
            }
        __syncthreads();
        const int bb = m0 >> 10, seq0 = m0 & 1023;
        const int m_local = tid & 127, nsel = tid >> 7;
#pragma unroll 8
        for (int rep = 0; rep < 64; rep++) {
            int n_local = rep * 2 + nsel;
            int n = n0 + n_local;
            int hh = n >> 6, dh = n & 63;
            size_t ob = ((size_t)((bb * 8 + hh) * 64 + dh)) * 1024 + seq0 + m_local;
            float f = stage[m_local * 129 + n_local];
            __nv_bfloat16 hbf = __float2bfloat16_rn(f);
            Oh[ob] = hbf;
            Ol[ob] = __float2bfloat16_rn(f - __bfloat162float(hbf));
        }
    } else if (mode == 2) {
#pragma unroll
        for (int mt = 0; mt < 4; mt++)
#pragma unroll
            for (int nt = 0; nt < 4; nt++) {
                int r0 = m0 + wm + mt * 16 + gid, cc0 = n0 + wn + nt * 8 + 2 * tig;
                *(float2*)(Cf + (size_t)r0 * 512 + cc0) =
                    make_float2(c[mt][nt][0], c[mt][nt][1]);
                *(float2*)(Cf + (size_t)(r0 + 8) * 512 + cc0) =
                    make_float2(c[mt][nt][2], c[mt][nt][3]);
            }
    } else {
#pragma unroll
        for (int mt = 0; mt < 4; mt++)
#pragma unroll
            for (int nt = 0; nt < 4; nt++) {
                int r0 = m0 + wm + mt * 16 + gid, cc0 = n0 + wn + nt * 8 + 2 * tig;
                unsigned hp, lp;
                split2(c[mt][nt][0], c[mt][nt][1], hp, lp);
                *(unsigned*)(Oh + (size_t)r0 * 512 + cc0) = hp;
                *(unsigned*)(Ol + (size_t)r0 * 512 + cc0) = lp;
                split2(c[mt][nt][2], c[mt][nt][3], hp, lp);
                *(unsigned*)(Oh + (size_t)(r0 + 8) * 512 + cc0) = hp;
                *(unsigned*)(Ol + (size_t)(r0 + 8) * 512 + cc0) = lp;
            }
    }
}

// ---------------- fused single-pass attention ----------------
#define VSPD 136
#define AT_QH 1024
#define AT_QL 19456
#define AT_BUF0 37888
#define AT_BUFSZ 71680
#define KH_OFF 0
#define KL_OFF 18432
#define VH_OFF 36864
#define VL_OFF 54272
#define AT_SMEM 181248

__global__ void __launch_bounds__(256) attn_kernel(float* __restrict__ att)
{
    extern __shared__ char smem[];
    const uint32_t sb = smem_u32(smem);
    float* sums = (float*)smem;
    const int tid = threadIdx.x, w = tid >> 5, lane = tid & 31;
    const int gid = lane >> 2, tig = lane & 3;
    const int bh = blockIdx.x, b = bh >> 3, h = bh & 7;
    const int q0 = blockIdx.y * 128;
    const float SCL = 0.18033688011112042f; // 0.125 * log2(e)
    const int rowsel = (lane & 7) + ((lane >> 4) << 3);
    const int colsel = ((lane >> 3) & 1) * 8;
    const unsigned klane = ((unsigned)rowsel * SPD + colsel) * 2;
    const unsigned vlane = ((unsigned)rowsel * VSPD + colsel) * 2;

    {
        const size_t qoff = ((size_t)(b * 1024 + q0)) * 512 + h * 64;
#pragma unroll
        for (int it = 0; it < 4; it++) {
            int idx = it * 256 + tid, row = idx >> 3, cu = idx & 7;
            *(uint4*)(smem + AT_QH + row * 144 + cu * 16) =
                *(const uint4*)(g_Qh + qoff + (size_t)row * 512 + cu * 8);
            *(uint4*)(smem + AT_QL + row * 144 + cu * 16) =
                *(const uint4*)(g_Ql + qoff + (size_t)row * 512 + cu * 8);
        }
    }
    __syncthreads();
    unsigned aqh[4][4], aql[4][4];
    {
        const uint32_t qa = sb + ((unsigned)(w * 16 + (lane & 15)) * SPD + (lane >> 4) * 8) * 2;
#pragma unroll
        for (int ks = 0; ks < 4; ks++) {
            ldm_x4(aqh[ks], qa + AT_QH + ks * 32);
            ldm_x4(aql[ks], qa + AT_QL + ks * 32);
        }
    }
    __syncthreads();

    const size_t rb0 = (size_t)(b * 1024 + q0 + w * 16 + gid) * 32;
    const size_t rb1 = rb0 + 8 * 32;
    const size_t vbase = (size_t)(bh * 64) * 1024;
    const size_t kbase = (size_t)(b * 1024) * 512 + h * 64;

    float rs0 = 0.0f, rs1 = 0.0f;
    float ctx[8][4];
#pragma unroll
    for (int dt = 0; dt < 8; dt++)
#pragma unroll
        for (int j = 0; j < 4; j++) ctx[dt][j] = 0.0f;

    float* arow0 = att ? att + ((size_t)(bh * 1024 + q0 + w * 16 + gid)) * 1024 : (float*)0;
    float* arow1 = arow0 ? arow0 + (size_t)8 * 1024 : (float*)0;

    {
        const uint32_t kb = sb + AT_BUF0;
        const size_t koff = kbase;
#pragma unroll
        for (int it = 0; it < 4; it++) {
            int idx = it * 256 + tid, row = idx >> 3, cu = idx & 7;
            CP16(kb + KH_OFF + row * 144 + cu * 16, g_Kh + koff + (size_t)row * 512 + cu * 8);
            CP16(kb + KL_OFF + row * 144 + cu * 16, g_Kl + koff + (size_t)row * 512 + cu * 8);
        }
#pragma unroll
        for (int it = 0; it < 4; it++) {
            int idx = it * 256 + tid, row = idx >> 4, cu = idx & 15;
            CP16(kb + VH_OFF + row * 272 + cu * 16, g_Vth + vbase + (size_t)row * 1024 + cu * 8);
            CP16(kb + VL_OFF + row * 272 + cu * 16, g_Vtl + vbase + (size_t)row * 1024 + cu * 8);
        }
        CP_COMMIT();
    }

    for (int c = 0; c < 8; c++) {
        const int kc = c * 128;
        if (c < 7) {
            const uint32_t kb = sb + AT_BUF0 + ((c + 1) & 1) * AT_BUFSZ;
            const size_t koff = kbase + (size_t)(kc + 128) * 512;
#pragma unroll
            for (int it = 0; it < 4; it++) {
                int idx = it * 256 + tid, row = idx >> 3, cu = idx & 7;
                CP16(kb + KH_OFF + row * 144 + cu * 16, g_Kh + koff + (size_t)row * 512 + cu * 8);
                CP16(kb + KL_OFF + row * 144 + cu * 16, g_Kl + koff + (size_t)row * 512 + cu * 8);
            }
#pragma unroll
            for (int it = 0; it < 4; it++) {
                int idx = it * 256 + tid, row = idx >> 4, cu = idx & 15;
                CP16(kb + VH_OFF + row * 272 + cu * 16,
                     g_Vth + vbase + (size_t)row * 1024 + kc + 128 + cu * 8);
                CP16(kb + VL_OFF + row * 272 + cu * 16,
                     g_Vtl + vbase + (size_t)row * 1024 + kc + 128 + cu * 8);
            }
            CP_COMMIT();
            CP_WAIT(1);
        } else {
            CP_WAIT(0);
        }
        __syncthreads();

        const uint32_t bb = sb + AT_BUF0 + (c & 1) * AT_BUFSZ;
        unsigned aw0[4], aw1[4], sw0[4], sw1[4];
#pragma unroll
        for (int j = 0; j < 4; j++) {
            aw0[j] = g_am[rb0 + (kc >> 5) + j];
            aw1[j] = g_am[rb1 + (kc >> 5) + j];
            sw0[j] = g_sm[rb0 + (kc >> 5) + j];
            sw1[j] = g_sm[rb1 + (kc >> 5) + j];
        }
#pragma unroll
        for (int nt2 = 0; nt2 < 8; nt2++) {
            float cc[2][4];
#pragma unroll
            for (int hh2 = 0; hh2 < 2; hh2++)
#pragma unroll
                for (int j = 0; j < 4; j++) cc[hh2][j] = 0.0f;
#pragma unroll
            for (int ks = 0; ks < 4; ks++) {
                unsigned kh4[4], kl4[4];
                ldm_x4(kh4, bb + KH_OFF + klane + (nt2 * 16 * SPD + ks * 16) * 2);
                ldm_x4(kl4, bb + KL_OFF + klane + (nt2 * 16 * SPD + ks * 16) * 2);
                MMA(cc[0], aqh[ks], &kh4[0]);
                MMA(cc[0], aqh[ks], &kl4[0]);
                MMA(cc[0], aql[ks], &kh4[0]);
                MMA(cc[1], aqh[ks], &kh4[2]);
                MMA(cc[1], aqh[ks], &kl4[2]);
                MMA(cc[1], aql[ks], &kh4[2]);
            }
            unsigned ph[4], pl[4];
#pragma unroll
            for (int half = 0; half < 2; half++) {
                int nt = nt2 * 2 + half;
                int bidx = nt * 8 + 2 * tig;
                unsigned w0 = aw0[bidx >> 5], w1 = aw1[bidx >> 5];
                unsigned s0 = sw0[bidx >> 5], s1 = sw1[bidx >> 5];
                int bo = bidx & 31;
                float t0 = cc[half][0] * SCL, t1 = cc[half][1] * SCL;
                float t2 = cc[half][2] * SCL, t3 = cc[half][3] * SCL;
                if ((w0 >> bo) & 1u) t0 = -1e30f;
                if ((w0 >> (bo + 1)) & 1u) t1 = -1e30f;
                if ((w1 >> bo) & 1u) t2 = -1e30f;
                if ((w1 >> (bo + 1)) & 1u) t3 = -1e30f;
                float p0 = fexp2(t0), p1 = fexp2(t1);
                float p2 = fexp2(t2), p3 = fexp2(t3);
                rs0 += p0 + p1;
                rs1 += p2 + p3;
                if ((s0 >> bo) & 1u) p0 = 0.0f;
                if ((s0 >> (bo + 1)) & 1u) p1 = 0.0f;
                if ((s1 >> bo) & 1u) p2 = 0.0f;
                if ((s1 >> (bo + 1)) & 1u) p3 = 0.0f;
                if (arow0) {
                    *(float2*)(arow0 + kc + bidx) = make_float2(p0, p1);
                    *(float2*)(arow1 + kc + bidx) = make_float2(p2, p3);
                }
                unsigned hp, lp;
                split2(p0, p1, hp, lp);
                ph[half * 2] = hp; pl[half * 2] = lp;
                split2(p2, p3, hp, lp);
                ph[half * 2 + 1] = hp; pl[half * 2 + 1] = lp;
            }
#pragma unroll
            for (int dt2 = 0; dt2 < 4; dt2++) {
                unsigned bvh[4], bvl[4];
                ldm_x4(bvh, bb + VH_OFF + vlane + (dt2 * 16 * VSPD + nt2 * 16) * 2);
                ldm_x4(bvl, bb + VL_OFF + vlane + (dt2 * 16 * VSPD + nt2 * 16) * 2);
                MMA(ctx[dt2 * 2], ph, &bvh[0]);
                MMA(ctx[dt2 * 2], ph, &bvl[0]);
                MMA(ctx[dt2 * 2], pl, &bvh[0]);
                MMA(ctx[dt2 * 2 + 1], ph, &bvh[2]);
                MMA(ctx[dt2 * 2 + 1], ph, &bvl[2]);
                MMA(ctx[dt2 * 2 + 1], pl, &bvh[2]);
            }
        }
        __syncthreads();
    }

    rs0 += __shfl_xor_sync(0xffffffffu, rs0, 1);
    rs0 += __shfl_xor_sync(0xffffffffu, rs0, 2);
    rs1 += __shfl_xor_sync(0xffffffffu, rs1, 1);
    rs1 += __shfl_xor_sync(0xffffffffu, rs1, 2);
    if (tig == 0) {
        sums[w * 16 + gid] = rs0;
        sums[w * 16 + gid + 8] = rs1;
    }
    __syncthreads();
    const float inv0 = 1.0f / sums[w * 16 + gid];
    const float inv1 = 1.0f / sums[w * 16 + gid + 8];
    if (tid < 128)
        g_inv[(size_t)bh * 1024 + q0 + tid] = 1.0f / sums[tid];

    {
        size_t r0 = (size_t)(b * 1024 + q0 + w * 16 + gid) * 512 + h * 64;
        size_t r1 = r0 + (size_t)8 * 512;
#pragma unroll
        for (int dt = 0; dt < 8; dt++) {
            int cc0 = dt * 8 + 2 * tig;
            unsigned hp, lp;
            split2(ctx[dt][0] * inv0, ctx[dt][1] * inv0, hp, lp);
            *(unsigned*)(g_Ch + r0 + cc0) = hp;
            *(unsigned*)(g_Cl + r0 + cc0) = lp;
            split2(ctx[dt][2] * inv1, ctx[dt][3] * inv1, hp, lp);
            *(unsigned*)(g_Ch + r1 + cc0) = hp;
            *(unsigned*)(g_Cl + r1 + cc0) = lp;
        }
    }
}

// ---------------- att normalization (x inv per row) ----------------
__global__ void __launch_bounds__(256) att_norm_kernel(float4* __restrict__ att)
{
    size_t i = (size_t)blockIdx.x * 256 + threadIdx.x;  // float4 index
    float4 v = att[i];
    float inv = g_inv[i >> 8];
    v.x *= inv; v.y *= inv; v.z *= inv; v.w *= inv;
    att[i] = v;
}

// ---------------- residual + LayerNorm ----------------
__global__ void __launch_bounds__(256) ln_kernel(
    const float* __restrict__ proj, const float* __restrict__ res,
    float* __restrict__ out)
{
    __shared__ float reds[8], redq[8];
    const int row = blockIdx.x, tid = threadIdx.x;
    const float* p = proj + (size_t)row * ND;
    const float* rr = res + (size_t)row * ND;
    float x0 = rr[tid] + p[tid];
    float x1 = rr[tid + 256] + p[tid + 256];
    float s = x0 + x1, q = x0 * x0 + x1 * x1;
#pragma unroll
    for (int o = 16; o > 0; o >>= 1) {
        s += __shfl_xor_sync(0xffffffffu, s, o);
        q += __shfl_xor_sync(0xffffffffu, q, o);
    }
    if ((tid & 31) == 0) { reds[tid >> 5] = s; redq[tid >> 5] = q; }
    __syncthreads();
    float ts = 0, tq = 0;
#pragma unroll
    for (int i = 0; i < 8; i++) { ts += reds[i]; tq += redq[i]; }
    float mean = ts * (1.0f / ND);
    float var = tq * (1.0f / ND) - mean * mean;
    float rsv = rsqrtf(var + 1e-5f);
    out[(size_t)row * ND + tid] = (x0 - mean) * rsv;
    out[(size_t)row * ND + tid + 256] = (x1 - mean) * rsv;
}

// ---------------------------------------------------------------------------
extern "C" void kernel_launch(void* const* d_in, const int* in_sizes, int n_in,
                              void* d_out, int out_size)
{
    const float* query = (const float*)d_in[0];
    const float* key   = (const float*)d_in[1];
    const float* value = (const float*)d_in[2];
    const void*  amask = d_in[3];
    const void*  smask = d_in[4];
    const float* Wq = (const float*)d_in[5];
    const float* Wk = (const float*)d_in[6];
    const float* Wv = (const float*)d_in[7];
    const float* Wo = (const float*)d_in[8];

    float* out = (float*)d_out;
    float* att = ((size_t)out_size >= ACT_ELEMS + ATT_ELEMS) ? out + ACT_ELEMS : (float*)0;

    void *pAh,*pAl,*pWh,*pWl,*pQh,*pQl,*pKh,*pKl,*pVth,*pVtl,*pCh,*pCl,*pPf,*pAm,*pSm;
    cudaGetSymbolAddress(&pAh, g_Ah);   cudaGetSymbolAddress(&pAl, g_Al);
    cudaGetSymbolAddress(&pWh, g_Wh);   cudaGetSymbolAddress(&pWl, g_Wl);
    cudaGetSymbolAddress(&pQh, g_Qh);   cudaGetSymbolAddress(&pQl, g_Ql);
    cudaGetSymbolAddress(&pKh, g_Kh);   cudaGetSymbolAddress(&pKl, g_Kl);
    cudaGetSymbolAddress(&pVth, g_Vth); cudaGetSymbolAddress(&pVtl, g_Vtl);
    cudaGetSymbolAddress(&pCh, g_Ch);   cudaGetSymbolAddress(&pCl, g_Cl);
    cudaGetSymbolAddress(&pPf, g_projf);
    cudaGetSymbolAddress(&pAm, g_am);   cudaGetSymbolAddress(&pSm, g_sm);

    cudaFuncSetAttribute(proj_kernel, cudaFuncAttributeMaxDynamicSharedMemorySize, PJ_SMEM);
    cudaFuncSetAttribute(attn_kernel, cudaFuncAttributeMaxDynamicSharedMemorySize, AT_SMEM);

    // side stream + events (created/destroyed per call; host-side only, no
    // device allocation; capture-safe fork/join pattern)
    cudaStream_t s1;
    cudaEvent_t evA, evB, evC, evD;
    cudaStreamCreateWithFlags(&s1, cudaStreamNonBlocking);
    cudaEventCreateWithFlags(&evA, cudaEventDisableTiming);
    cudaEventCreateWithFlags(&evB, cudaEventDisableTiming);
    cudaEventCreateWithFlags(&evC, cudaEventDisableTiming);
    cudaEventCreateWithFlags(&evD, cudaEventDisableTiming);

    detect_mask_kernel<<<1, 256>>>((const unsigned*)amask);
    cudaEventRecord(evA, 0);
    cudaStreamWaitEvent(s1, evA, 0);
    pack_mask_kernel<<<MASK_WORDS / 256, 256, 0, s1>>>(amask, (unsigned*)pAm);
    pack_mask_kernel<<<MASK_WORDS / 256, 256, 0, s1>>>(smask, (unsigned*)pSm);
    cudaEventRecord(evB, s1);

    const int nA4 = (int)(ACT_ELEMS / 4), nW4 = (int)(W_ELEMS / 4);
    dim3 pgrid(TOK / 128, ND / 128);

    conv_split_kernel<<<nA4 / 256, 256>>>((const float4*)query,
        (__nv_bfloat16*)pAh, (__nv_bfloat16*)pAl, nA4);
    conv_split_kernel<<<nW4 / 256, 256>>>((const float4*)Wq,
        (__nv_bfloat16*)pWh, (__nv_bfloat16*)pWl, nW4);
    proj_kernel<<<pgrid, 256, PJ_SMEM>>>((const __nv_bfloat16*)pAh, (const __nv_bfloat16*)pAl,
        (const __nv_bfloat16*)pWh, (const __nv_bfloat16*)pWl,
        (float*)0, (__nv_bfloat16*)pQh, (__nv_bfloat16*)pQl, 0);

    conv_split_kernel<<<nA4 / 256, 256>>>((const float4*)key,
        (__nv_bfloat16*)pAh, (__nv_bfloat16*)pAl, nA4);
    conv_split_kernel<<<nW4 / 256, 256>>>((const float4*)Wk,
        (__nv_bfloat16*)pWh, (__nv_bfloat16*)pWl, nW4);
    proj_kernel<<<pgrid, 256, PJ_SMEM>>>((const __nv_bfloat16*)pAh, (const __nv_bfloat16*)pAl,
        (const __nv_bfloat16*)pWh, (const __nv_bfloat16*)pWl,
        (float*)0, (__nv_bfloat16*)pKh, (__nv_bfloat16*)pKl, 0);

    conv_split_kernel<<<nA4 / 256, 256>>>((const float4*)value,
        (__nv_bfloat16*)pAh, (__nv_bfloat16*)pAl, nA4);
    conv_split_kernel<<<nW4 / 256, 256>>>((const float4*)Wv,
        (__nv_bfloat16*)pWh, (__nv_bfloat16*)pWl, nW4);
    proj_kernel<<<pgrid, 256, PJ_SMEM>>>((const __nv_bfloat16*)pAh, (const __nv_bfloat16*)pAl,
        (const __nv_bfloat16*)pWh, (const __nv_bfloat16*)pWl,
        (float*)0, (__nv_bfloat16*)pVth, (__nv_bfloat16*)pVtl, 1);

    cudaStreamWaitEvent(0, evB, 0);   // masks ready before attn
    attn_kernel<<<dim3(NB * NH, NL / 128), 256, AT_SMEM>>>(att);

    cudaEventRecord(evC, 0);
    if (att) {
        cudaStreamWaitEvent(s1, evC, 0);
        att_norm_kernel<<<(unsigned)(ATT_ELEMS / 4 / 256), 256, 0, s1>>>((float4*)att);
        cudaEventRecord(evD, s1);
    }

    conv_split_kernel<<<nW4 / 256, 256>>>((const float4*)Wo,
        (__nv_bfloat16*)pWh, (__nv_bfloat16*)pWl, nW4);
    proj_kernel<<<pgrid, 256, PJ_SMEM>>>((const __nv_bfloat16*)pCh, (const __nv_bfloat16*)pCl,
        (const __nv_bfloat16*)pWh, (const __nv_bfloat16*)pWl,
        (float*)pPf, (__nv_bfloat16*)0, (__nv_bfloat16*)0, 2);

    ln_kernel<<<TOK, 256>>>((const float*)pPf, query, out);
    if (att) cudaStreamWaitEvent(0, evD, 0);   // join side stream at graph leaf

    cudaEventDestroy(evA); cudaEventDestroy(evB);
    cudaEventDestroy(evC); cudaEventDestroy(evD);
    cudaStreamDestroy(s1);
}

// round 10
// speedup vs baseline: 2.5546x; 1.0182x over previous
#include <cuda_runtime.h>
#include <cuda_bf16.h>
#include <math.h>
#include <stdint.h>

#define NB 8
#define NL 1024
#define ND 512
#define NH 8
#define NDH 64
#define TOK (NB * NL)
#define ACT_ELEMS ((size_t)TOK * ND)
#define W_ELEMS ((size_t)ND * ND)
#define ATT_ELEMS ((size_t)NB * NH * NL * NL)
#define MASK_WORDS (ATT_ELEMS / 32)

// per-path staging buffers (no false deps between Q/K/V pipelines)
__device__ __nv_bfloat16 g_QAh[ACT_ELEMS], g_QAl[ACT_ELEMS];
__device__ __nv_bfloat16 g_KAh[ACT_ELEMS], g_KAl[ACT_ELEMS];
__device__ __nv_bfloat16 g_VAh[ACT_ELEMS], g_VAl[ACT_ELEMS];
__device__ __nv_bfloat16 g_WQh[W_ELEMS], g_WQl[W_ELEMS];
__device__ __nv_bfloat16 g_WKh[W_ELEMS], g_WKl[W_ELEMS];
__device__ __nv_bfloat16 g_WVh[W_ELEMS], g_WVl[W_ELEMS];
__device__ __nv_bfloat16 g_WOh[W_ELEMS], g_WOl[W_ELEMS];
__device__ __nv_bfloat16 g_Qh[ACT_ELEMS], g_Ql[ACT_ELEMS];
__device__ __nv_bfloat16 g_Kh[ACT_ELEMS], g_Kl[ACT_ELEMS];
__device__ __nv_bfloat16 g_Vth[ACT_ELEMS], g_Vtl[ACT_ELEMS]; // [bh*64+d][1024]
__device__ __nv_bfloat16 g_Ch[ACT_ELEMS], g_Cl[ACT_ELEMS];
__device__ float        g_projf[ACT_ELEMS];
__device__ unsigned     g_am[MASK_WORDS], g_sm[MASK_WORDS];
__device__ int          g_mask_mode;

// ---------------- helpers ----------------
__device__ __forceinline__ uint32_t smem_u32(const void* p) {
    uint32_t a;
    asm("{ .reg .u64 t; cvta.to.shared.u64 t, %1; cvt.u32.u64 %0, t; }" : "=r"(a) : "l"(p));
    return a;
}
__device__ __forceinline__ void ldm_x4(unsigned r[4], uint32_t a) {
    asm volatile("ldmatrix.sync.aligned.m8n8.x4.shared.b16 {%0,%1,%2,%3}, [%4];"
                 : "=r"(r[0]), "=r"(r[1]), "=r"(r[2]), "=r"(r[3]) : "r"(a) : "memory");
}
#define MMA(c, a, b) \
    asm volatile("mma.sync.aligned.m16n8k16.row.col.f32.bf16.bf16.f32 " \
                 "{%0,%1,%2,%3},{%4,%5,%6,%7},{%8,%9},{%0,%1,%2,%3};" \
                 : "+f"((c)[0]), "+f"((c)[1]), "+f"((c)[2]), "+f"((c)[3]) \
                 : "r"((a)[0]), "r"((a)[1]), "r"((a)[2]), "r"((a)[3]), \
                   "r"((b)[0]), "r"((b)[1]))

#define CP16(dst, src) \
    asm volatile("cp.async.cg.shared.global [%0], [%1], 16;" :: "r"(dst), "l"(src) : "memory")
#define CP_COMMIT() asm volatile("cp.async.commit_group;" ::: "memory")
#define CP_WAIT(n)  asm volatile("cp.async.wait_group %0;" :: "n"(n) : "memory")

__device__ __forceinline__ void split2(float f0, float f1, unsigned& hp, unsigned& lp) {
    __nv_bfloat16 h0 = __float2bfloat16_rn(f0), h1 = __float2bfloat16_rn(f1);
    __nv_bfloat16 l0 = __float2bfloat16_rn(f0 - __bfloat162float(h0));
    __nv_bfloat16 l1 = __float2bfloat16_rn(f1 - __bfloat162float(h1));
    hp = (unsigned)__bfloat16_as_ushort(h0) | ((unsigned)__bfloat16_as_ushort(h1) << 16);
    lp = (unsigned)__bfloat16_as_ushort(l0) | ((unsigned)__bfloat16_as_ushort(l1) << 16);
}

// degree-4 exp2 on fma pipe; rel err ~3e-6
__device__ __forceinline__ float fexp2(float x) {
    x = fmaxf(fminf(x, 120.0f), -126.0f);
    float fl = floorf(x);
    float f = x - fl;
    float p = 1.35557472e-2f;
    p = fmaf(p, f, 5.20323690e-2f);
    p = fmaf(p, f, 2.41379774e-1f);
    p = fmaf(p, f, 6.93018210e-1f);
    p = fmaf(p, f, 1.00000370f);
    return __int_as_float(__float_as_int(p) + (((int)fl) << 23));
}

// ---------------- prep kernels ----------------
__global__ void detect_mask_kernel(const unsigned* __restrict__ m) {
    __shared__ int f32flag, u8flag;
    if (threadIdx.x == 0) { f32flag = 0; u8flag = 0; }
    __syncthreads();
    int lf = 0, lu = 0;
    for (int i = threadIdx.x; i < 4096; i += blockDim.x) {
        unsigned w = m[i];
        if (w == 0x3f800000u) lf = 1;
        else if (w > 1u) lu = 1;
    }
    if (lf) atomicOr(&f32flag, 1);
    if (lu) atomicOr(&u8flag, 1);
    __syncthreads();
    if (threadIdx.x == 0) g_mask_mode = f32flag ? 2 : (u8flag ? 0 : 1);
}

__global__ void pack_mask_kernel(const void* __restrict__ m, unsigned* __restrict__ out) {
    int w = blockIdx.x * 256 + threadIdx.x;
    if (w >= (int)MASK_WORDS) return;
    int mode = g_mask_mode;
    unsigned bits = 0;
    if (mode == 0) {
        const unsigned* p = (const unsigned*)m + (size_t)w * 8;
#pragma unroll
        for (int j = 0; j < 8; j++) {
            unsigned v = __vcmpne4(p[j], 0u);
            bits |= ((((v & 0x01010101u) * 0x01020408u) >> 24) & 0xFu) << (j * 4);
        }
    } else if (mode == 1) {
        const int* p = (const int*)m + (size_t)w * 32;
#pragma unroll
        for (int j = 0; j < 32; j++) bits |= (unsigned)(p[j] != 0) << j;
    } else {
        const float* p = (const float*)m + (size_t)w * 32;
#pragma unroll
        for (int j = 0; j < 32; j++) bits |= (unsigned)(p[j] != 0.0f) << j;
    }
    out[w] = bits;
}

__global__ void conv_split_kernel(const float4* __restrict__ x,
                                  __nv_bfloat16* __restrict__ hi,
                                  __nv_bfloat16* __restrict__ lo, int n4) {
    int i = blockIdx.x * 256 + threadIdx.x;
    if (i >= n4) return;
    float4 v = x[i];
    unsigned h0, l0, h1, l1;
    split2(v.x, v.y, h0, l0);
    split2(v.z, v.w, h1, l1);
    ((uint2*)hi)[i] = make_uint2(h0, h1);
    ((uint2*)lo)[i] = make_uint2(l0, l1);
}

// ---------------- projection GEMM (mma.sync, 3-term split bf16) ------------
#define SPD 72
#define PJ_AH 0
#define PJ_AL 18432
#define PJ_BH 36864
#define PJ_BL 55296
#define PJ_SMEM 73728

__global__ void __launch_bounds__(256) proj_kernel(
    const __nv_bfloat16* __restrict__ Ah, const __nv_bfloat16* __restrict__ Al,
    const __nv_bfloat16* __restrict__ Bh, const __nv_bfloat16* __restrict__ Bl,
    float* __restrict__ Cf, __nv_bfloat16* __restrict__ Oh,
    __nv_bfloat16* __restrict__ Ol, int mode)
{
    extern __shared__ char smem[];
    const uint32_t sb = smem_u32(smem);
    const int tid = threadIdx.x, w = tid >> 5, lane = tid & 31;
    const int gid = lane >> 2, tig = lane & 3;
    const int m0 = blockIdx.x * 128, n0 = blockIdx.y * 128;
    const int wm = (w >> 2) * 64, wn = (w & 3) * 32;
    const int rowsel = (lane & 7) + ((lane >> 4) << 3);
    const int colsel = ((lane >> 3) & 1) * 8;

    float c[4][4][4];
#pragma unroll
    for (int mt = 0; mt < 4; mt++)
#pragma unroll
        for (int nt = 0; nt < 4; nt++)
#pragma unroll
            for (int j = 0; j < 4; j++) c[mt][nt][j] = 0.0f;

    const uint32_t aAddr = sb + ((unsigned)(wm + (lane & 15)) * SPD + (lane >> 4) * 8) * 2;
    const uint32_t bAddr4 = sb + ((unsigned)(wn + rowsel) * SPD + colsel) * 2;

    for (int kc = 0; kc < 512; kc += 64) {
#pragma unroll
        for (int it = 0; it < 4; it++) {
            int idx = it * 256 + tid, row = idx >> 3, cu = idx & 7;
            *(uint4*)(smem + PJ_AH + row * 144 + cu * 16) =
                *(const uint4*)(Ah + (size_t)(m0 + row) * 512 + kc + cu * 8);
            *(uint4*)(smem + PJ_AL + row * 144 + cu * 16) =
                *(const uint4*)(Al + (size_t)(m0 + row) * 512 + kc + cu * 8);
            *(uint4*)(smem + PJ_BH + row * 144 + cu * 16) =
                *(const uint4*)(Bh + (size_t)(n0 + row) * 512 + kc + cu * 8);
            *(uint4*)(smem + PJ_BL + row * 144 + cu * 16) =
                *(const uint4*)(Bl + (size_t)(n0 + row) * 512 + kc + cu * 8);
        }
        __syncthreads();
#pragma unroll
        for (int ks = 0; ks < 4; ks++) {
            unsigned ah[4][4], al[4][4], bh4[2][4], bl4[2][4];
#pragma unroll
            for (int mt = 0; mt < 4; mt++) {
                ldm_x4(ah[mt], aAddr + PJ_AH + (mt * 16 * SPD + ks * 16) * 2);
                ldm_x4(al[mt], aAddr + PJ_AL + (mt * 16 * SPD + ks * 16) * 2);
            }
#pragma unroll
            for (int p = 0; p < 2; p++) {
                ldm_x4(bh4[p], bAddr4 + PJ_BH + (p * 16 * SPD + ks * 16) * 2);
                ldm_x4(bl4[p], bAddr4 + PJ_BL + (p * 16 * SPD + ks * 16) * 2);
            }
#pragma unroll
            for (int mt = 0; mt < 4; mt++)
#pragma unroll
                for (int nt = 0; nt < 4; nt++) {
                    unsigned* bh = &bh4[nt >> 1][(nt & 1) * 2];
                    unsigned* bl = &bl4[nt >> 1][(nt & 1) * 2];
                    MMA(c[mt][nt], ah[mt], bh);
                    MMA(c[mt][nt], ah[mt], bl);
                    MMA(c[mt][nt], al[mt], bh);
                }
        }
        __syncthreads();
    }

    if (mode == 1) {
        float* stage = (float*)smem;  // 128 x 129 f32
#pragma unroll
        for (int mt = 0; mt < 4; mt++)
#pragma unroll
            for (int nt = 0; nt < 4; nt++) {
                int r0 = wm + mt * 16 + gid, cc0 = wn + nt * 8 + 2 * tig;
                stage[r0 * 129 + cc0] = c[mt][nt][0];
                stage[r0 * 129 + cc0 + 1] = c[mt][nt][1];
                stage[(r0 + 8) * 129 + cc0] = c[mt][nt][2];
                stage[(r0 + 8) * 129 + cc0 + 1] = c[mt][nt][3];
            }
        __syncthreads();
        const int bb = m0 >> 10, seq0 = m0 & 1023;
        const int m_local = tid & 127, nsel = tid >> 7;
#pragma unroll 8
        for (int rep = 0; rep < 64; rep++) {
            int n_local = rep * 2 + nsel;
            int n = n0 + n_local;
            int hh = n >> 6, dh = n & 63;
            size_t ob = ((size_t)((bb * 8 + hh) * 64 + dh)) * 1024 + seq0 + m_local;
            float f = stage[m_local * 129 + n_local];
            __nv_bfloat16 hbf = __float2bfloat16_rn(f);
            Oh[ob] = hbf;
            Ol[ob] = __float2bfloat16_rn(f - __bfloat162float(hbf));
        }
    } else if (mode == 2) {
#pragma unroll
        for (int mt = 0; mt < 4; mt++)
#pragma unroll
            for (int nt = 0; nt < 4; nt++) {
                int r0 = m0 + wm + mt * 16 + gid, cc0 = n0 + wn + nt * 8 + 2 * tig;
                *(float2*)(Cf + (size_t)r0 * 512 + cc0) =
                    make_float2(c[mt][nt][0], c[mt][nt][1]);
                *(float2*)(Cf + (size_t)(r0 + 8) * 512 + cc0) =
                    make_float2(c[mt][nt][2], c[mt][nt][3]);
            }
    } else {
#pragma unroll
        for (int mt = 0; mt < 4; mt++)
#pragma unroll
            for (int nt = 0; nt < 4; nt++) {
                int r0 = m0 + wm + mt * 16 + gid, cc0 = n0 + wn + nt * 8 + 2 * tig;
                unsigned hp, lp;
                split2(c[mt][nt][0], c[mt][nt][1], hp, lp);
                *(unsigned*)(Oh + (size_t)r0 * 512 + cc0) = hp;
                *(unsigned*)(Ol + (size_t)r0 * 512 + cc0) = lp;
                split2(c[mt][nt][2], c[mt][nt][3], hp, lp);
                *(unsigned*)(Oh + (size_t)(r0 + 8) * 512 + cc0) = hp;
                *(unsigned*)(Ol + (size_t)(r0 + 8) * 512 + cc0) = lp;
            }
    }
}

// ---------------- fused single-pass attention (self-normalizing) ----------
#define VSPD 136
#define AT_QH 1024
#define AT_QL 19456
#define AT_BUF0 37888
#define AT_BUFSZ 71680
#define KH_OFF 0
#define KL_OFF 18432
#define VH_OFF 36864
#define VL_OFF 54272
#define AT_SMEM 181248

__global__ void __launch_bounds__(256) attn_kernel(float* __restrict__ att)
{
    extern __shared__ char smem[];
    const uint32_t sb = smem_u32(smem);
    float* sums = (float*)smem;  // 128 floats (then inverted in place)
    const int tid = threadIdx.x, w = tid >> 5, lane = tid & 31;
    const int gid = lane >> 2, tig = lane & 3;
    const int bh = blockIdx.x, b = bh >> 3, h = bh & 7;
    const int q0 = blockIdx.y * 128;
    const float SCL = 0.18033688011112042f; // 0.125 * log2(e)
    const int rowsel = (lane & 7) + ((lane >> 4) << 3);
    const int colsel = ((lane >> 3) & 1) * 8;
    const unsigned klane = ((unsigned)rowsel * SPD + colsel) * 2;
    const unsigned vlane = ((unsigned)rowsel * VSPD + colsel) * 2;

    {
        const size_t qoff = ((size_t)(b * 1024 + q0)) * 512 + h * 64;
#pragma unroll
        for (int it = 0; it < 4; it++) {
            int idx = it * 256 + tid, row = idx >> 3, cu = idx & 7;
            *(uint4*)(smem + AT_QH + row * 144 + cu * 16) =
                *(const uint4*)(g_Qh + qoff + (size_t)row * 512 + cu * 8);
            *(uint4*)(smem + AT_QL + row * 144 + cu * 16) =
                *(const uint4*)(g_Ql + qoff + (size_t)row * 512 + cu * 8);
        }
    }
    __syncthreads();
    unsigned aqh[4][4], aql[4][4];
    {
        const uint32_t qa = sb + ((unsigned)(w * 16 + (lane & 15)) * SPD + (lane >> 4) * 8) * 2;
#pragma unroll
        for (int ks = 0; ks < 4; ks++) {
            ldm_x4(aqh[ks], qa + AT_QH + ks * 32);
            ldm_x4(aql[ks], qa + AT_QL + ks * 32);
        }
    }
    __syncthreads();

    const size_t rb0 = (size_t)(b * 1024 + q0 + w * 16 + gid) * 32;
    const size_t rb1 = rb0 + 8 * 32;
    const size_t vbase = (size_t)(bh * 64) * 1024;
    const size_t kbase = (size_t)(b * 1024) * 512 + h * 64;

    float rs0 = 0.0f, rs1 = 0.0f;
    float ctx[8][4];
#pragma unroll
    for (int dt = 0; dt < 8; dt++)
#pragma unroll
        for (int j = 0; j < 4; j++) ctx[dt][j] = 0.0f;

    float* arow0 = att ? att + ((size_t)(bh * 1024 + q0 + w * 16 + gid)) * 1024 : (float*)0;
    float* arow1 = arow0 ? arow0 + (size_t)8 * 1024 : (float*)0;

    {
        const uint32_t kb = sb + AT_BUF0;
        const size_t koff = kbase;
#pragma unroll
        for (int it = 0; it < 4; it++) {
            int idx = it * 256 + tid, row = idx >> 3, cu = idx & 7;
            CP16(kb + KH_OFF + row * 144 + cu * 16, g_Kh + koff + (size_t)row * 512 + cu * 8);
            CP16(kb + KL_OFF + row * 144 + cu * 16, g_Kl + koff + (size_t)row * 512 + cu * 8);
        }
#pragma unroll
        for (int it = 0; it < 4; it++) {
            int idx = it * 256 + tid, row = idx >> 4, cu = idx & 15;
            CP16(kb + VH_OFF + row * 272 + cu * 16, g_Vth + vbase + (size_t)row * 1024 + cu * 8);
            CP16(kb + VL_OFF + row * 272 + cu * 16, g_Vtl + vbase + (size_t)row * 1024 + cu * 8);
        }
        CP_COMMIT();
    }

    for (int c = 0; c < 8; c++) {
        const int kc = c * 128;
        if (c < 7) {
            const uint32_t kb = sb + AT_BUF0 + ((c + 1) & 1) * AT_BUFSZ;
            const size_t koff = kbase + (size_t)(kc + 128) * 512;
#pragma unroll
            for (int it = 0; it < 4; it++) {
                int idx = it * 256 + tid, row = idx >> 3, cu = idx & 7;
                CP16(kb + KH_OFF + row * 144 + cu * 16, g_Kh + koff + (size_t)row * 512 + cu * 8);
                CP16(kb + KL_OFF + row * 144 + cu * 16, g_Kl + koff + (size_t)row * 512 + cu * 8);
            }
#pragma unroll
            for (int it = 0; it < 4; it++) {
                int idx = it * 256 + tid, row = idx >> 4, cu = idx & 15;
                CP16(kb + VH_OFF + row * 272 + cu * 16,
                     g_Vth + vbase + (size_t)row * 1024 + kc + 128 + cu * 8);
                CP16(kb + VL_OFF + row * 272 + cu * 16,
                     g_Vtl + vbase + (size_t)row * 1024 + kc + 128 + cu * 8);
            }
            CP_COMMIT();
            CP_WAIT(1);
        } else {
            CP_WAIT(0);
        }
        __syncthreads();

        const uint32_t bb = sb + AT_BUF0 + (c & 1) * AT_BUFSZ;
        unsigned aw0[4], aw1[4], sw0[4], sw1[4];
#pragma unroll
        for (int j = 0; j < 4; j++) {
            aw0[j] = g_am[rb0 + (kc >> 5) + j];
            aw1[j] = g_am[rb1 + (kc >> 5) + j];
            sw0[j] = g_sm[rb0 + (kc >> 5) + j];
            sw1[j] = g_sm[rb1 + (kc >> 5) + j];
        }
#pragma unroll
        for (int nt2 = 0; nt2 < 8; nt2++) {
            float cc[2][4];
#pragma unroll
            for (int hh2 = 0; hh2 < 2; hh2++)
#pragma unroll
                for (int j = 0; j < 4; j++) cc[hh2][j] = 0.0f;
#pragma unroll
            for (int ks = 0; ks < 4; ks++) {
                unsigned kh4[4], kl4[4];
                ldm_x4(kh4, bb + KH_OFF + klane + (nt2 * 16 * SPD + ks * 16) * 2);
                ldm_x4(kl4, bb + KL_OFF + klane + (nt2 * 16 * SPD + ks * 16) * 2);
                MMA(cc[0], aqh[ks], &kh4[0]);
                MMA(cc[0], aqh[ks], &kl4[0]);
                MMA(cc[0], aql[ks], &kh4[0]);
                MMA(cc[1], aqh[ks], &kh4[2]);
                MMA(cc[1], aqh[ks], &kl4[2]);
                MMA(cc[1], aql[ks], &kh4[2]);
            }
            unsigned ph[4], pl[4];
#pragma unroll
            for (int half = 0; half < 2; half++) {
                int nt = nt2 * 2 + half;
                int bidx = nt * 8 + 2 * tig;
                unsigned w0 = aw0[bidx >> 5], w1 = aw1[bidx >> 5];
                unsigned s0 = sw0[bidx >> 5], s1 = sw1[bidx >> 5];
                int bo = bidx & 31;
                float t0 = cc[half][0] * SCL, t1 = cc[half][1] * SCL;
                float t2 = cc[half][2] * SCL, t3 = cc[half][3] * SCL;
                if ((w0 >> bo) & 1u) t0 = -1e30f;
                if ((w0 >> (bo + 1)) & 1u) t1 = -1e30f;
                if ((w1 >> bo) & 1u) t2 = -1e30f;
                if ((w1 >> (bo + 1)) & 1u) t3 = -1e30f;
                float p0 = fexp2(t0), p1 = fexp2(t1);
                float p2 = fexp2(t2), p3 = fexp2(t3);
                rs0 += p0 + p1;
                rs1 += p2 + p3;
                if ((s0 >> bo) & 1u) p0 = 0.0f;
                if ((s0 >> (bo + 1)) & 1u) p1 = 0.0f;
                if ((s1 >> bo) & 1u) p2 = 0.0f;
                if ((s1 >> (bo + 1)) & 1u) p3 = 0.0f;
                if (arow0) {
                    *(float2*)(arow0 + kc + bidx) = make_float2(p0, p1);
                    *(float2*)(arow1 + kc + bidx) = make_float2(p2, p3);
                }
                unsigned hp, lp;
                split2(p0, p1, hp, lp);
                ph[half * 2] = hp; pl[half * 2] = lp;
                split2(p2, p3, hp, lp);
                ph[half * 2 + 1] = hp; pl[half * 2 + 1] = lp;
            }
#pragma unroll
            for (int dt2 = 0; dt2 < 4; dt2++) {
                unsigned bvh[4], bvl[4];
                ldm_x4(bvh, bb + VH_OFF + vlane + (dt2 * 16 * VSPD + nt2 * 16) * 2);
                ldm_x4(bvl, bb + VL_OFF + vlane + (dt2 * 16 * VSPD + nt2 * 16) * 2);
                MMA(ctx[dt2 * 2], ph, &bvh[0]);
                MMA(ctx[dt2 * 2], ph, &bvl[0]);
                MMA(ctx[dt2 * 2], pl, &bvh[0]);
                MMA(ctx[dt2 * 2 + 1], ph, &bvh[2]);
                MMA(ctx[dt2 * 2 + 1], ph, &bvl[2]);
                MMA(ctx[dt2 * 2 + 1], pl, &bvh[2]);
            }
        }
        __syncthreads();
    }

    rs0 += __shfl_xor_sync(0xffffffffu, rs0, 1);
    rs0 += __shfl_xor_sync(0xffffffffu, rs0, 2);
    rs1 += __shfl_xor_sync(0xffffffffu, rs1, 1);
    rs1 += __shfl_xor_sync(0xffffffffu, rs1, 2);
    if (tig == 0) {
        sums[w * 16 + gid] = rs0;
        sums[w * 16 + gid + 8] = rs1;
    }
    __syncthreads();
    if (tid < 128) sums[tid] = 1.0f / sums[tid];  // invert in place
    __syncthreads();
    const float inv0 = sums[w * 16 + gid];
    const float inv1 = sums[w * 16 + gid + 8];

    // ctx epilogue (normalized)
    {
        size_t r0 = (size_t)(b * 1024 + q0 + w * 16 + gid) * 512 + h * 64;
        size_t r1 = r0 + (size_t)8 * 512;
#pragma unroll
        for (int dt = 0; dt < 8; dt++) {
            int cc0 = dt * 8 + 2 * tig;
            unsigned hp, lp;
            split2(ctx[dt][0] * inv0, ctx[dt][1] * inv0, hp, lp);
            *(unsigned*)(g_Ch + r0 + cc0) = hp;
            *(unsigned*)(g_Cl + r0 + cc0) = lp;
            split2(ctx[dt][2] * inv1, ctx[dt][3] * inv1, hp, lp);
            *(unsigned*)(g_Ch + r1 + cc0) = hp;
            *(unsigned*)(g_Cl + r1 + cc0) = lp;
        }
    }

    // self-normalize this CTA's att rows (512 KB, L2-resident)
    if (att) {
        float4* ab = (float4*)(att + ((size_t)(bh * 1024 + q0)) * 1024);
#pragma unroll 4
        for (int i = tid; i < 128 * 256; i += 256) {
            float s = sums[i >> 8];
            float4 v = ab[i];
            v.x *= s; v.y *= s; v.z *= s; v.w *= s;
            ab[i] = v;
        }
    }
}

// ---------------- residual + LayerNorm ----------------
__global__ void __launch_bounds__(256) ln_kernel(
    const float* __restrict__ proj, const float* __restrict__ res,
    float* __restrict__ out)
{
    __shared__ float reds[8], redq[8];
    const int row = blockIdx.x, tid = threadIdx.x;
    const float* p = proj + (size_t)row * ND;
    const float* rr = res + (size_t)row * ND;
    float x0 = rr[tid] + p[tid];
    float x1 = rr[tid + 256] + p[tid + 256];
    float s = x0 + x1, q = x0 * x0 + x1 * x1;
#pragma unroll
    for (int o = 16; o > 0; o >>= 1) {
        s += __shfl_xor_sync(0xffffffffu, s, o);
        q += __shfl_xor_sync(0xffffffffu, q, o);
    }
    if ((tid & 31) == 0) { reds[tid >> 5] = s; redq[tid >> 5] = q; }
    __syncthreads();
    float ts = 0, tq = 0;
#pragma unroll
    for (int i = 0; i < 8; i++) { ts += reds[i]; tq += redq[i]; }
    float mean = ts * (1.0f / ND);
    float var = tq * (1.0f / ND) - mean * mean;
    float rsv = rsqrtf(var + 1e-5f);
    out[(size_t)row * ND + tid] = (x0 - mean) * rsv;
    out[(size_t)row * ND + tid + 256] = (x1 - mean) * rsv;
}

// ---------------------------------------------------------------------------
extern "C" void kernel_launch(void* const* d_in, const int* in_sizes, int n_in,
                              void* d_out, int out_size)
{
    const float* query = (const float*)d_in[0];
    const float* key   = (const float*)d_in[1];
    const float* value = (const float*)d_in[2];
    const void*  amask = d_in[3];
    const void*  smask = d_in[4];
    const float* Wq = (const float*)d_in[5];
    const float* Wk = (const float*)d_in[6];
    const float* Wv = (const float*)d_in[7];
    const float* Wo = (const float*)d_in[8];

    float* out = (float*)d_out;
    float* att = ((size_t)out_size >= ACT_ELEMS + ATT_ELEMS) ? out + ACT_ELEMS : (float*)0;

    void *pQAh,*pQAl,*pKAh,*pKAl,*pVAh,*pVAl;
    void *pWQh,*pWQl,*pWKh,*pWKl,*pWVh,*pWVl,*pWOh,*pWOl;
    void *pQh,*pQl,*pKh,*pKl,*pVth,*pVtl,*pCh,*pCl,*pPf,*pAm,*pSm;
    cudaGetSymbolAddress(&pQAh, g_QAh); cudaGetSymbolAddress(&pQAl, g_QAl);
    cudaGetSymbolAddress(&pKAh, g_KAh); cudaGetSymbolAddress(&pKAl, g_KAl);
    cudaGetSymbolAddress(&pVAh, g_VAh); cudaGetSymbolAddress(&pVAl, g_VAl);
    cudaGetSymbolAddress(&pWQh, g_WQh); cudaGetSymbolAddress(&pWQl, g_WQl);
    cudaGetSymbolAddress(&pWKh, g_WKh); cudaGetSymbolAddress(&pWKl, g_WKl);
    cudaGetSymbolAddress(&pWVh, g_WVh); cudaGetSymbolAddress(&pWVl, g_WVl);
    cudaGetSymbolAddress(&pWOh, g_WOh); cudaGetSymbolAddress(&pWOl, g_WOl);
    cudaGetSymbolAddress(&pQh, g_Qh);   cudaGetSymbolAddress(&pQl, g_Ql);
    cudaGetSymbolAddress(&pKh, g_Kh);   cudaGetSymbolAddress(&pKl, g_Kl);
    cudaGetSymbolAddress(&pVth, g_Vth); cudaGetSymbolAddress(&pVtl, g_Vtl);
    cudaGetSymbolAddress(&pCh, g_Ch);   cudaGetSymbolAddress(&pCl, g_Cl);
    cudaGetSymbolAddress(&pPf, g_projf);
    cudaGetSymbolAddress(&pAm, g_am);   cudaGetSymbolAddress(&pSm, g_sm);

    cudaFuncSetAttribute(proj_kernel, cudaFuncAttributeMaxDynamicSharedMemorySize, PJ_SMEM);
    cudaFuncSetAttribute(attn_kernel, cudaFuncAttributeMaxDynamicSharedMemorySize, AT_SMEM);

    cudaStream_t s1, s2, s3;
    cudaEvent_t evA, evB, evK, evV;
    cudaStreamCreateWithFlags(&s1, cudaStreamNonBlocking);
    cudaStreamCreateWithFlags(&s2, cudaStreamNonBlocking);
    cudaStreamCreateWithFlags(&s3, cudaStreamNonBlocking);
    cudaEventCreateWithFlags(&evA, cudaEventDisableTiming);
    cudaEventCreateWithFlags(&evB, cudaEventDisableTiming);
    cudaEventCreateWithFlags(&evK, cudaEventDisableTiming);
    cudaEventCreateWithFlags(&evV, cudaEventDisableTiming);

    const int nA4 = (int)(ACT_ELEMS / 4), nW4 = (int)(W_ELEMS / 4);
    dim3 pgrid(TOK / 128, ND / 128);

    detect_mask_kernel<<<1, 256>>>((const unsigned*)amask);
    cudaEventRecord(evA, 0);

    // s1: masks + Wo conversion
    cudaStreamWaitEvent(s1, evA, 0);
    pack_mask_kernel<<<MASK_WORDS / 256, 256, 0, s1>>>(amask, (unsigned*)pAm);
    pack_mask_kernel<<<MASK_WORDS / 256, 256, 0, s1>>>(smask, (unsigned*)pSm);
    conv_split_kernel<<<nW4 / 256, 256, 0, s1>>>((const float4*)Wo,
        (__nv_bfloat16*)pWOh, (__nv_bfloat16*)pWOl, nW4);
    cudaEventRecord(evB, s1);

    // s2: K pipeline
    cudaStreamWaitEvent(s2, evA, 0);
    conv_split_kernel<<<nA4 / 256, 256, 0, s2>>>((const float4*)key,
        (__nv_bfloat16*)pKAh, (__nv_bfloat16*)pKAl, nA4);
    conv_split_kernel<<<nW4 / 256, 256, 0, s2>>>((const float4*)Wk,
        (__nv_bfloat16*)pWKh, (__nv_bfloat16*)pWKl, nW4);
    proj_kernel<<<pgrid, 256, PJ_SMEM, s2>>>((const __nv_bfloat16*)pKAh, (const __nv_bfloat16*)pKAl,
        (const __nv_bfloat16*)pWKh, (const __nv_bfloat16*)pWKl,
        (float*)0, (__nv_bfloat16*)pKh, (__nv_bfloat16*)pKl, 0);
    cudaEventRecord(evK, s2);

    // s3: V pipeline
    cudaStreamWaitEvent(s3, evA, 0);
    conv_split_kernel<<<nA4 / 256, 256, 0, s3>>>((const float4*)value,
        (__nv_bfloat16*)pVAh, (__nv_bfloat16*)pVAl, nA4);
    conv_split_kernel<<<nW4 / 256, 256, 0, s3>>>((const float4*)Wv,
        (__nv_bfloat16*)pWVh, (__nv_bfloat16*)pWVl, nW4);
    proj_kernel<<<pgrid, 256, PJ_SMEM, s3>>>((const __nv_bfloat16*)pVAh, (const __nv_bfloat16*)pVAl,
        (const __nv_bfloat16*)pWVh, (const __nv_bfloat16*)pWVl,
        (float*)0, (__nv_bfloat16*)pVth, (__nv_bfloat16*)pVtl, 1);
    cudaEventRecord(evV, s3);

    // main: Q pipeline
    conv_split_kernel<<<nA4 / 256, 256>>>((const float4*)query,
        (__nv_bfloat16*)pQAh, (__nv_bfloat16*)pQAl, nA4);
    conv_split_kernel<<<nW4 / 256, 256>>>((const float4*)Wq,
        (__nv_bfloat16*)pWQh, (__nv_bfloat16*)pWQl, nW4);
    proj_kernel<<<pgrid, 256, PJ_SMEM>>>((const __nv_bfloat16*)pQAh, (const __nv_bfloat16*)pQAl,
        (const __nv_bfloat16*)pWQh, (const __nv_bfloat16*)pWQl,
        (float*)0, (__nv_bfloat16*)pQh, (__nv_bfloat16*)pQl, 0);

    cudaStreamWaitEvent(0, evB, 0);
    cudaStreamWaitEvent(0, evK, 0);
    cudaStreamWaitEvent(0, evV, 0);
    attn_kernel<<<dim3(NB * NH, NL / 128), 256, AT_SMEM>>>(att);

    proj_kernel<<<pgrid, 256, PJ_SMEM>>>((const __nv_bfloat16*)pCh, (const __nv_bfloat16*)pCl,
        (const __nv_bfloat16*)pWOh, (const __nv_bfloat16*)pWOl,
        (float*)pPf, (__nv_bfloat16*)0, (__nv_bfloat16*)0, 2);
    ln_kernel<<<TOK, 256>>>((const float*)pPf, query, out);

    cudaEventDestroy(evA); cudaEventDestroy(evB);
    cudaEventDestroy(evK); cudaEventDestroy(evV);
    cudaStreamDestroy(s1); cudaStreamDestroy(s2); cudaStreamDestroy(s3);
}

// round 11
// speedup vs baseline: 2.6984x; 1.0563x over previous
#include <cuda_runtime.h>
#include <cuda_bf16.h>
#include <math.h>
#include <stdint.h>

#define NB 8
#define NL 1024
#define ND 512
#define NH 8
#define NDH 64
#define TOK (NB * NL)
#define ACT_ELEMS ((size_t)TOK * ND)
#define W_ELEMS ((size_t)ND * ND)
#define ATT_ELEMS ((size_t)NB * NH * NL * NL)
#define MASK_WORDS (ATT_ELEMS / 32)

// per-path staging buffers (no false deps between Q/K/V pipelines)
__device__ __nv_bfloat16 g_QAh[ACT_ELEMS], g_QAl[ACT_ELEMS];
__device__ __nv_bfloat16 g_KAh[ACT_ELEMS], g_KAl[ACT_ELEMS];
__device__ __nv_bfloat16 g_VAh[ACT_ELEMS], g_VAl[ACT_ELEMS];
__device__ __nv_bfloat16 g_WQh[W_ELEMS], g_WQl[W_ELEMS];
__device__ __nv_bfloat16 g_WKh[W_ELEMS], g_WKl[W_ELEMS];
__device__ __nv_bfloat16 g_WVh[W_ELEMS], g_WVl[W_ELEMS];
__device__ __nv_bfloat16 g_WOh[W_ELEMS], g_WOl[W_ELEMS];
__device__ __nv_bfloat16 g_Qh[ACT_ELEMS], g_Ql[ACT_ELEMS];
__device__ __nv_bfloat16 g_Kh[ACT_ELEMS], g_Kl[ACT_ELEMS];
__device__ __nv_bfloat16 g_Vth[ACT_ELEMS], g_Vtl[ACT_ELEMS]; // [bh*64+d][1024]
__device__ __nv_bfloat16 g_Ch[ACT_ELEMS], g_Cl[ACT_ELEMS];
__device__ float        g_projf[ACT_ELEMS];
__device__ unsigned     g_am[MASK_WORDS], g_sm[MASK_WORDS];
__device__ int          g_mask_mode;

// ---------------- helpers ----------------
__device__ __forceinline__ uint32_t smem_u32(const void* p) {
    uint32_t a;
    asm("{ .reg .u64 t; cvta.to.shared.u64 t, %1; cvt.u32.u64 %0, t; }" : "=r"(a) : "l"(p));
    return a;
}
__device__ __forceinline__ void ldm_x4(unsigned r[4], uint32_t a) {
    asm volatile("ldmatrix.sync.aligned.m8n8.x4.shared.b16 {%0,%1,%2,%3}, [%4];"
                 : "=r"(r[0]), "=r"(r[1]), "=r"(r[2]), "=r"(r[3]) : "r"(a) : "memory");
}
#define MMA(c, a, b) \
    asm volatile("mma.sync.aligned.m16n8k16.row.col.f32.bf16.bf16.f32 " \
                 "{%0,%1,%2,%3},{%4,%5,%6,%7},{%8,%9},{%0,%1,%2,%3};" \
                 : "+f"((c)[0]), "+f"((c)[1]), "+f"((c)[2]), "+f"((c)[3]) \
                 : "r"((a)[0]), "r"((a)[1]), "r"((a)[2]), "r"((a)[3]), \
                   "r"((b)[0]), "r"((b)[1]))

#define CP16(dst, src) \
    asm volatile("cp.async.cg.shared.global [%0], [%1], 16;" :: "r"(dst), "l"(src) : "memory")
#define CP_COMMIT() asm volatile("cp.async.commit_group;" ::: "memory")
#define CP_WAIT(n)  asm volatile("cp.async.wait_group %0;" :: "n"(n) : "memory")

__device__ __forceinline__ void split2(float f0, float f1, unsigned& hp, unsigned& lp) {
    __nv_bfloat16 h0 = __float2bfloat16_rn(f0), h1 = __float2bfloat16_rn(f1);
    __nv_bfloat16 l0 = __float2bfloat16_rn(f0 - __bfloat162float(h0));
    __nv_bfloat16 l1 = __float2bfloat16_rn(f1 - __bfloat162float(h1));
    hp = (unsigned)__bfloat16_as_ushort(h0) | ((unsigned)__bfloat16_as_ushort(h1) << 16);
    lp = (unsigned)__bfloat16_as_ushort(l0) | ((unsigned)__bfloat16_as_ushort(l1) << 16);
}

// degree-4 exp2 on fma pipe; rel err ~3e-6
__device__ __forceinline__ float fexp2(float x) {
    x = fmaxf(fminf(x, 120.0f), -126.0f);
    float fl = floorf(x);
    float f = x - fl;
    float p = 1.35557472e-2f;
    p = fmaf(p, f, 5.20323690e-2f);
    p = fmaf(p, f, 2.41379774e-1f);
    p = fmaf(p, f, 6.93018210e-1f);
    p = fmaf(p, f, 1.00000370f);
    return __int_as_float(__float_as_int(p) + (((int)fl) << 23));
}

// ---------------- prep kernels ----------------
__global__ void detect_mask_kernel(const unsigned* __restrict__ m) {
    __shared__ int f32flag, u8flag;
    if (threadIdx.x == 0) { f32flag = 0; u8flag = 0; }
    __syncthreads();
    int lf = 0, lu = 0;
    for (int i = threadIdx.x; i < 4096; i += blockDim.x) {
        unsigned w = m[i];
        if (w == 0x3f800000u) lf = 1;
        else if (w > 1u) lu = 1;
    }
    if (lf) atomicOr(&f32flag, 1);
    if (lu) atomicOr(&u8flag, 1);
    __syncthreads();
    if (threadIdx.x == 0) g_mask_mode = f32flag ? 2 : (u8flag ? 0 : 1);
}

__global__ void pack_mask_kernel(const void* __restrict__ m, unsigned* __restrict__ out) {
    int w = blockIdx.x * 256 + threadIdx.x;
    if (w >= (int)MASK_WORDS) return;
    int mode = g_mask_mode;
    unsigned bits = 0;
    if (mode == 0) {
        const unsigned* p = (const unsigned*)m + (size_t)w * 8;
#pragma unroll
        for (int j = 0; j < 8; j++) {
            unsigned v = __vcmpne4(p[j], 0u);
            bits |= ((((v & 0x01010101u) * 0x01020408u) >> 24) & 0xFu) << (j * 4);
        }
    } else if (mode == 1) {
        const int* p = (const int*)m + (size_t)w * 32;
#pragma unroll
        for (int j = 0; j < 32; j++) bits |= (unsigned)(p[j] != 0) << j;
    } else {
        const float* p = (const float*)m + (size_t)w * 32;
#pragma unroll
        for (int j = 0; j < 32; j++) bits |= (unsigned)(p[j] != 0.0f) << j;
    }
    out[w] = bits;
}

__global__ void conv_split_kernel(const float4* __restrict__ x,
                                  __nv_bfloat16* __restrict__ hi,
                                  __nv_bfloat16* __restrict__ lo, int n4) {
    int i = blockIdx.x * 256 + threadIdx.x;
    if (i >= n4) return;
    float4 v = x[i];
    unsigned h0, l0, h1, l1;
    split2(v.x, v.y, h0, l0);
    split2(v.z, v.w, h1, l1);
    ((uint2*)hi)[i] = make_uint2(h0, h1);
    ((uint2*)lo)[i] = make_uint2(l0, l1);
}

// ---------------- projection GEMM (mma.sync, 3-term split bf16) ------------
#define SPD 72
#define PJ_AH 0
#define PJ_AL 18432
#define PJ_BH 36864
#define PJ_BL 55296
#define PJ_SMEM 73728

__global__ void __launch_bounds__(256) proj_kernel(
    const __nv_bfloat16* __restrict__ Ah, const __nv_bfloat16* __restrict__ Al,
    const __nv_bfloat16* __restrict__ Bh, const __nv_bfloat16* __restrict__ Bl,
    float* __restrict__ Cf, __nv_bfloat16* __restrict__ Oh,
    __nv_bfloat16* __restrict__ Ol, int mode)
{
    extern __shared__ char smem[];
    const uint32_t sb = smem_u32(smem);
    const int tid = threadIdx.x, w = tid >> 5, lane = tid & 31;
    const int gid = lane >> 2, tig = lane & 3;
    const int m0 = blockIdx.x * 128, n0 = blockIdx.y * 128;
    const int wm = (w >> 2) * 64, wn = (w & 3) * 32;
    const int rowsel = (lane & 7) + ((lane >> 4) << 3);
    const int colsel = ((lane >> 3) & 1) * 8;

    float c[4][4][4];
#pragma unroll
    for (int mt = 0; mt < 4; mt++)
#pragma unroll
        for (int nt = 0; nt < 4; nt++)
#pragma unroll
            for (int j = 0; j < 4; j++) c[mt][nt][j] = 0.0f;

    const uint32_t aAddr = sb + ((unsigned)(wm + (lane & 15)) * SPD + (lane >> 4) * 8) * 2;
    const uint32_t bAddr4 = sb + ((unsigned)(wn + rowsel) * SPD + colsel) * 2;

    for (int kc = 0; kc < 512; kc += 64) {
#pragma unroll
        for (int it = 0; it < 4; it++) {
            int idx = it * 256 + tid, row = idx >> 3, cu = idx & 7;
            *(uint4*)(smem + PJ_AH + row * 144 + cu * 16) =
                *(const uint4*)(Ah + (size_t)(m0 + row) * 512 + kc + cu * 8);
            *(uint4*)(smem + PJ_AL + row * 144 + cu * 16) =
                *(const uint4*)(Al + (size_t)(m0 + row) * 512 + kc + cu * 8);
            *(uint4*)(smem + PJ_BH + row * 144 + cu * 16) =
                *(const uint4*)(Bh + (size_t)(n0 + row) * 512 + kc + cu * 8);
            *(uint4*)(smem + PJ_BL + row * 144 + cu * 16) =
                *(const uint4*)(Bl + (size_t)(n0 + row) * 512 + kc + cu * 8);
        }
        __syncthreads();
#pragma unroll
        for (int ks = 0; ks < 4; ks++) {
            unsigned ah[4][4], al[4][4], bh4[2][4], bl4[2][4];
#pragma unroll
            for (int mt = 0; mt < 4; mt++) {
                ldm_x4(ah[mt], aAddr + PJ_AH + (mt * 16 * SPD + ks * 16) * 2);
                ldm_x4(al[mt], aAddr + PJ_AL + (mt * 16 * SPD + ks * 16) * 2);
            }
#pragma unroll
            for (int p = 0; p < 2; p++) {
                ldm_x4(bh4[p], bAddr4 + PJ_BH + (p * 16 * SPD + ks * 16) * 2);
                ldm_x4(bl4[p], bAddr4 + PJ_BL + (p * 16 * SPD + ks * 16) * 2);
            }
#pragma unroll
            for (int mt = 0; mt < 4; mt++)
#pragma unroll
                for (int nt = 0; nt < 4; nt++) {
                    unsigned* bh = &bh4[nt >> 1][(nt & 1) * 2];
                    unsigned* bl = &bl4[nt >> 1][(nt & 1) * 2];
                    MMA(c[mt][nt], ah[mt], bh);
                    MMA(c[mt][nt], ah[mt], bl);
                    MMA(c[mt][nt], al[mt], bh);
                }
        }
        __syncthreads();
    }

    if (mode == 1) {
        float* stage = (float*)smem;  // 128 x 129 f32
#pragma unroll
        for (int mt = 0; mt < 4; mt++)
#pragma unroll
            for (int nt = 0; nt < 4; nt++) {
                int r0 = wm + mt * 16 + gid, cc0 = wn + nt * 8 + 2 * tig;
                stage[r0 * 129 + cc0] = c[mt][nt][0];
                stage[r0 * 129 + cc0 + 1] = c[mt][nt][1];
                stage[(r0 + 8) * 129 + cc0] = c[mt][nt][2];
                stage[(r0 + 8) * 129 + cc0 + 1] = c[mt][nt][3];
            }
        __syncthreads();
        const int bb = m0 >> 10, seq0 = m0 & 1023;
        const int m_local = tid & 127, nsel = tid >> 7;
#pragma unroll 8
        for (int rep = 0; rep < 64; rep++) {
            int n_local = rep * 2 + nsel;
            int n = n0 + n_local;
            int hh = n >> 6, dh = n & 63;
            size_t ob = ((size_t)((bb * 8 + hh) * 64 + dh)) * 1024 + seq0 + m_local;
            float f = stage[m_local * 129 + n_local];
            __nv_bfloat16 hbf = __float2bfloat16_rn(f);
            Oh[ob] = hbf;
            Ol[ob] = __float2bfloat16_rn(f - __bfloat162float(hbf));
        }
    } else if (mode == 2) {
#pragma unroll
        for (int mt = 0; mt < 4; mt++)
#pragma unroll
            for (int nt = 0; nt < 4; nt++) {
                int r0 = m0 + wm + mt * 16 + gid, cc0 = n0 + wn + nt * 8 + 2 * tig;
                *(float2*)(Cf + (size_t)r0 * 512 + cc0) =
                    make_float2(c[mt][nt][0], c[mt][nt][1]);
                *(float2*)(Cf + (size_t)(r0 + 8) * 512 + cc0) =
                    make_float2(c[mt][nt][2], c[mt][nt][3]);
            }
    } else {
#pragma unroll
        for (int mt = 0; mt < 4; mt++)
#pragma unroll
            for (int nt = 0; nt < 4; nt++) {
                int r0 = m0 + wm + mt * 16 + gid, cc0 = n0 + wn + nt * 8 + 2 * tig;
                unsigned hp, lp;
                split2(c[mt][nt][0], c[mt][nt][1], hp, lp);
                *(unsigned*)(Oh + (size_t)r0 * 512 + cc0) = hp;
                *(unsigned*)(Ol + (size_t)r0 * 512 + cc0) = lp;
                split2(c[mt][nt][2], c[mt][nt][3], hp, lp);
                *(unsigned*)(Oh + (size_t)(r0 + 8) * 512 + cc0) = hp;
                *(unsigned*)(Ol + (size_t)(r0 + 8) * 512 + cc0) = lp;
            }
    }
}

// ---------------- fused single-pass attention (chunk 64, 2 CTA/SM) --------
// smem: sums 1024B | Q hi/lo 2x18432 | 2 buffers x (KH,KL,VH,VL each 9216)
#define AT_QH 1024
#define AT_QL 19456
#define AT_BUF0 37888
#define AT_BUFSZ 36864
#define KH_OFF 0
#define KL_OFF 9216
#define VH_OFF 18432
#define VL_OFF 27648
#define AT_SMEM 111616

__global__ void __launch_bounds__(256, 2) attn_kernel(float* __restrict__ att)
{
    extern __shared__ char smem[];
    const uint32_t sb = smem_u32(smem);
    float* sums = (float*)smem;  // 128 floats (then inverted in place)
    const int tid = threadIdx.x, w = tid >> 5, lane = tid & 31;
    const int gid = lane >> 2, tig = lane & 3;
    const int bh = blockIdx.x, b = bh >> 3, h = bh & 7;
    const int q0 = blockIdx.y * 128;
    const float SCL = 0.18033688011112042f; // 0.125 * log2(e)
    const int rowsel = (lane & 7) + ((lane >> 4) << 3);
    const int colsel = ((lane >> 3) & 1) * 8;
    const unsigned klane = ((unsigned)rowsel * SPD + colsel) * 2;

    {
        const size_t qoff = ((size_t)(b * 1024 + q0)) * 512 + h * 64;
#pragma unroll
        for (int it = 0; it < 4; it++) {
            int idx = it * 256 + tid, row = idx >> 3, cu = idx & 7;
            *(uint4*)(smem + AT_QH + row * 144 + cu * 16) =
                *(const uint4*)(g_Qh + qoff + (size_t)row * 512 + cu * 8);
            *(uint4*)(smem + AT_QL + row * 144 + cu * 16) =
                *(const uint4*)(g_Ql + qoff + (size_t)row * 512 + cu * 8);
        }
    }
    __syncthreads();
    unsigned aqh[4][4], aql[4][4];
    {
        const uint32_t qa = sb + ((unsigned)(w * 16 + (lane & 15)) * SPD + (lane >> 4) * 8) * 2;
#pragma unroll
        for (int ks = 0; ks < 4; ks++) {
            ldm_x4(aqh[ks], qa + AT_QH + ks * 32);
            ldm_x4(aql[ks], qa + AT_QL + ks * 32);
        }
    }
    __syncthreads();

    const size_t rb0 = (size_t)(b * 1024 + q0 + w * 16 + gid) * 32;
    const size_t rb1 = rb0 + 8 * 32;
    const size_t vbase = (size_t)(bh * 64) * 1024;
    const size_t kbase = (size_t)(b * 1024) * 512 + h * 64;

    float rs0 = 0.0f, rs1 = 0.0f;
    float ctx[8][4];
#pragma unroll
    for (int dt = 0; dt < 8; dt++)
#pragma unroll
        for (int j = 0; j < 4; j++) ctx[dt][j] = 0.0f;

    float* arow0 = att ? att + ((size_t)(bh * 1024 + q0 + w * 16 + gid)) * 1024 : (float*)0;
    float* arow1 = arow0 ? arow0 + (size_t)8 * 1024 : (float*)0;

    // prologue: chunk 0 (64 k-cols: K 64 rows x 128B, V 64 d-rows x 128B)
    {
        const uint32_t kb = sb + AT_BUF0;
#pragma unroll
        for (int it = 0; it < 2; it++) {
            int idx = it * 256 + tid, row = idx >> 3, cu = idx & 7;
            CP16(kb + KH_OFF + row * 144 + cu * 16, g_Kh + kbase + (size_t)row * 512 + cu * 8);
            CP16(kb + KL_OFF + row * 144 + cu * 16, g_Kl + kbase + (size_t)row * 512 + cu * 8);
            CP16(kb + VH_OFF + row * 144 + cu * 16, g_Vth + vbase + (size_t)row * 1024 + cu * 8);
            CP16(kb + VL_OFF + row * 144 + cu * 16, g_Vtl + vbase + (size_t)row * 1024 + cu * 8);
        }
        CP_COMMIT();
    }

    for (int c = 0; c < 16; c++) {
        const int kc = c * 64;
        if (c < 15) {
            const uint32_t kb = sb + AT_BUF0 + ((c + 1) & 1) * AT_BUFSZ;
            const size_t koff = kbase + (size_t)(kc + 64) * 512;
#pragma unroll
            for (int it = 0; it < 2; it++) {
                int idx = it * 256 + tid, row = idx >> 3, cu = idx & 7;
                CP16(kb + KH_OFF + row * 144 + cu * 16, g_Kh + koff + (size_t)row * 512 + cu * 8);
                CP16(kb + KL_OFF + row * 144 + cu * 16, g_Kl + koff + (size_t)row * 512 + cu * 8);
                CP16(kb + VH_OFF + row * 144 + cu * 16,
                     g_Vth + vbase + (size_t)row * 1024 + kc + 64 + cu * 8);
                CP16(kb + VL_OFF + row * 144 + cu * 16,
                     g_Vtl + vbase + (size_t)row * 1024 + kc + 64 + cu * 8);
            }
            CP_COMMIT();
            CP_WAIT(1);
        } else {
            CP_WAIT(0);
        }
        __syncthreads();

        const uint32_t bb = sb + AT_BUF0 + (c & 1) * AT_BUFSZ;
        unsigned aw0[2], aw1[2], sw0[2], sw1[2];
#pragma unroll
        for (int j = 0; j < 2; j++) {
            aw0[j] = g_am[rb0 + (kc >> 5) + j];
            aw1[j] = g_am[rb1 + (kc >> 5) + j];
            sw0[j] = g_sm[rb0 + (kc >> 5) + j];
            sw1[j] = g_sm[rb1 + (kc >> 5) + j];
        }
#pragma unroll
        for (int nt2 = 0; nt2 < 4; nt2++) {
            float cc[2][4];
#pragma unroll
            for (int hh2 = 0; hh2 < 2; hh2++)
#pragma unroll
                for (int j = 0; j < 4; j++) cc[hh2][j] = 0.0f;
#pragma unroll
            for (int ks = 0; ks < 4; ks++) {
                unsigned kh4[4], kl4[4];
                ldm_x4(kh4, bb + KH_OFF + klane + (nt2 * 16 * SPD + ks * 16) * 2);
                ldm_x4(kl4, bb + KL_OFF + klane + (nt2 * 16 * SPD + ks * 16) * 2);
                MMA(cc[0], aqh[ks], &kh4[0]);
                MMA(cc[0], aqh[ks], &kl4[0]);
                MMA(cc[0], aql[ks], &kh4[0]);
                MMA(cc[1], aqh[ks], &kh4[2]);
                MMA(cc[1], aqh[ks], &kl4[2]);
                MMA(cc[1], aql[ks], &kh4[2]);
            }
            unsigned ph[4], pl[4];
#pragma unroll
            for (int half = 0; half < 2; half++) {
                int nt = nt2 * 2 + half;
                int bidx = nt * 8 + 2 * tig;
                unsigned w0 = aw0[bidx >> 5], w1 = aw1[bidx >> 5];
                unsigned s0 = sw0[bidx >> 5], s1 = sw1[bidx >> 5];
                int bo = bidx & 31;
                float t0 = cc[half][0] * SCL, t1 = cc[half][1] * SCL;
                float t2 = cc[half][2] * SCL, t3 = cc[half][3] * SCL;
                if ((w0 >> bo) & 1u) t0 = -1e30f;
                if ((w0 >> (bo + 1)) & 1u) t1 = -1e30f;
                if ((w1 >> bo) & 1u) t2 = -1e30f;
                if ((w1 >> (bo + 1)) & 1u) t3 = -1e30f;
                float p0 = fexp2(t0), p1 = fexp2(t1);
                float p2 = fexp2(t2), p3 = fexp2(t3);
                rs0 += p0 + p1;
                rs1 += p2 + p3;
                if ((s0 >> bo) & 1u) p0 = 0.0f;
                if ((s0 >> (bo + 1)) & 1u) p1 = 0.0f;
                if ((s1 >> bo) & 1u) p2 = 0.0f;
                if ((s1 >> (bo + 1)) & 1u) p3 = 0.0f;
                if (arow0) {
                    *(float2*)(arow0 + kc + bidx) = make_float2(p0, p1);
                    *(float2*)(arow1 + kc + bidx) = make_float2(p2, p3);
                }
                unsigned hp, lp;
                split2(p0, p1, hp, lp);
                ph[half * 2] = hp; pl[half * 2] = lp;
                split2(p2, p3, hp, lp);
                ph[half * 2 + 1] = hp; pl[half * 2 + 1] = lp;
            }
#pragma unroll
            for (int dt2 = 0; dt2 < 4; dt2++) {
                unsigned bvh[4], bvl[4];
                ldm_x4(bvh, bb + VH_OFF + klane + (dt2 * 16 * SPD + nt2 * 16) * 2);
                ldm_x4(bvl, bb + VL_OFF + klane + (dt2 * 16 * SPD + nt2 * 16) * 2);
                MMA(ctx[dt2 * 2], ph, &bvh[0]);
                MMA(ctx[dt2 * 2], ph, &bvl[0]);
                MMA(ctx[dt2 * 2], pl, &bvh[0]);
                MMA(ctx[dt2 * 2 + 1], ph, &bvh[2]);
                MMA(ctx[dt2 * 2 + 1], ph, &bvl[2]);
                MMA(ctx[dt2 * 2 + 1], pl, &bvh[2]);
            }
        }
        __syncthreads();
    }

    rs0 += __shfl_xor_sync(0xffffffffu, rs0, 1);
    rs0 += __shfl_xor_sync(0xffffffffu, rs0, 2);
    rs1 += __shfl_xor_sync(0xffffffffu, rs1, 1);
    rs1 += __shfl_xor_sync(0xffffffffu, rs1, 2);
    if (tig == 0) {
        sums[w * 16 + gid] = rs0;
        sums[w * 16 + gid + 8] = rs1;
    }
    __syncthreads();
    if (tid < 128) sums[tid] = 1.0f / sums[tid];  // invert in place
    __syncthreads();
    const float inv0 = sums[w * 16 + gid];
    const float inv1 = sums[w * 16 + gid + 8];

    // ctx epilogue (normalized)
    {
        size_t r0 = (size_t)(b * 1024 + q0 + w * 16 + gid) * 512 + h * 64;
        size_t r1 = r0 + (size_t)8 * 512;
#pragma unroll
        for (int dt = 0; dt < 8; dt++) {
            int cc0 = dt * 8 + 2 * tig;
            unsigned hp, lp;
            split2(ctx[dt][0] * inv0, ctx[dt][1] * inv0, hp, lp);
            *(unsigned*)(g_Ch + r0 + cc0) = hp;
            *(unsigned*)(g_Cl + r0 + cc0) = lp;
            split2(ctx[dt][2] * inv1, ctx[dt][3] * inv1, hp, lp);
            *(unsigned*)(g_Ch + r1 + cc0) = hp;
            *(unsigned*)(g_Cl + r1 + cc0) = lp;
        }
    }

    // self-normalize this CTA's att rows (512 KB, mostly L2-resident)
    if (att) {
        float4* ab = (float4*)(att + ((size_t)(bh * 1024 + q0)) * 1024);
#pragma unroll 4
        for (int i = tid; i < 128 * 256; i += 256) {
            float s = sums[i >> 8];
            float4 v = ab[i];
            v.x *= s; v.y *= s; v.z *= s; v.w *= s;
            ab[i] = v;
        }
    }
}

// ---------------- residual + LayerNorm ----------------
__global__ void __launch_bounds__(256) ln_kernel(
    const float* __restrict__ proj, const float* __restrict__ res,
    float* __restrict__ out)
{
    __shared__ float reds[8], redq[8];
    const int row = blockIdx.x, tid = threadIdx.x;
    const float* p = proj + (size_t)row * ND;
    const float* rr = res + (size_t)row * ND;
    float x0 = rr[tid] + p[tid];
    float x1 = rr[tid + 256] + p[tid + 256];
    float s = x0 + x1, q = x0 * x0 + x1 * x1;
#pragma unroll
    for (int o = 16; o > 0; o >>= 1) {
        s += __shfl_xor_sync(0xffffffffu, s, o);
        q += __shfl_xor_sync(0xffffffffu, q, o);
    }
    if ((tid & 31) == 0) { reds[tid >> 5] = s; redq[tid >> 5] = q; }
    __syncthreads();
    float ts = 0, tq = 0;
#pragma unroll
    for (int i = 0; i < 8; i++) { ts += reds[i]; tq += redq[i]; }
    float mean = ts * (1.0f / ND);
    float var = tq * (1.0f / ND) - mean * mean;
    float rsv = rsqrtf(var + 1e-5f);
    out[(size_t)row * ND + tid] = (x0 - mean) * rsv;
    out[(size_t)row * ND + tid + 256] = (x1 - mean) * rsv;
}

// ---------------------------------------------------------------------------
extern "C" void kernel_launch(void* const* d_in, const int* in_sizes, int n_in,
                              void* d_out, int out_size)
{
    const float* query = (const float*)d_in[0];
    const float* key   = (const float*)d_in[1];
    const float* value = (const float*)d_in[2];
    const void*  amask = d_in[3];
    const void*  smask = d_in[4];
    const float* Wq = (const float*)d_in[5];
    const float* Wk = (const float*)d_in[6];
    const float* Wv = (const float*)d_in[7];
    const float* Wo = (const float*)d_in[8];

    float* out = (float*)d_out;
    float* att = ((size_t)out_size >= ACT_ELEMS + ATT_ELEMS) ? out + ACT_ELEMS : (float*)0;

    void *pQAh,*pQAl,*pKAh,*pKAl,*pVAh,*pVAl;
    void *pWQh,*pWQl,*pWKh,*pWKl,*pWVh,*pWVl,*pWOh,*pWOl;
    void *pQh,*pQl,*pKh,*pKl,*pVth,*pVtl,*pCh,*pCl,*pPf,*pAm,*pSm;
    cudaGetSymbolAddress(&pQAh, g_QAh); cudaGetSymbolAddress(&pQAl, g_QAl);
    cudaGetSymbolAddress(&pKAh, g_KAh); cudaGetSymbolAddress(&pKAl, g_KAl);
    cudaGetSymbolAddress(&pVAh, g_VAh); cudaGetSymbolAddress(&pVAl, g_VAl);
    cudaGetSymbolAddress(&pWQh, g_WQh); cudaGetSymbolAddress(&pWQl, g_WQl);
    cudaGetSymbolAddress(&pWKh, g_WKh); cudaGetSymbolAddress(&pWKl, g_WKl);
    cudaGetSymbolAddress(&pWVh, g_WVh); cudaGetSymbolAddress(&pWVl, g_WVl);
    cudaGetSymbolAddress(&pWOh, g_WOh); cudaGetSymbolAddress(&pWOl, g_WOl);
    cudaGetSymbolAddress(&pQh, g_Qh);   cudaGetSymbolAddress(&pQl, g_Ql);
    cudaGetSymbolAddress(&pKh, g_Kh);   cudaGetSymbolAddress(&pKl, g_Kl);
    cudaGetSymbolAddress(&pVth, g_Vth); cudaGetSymbolAddress(&pVtl, g_Vtl);
    cudaGetSymbolAddress(&pCh, g_Ch);   cudaGetSymbolAddress(&pCl, g_Cl);
    cudaGetSymbolAddress(&pPf, g_projf);
    cudaGetSymbolAddress(&pAm, g_am);   cudaGetSymbolAddress(&pSm, g_sm);

    cudaFuncSetAttribute(proj_kernel, cudaFuncAttributeMaxDynamicSharedMemorySize, PJ_SMEM);
    cudaFuncSetAttribute(attn_kernel, cudaFuncAttributeMaxDynamicSharedMemorySize, AT_SMEM);

    cudaStream_t s1, s2, s3;
    cudaEvent_t evA, evB, evK, evV;
    cudaStreamCreateWithFlags(&s1, cudaStreamNonBlocking);
    cudaStreamCreateWithFlags(&s2, cudaStreamNonBlocking);
    cudaStreamCreateWithFlags(&s3, cudaStreamNonBlocking);
    cudaEventCreateWithFlags(&evA, cudaEventDisableTiming);
    cudaEventCreateWithFlags(&evB, cudaEventDisableTiming);
    cudaEventCreateWithFlags(&evK, cudaEventDisableTiming);
    cudaEventCreateWithFlags(&evV, cudaEventDisableTiming);

    const int nA4 = (int)(ACT_ELEMS / 4), nW4 = (int)(W_ELEMS / 4);
    dim3 pgrid(TOK / 128, ND / 128);

    detect_mask_kernel<<<1, 256>>>((const unsigned*)amask);
    cudaEventRecord(evA, 0);

    // s1: masks + Wo conversion
    cudaStreamWaitEvent(s1, evA, 0);
    pack_mask_kernel<<<MASK_WORDS / 256, 256, 0, s1>>>(amask, (unsigned*)pAm);
    pack_mask_kernel<<<MASK_WORDS / 256, 256, 0, s1>>>(smask, (unsigned*)pSm);
    conv_split_kernel<<<nW4 / 256, 256, 0, s1>>>((const float4*)Wo,
        (__nv_bfloat16*)pWOh, (__nv_bfloat16*)pWOl, nW4);
    cudaEventRecord(evB, s1);

    // s2: K pipeline
    cudaStreamWaitEvent(s2, evA, 0);
    conv_split_kernel<<<nA4 / 256, 256, 0, s2>>>((const float4*)key,
        (__nv_bfloat16*)pKAh, (__nv_bfloat16*)pKAl, nA4);
    conv_split_kernel<<<nW4 / 256, 256, 0, s2>>>((const float4*)Wk,
        (__nv_bfloat16*)pWKh, (__nv_bfloat16*)pWKl, nW4);
    proj_kernel<<<pgrid, 256, PJ_SMEM, s2>>>((const __nv_bfloat16*)pKAh, (const __nv_bfloat16*)pKAl,
        (const __nv_bfloat16*)pWKh, (const __nv_bfloat16*)pWKl,
        (float*)0, (__nv_bfloat16*)pKh, (__nv_bfloat16*)pKl, 0);
    cudaEventRecord(evK, s2);

    // s3: V pipeline
    cudaStreamWaitEvent(s3, evA, 0);
    conv_split_kernel<<<nA4 / 256, 256, 0, s3>>>((const float4*)value,
        (__nv_bfloat16*)pVAh, (__nv_bfloat16*)pVAl, nA4);
    conv_split_kernel<<<nW4 / 256, 256, 0, s3>>>((const float4*)Wv,
        (__nv_bfloat16*)pWVh, (__nv_bfloat16*)pWVl, nW4);
    proj_kernel<<<pgrid, 256, PJ_SMEM, s3>>>((const __nv_bfloat16*)pVAh, (const __nv_bfloat16*)pVAl,
        (const __nv_bfloat16*)pWVh, (const __nv_bfloat16*)pWVl,
        (float*)0, (__nv_bfloat16*)pVth, (__nv_bfloat16*)pVtl, 1);
    cudaEventRecord(evV, s3);

    // main: Q pipeline
    conv_split_kernel<<<nA4 / 256, 256>>>((const float4*)query,
        (__nv_bfloat16*)pQAh, (__nv_bfloat16*)pQAl, nA4);
    conv_split_kernel<<<nW4 / 256, 256>>>((const float4*)Wq,
        (__nv_bfloat16*)pWQh, (__nv_bfloat16*)pWQl, nW4);
    proj_kernel<<<pgrid, 256, PJ_SMEM>>>((const __nv_bfloat16*)pQAh, (const __nv_bfloat16*)pQAl,
        (const __nv_bfloat16*)pWQh, (const __nv_bfloat16*)pWQl,
        (float*)0, (__nv_bfloat16*)pQh, (__nv_bfloat16*)pQl, 0);

    cudaStreamWaitEvent(0, evB, 0);
    cudaStreamWaitEvent(0, evK, 0);
    cudaStreamWaitEvent(0, evV, 0);
    attn_kernel<<<dim3(NB * NH, NL / 128), 256, AT_SMEM>>>(att);

    proj_kernel<<<pgrid, 256, PJ_SMEM>>>((const __nv_bfloat16*)pCh, (const __nv_bfloat16*)pCl,
        (const __nv_bfloat16*)pWOh, (const __nv_bfloat16*)pWOl,
        (float*)pPf, (__nv_bfloat16*)0, (__nv_bfloat16*)0, 2);
    ln_kernel<<<TOK, 256>>>((const float*)pPf, query, out);

    cudaEventDestroy(evA); cudaEventDestroy(evB);
    cudaEventDestroy(evK); cudaEventDestroy(evV);
    cudaStreamDestroy(s1); cudaStreamDestroy(s2); cudaStreamDestroy(s3);
}

// round 12
// speedup vs baseline: 2.8564x; 1.0586x over previous
#include <cuda_runtime.h>
#include <cuda_bf16.h>
#include <cuda_fp16.h>
#include <math.h>
#include <stdint.h>

#define NB 8
#define NL 1024
#define ND 512
#define NH 8
#define NDH 64
#define TOK (NB * NL)
#define ACT_ELEMS ((size_t)TOK * ND)
#define W_ELEMS ((size_t)ND * ND)
#define ATT_ELEMS ((size_t)NB * NH * NL * NL)
#define MASK_WORDS (ATT_ELEMS / 32)

// per-path staging buffers (no false deps between Q/K/V pipelines)
__device__ __nv_bfloat16 g_QAh[ACT_ELEMS], g_QAl[ACT_ELEMS];
__device__ __nv_bfloat16 g_KAh[ACT_ELEMS], g_KAl[ACT_ELEMS];
__device__ __nv_bfloat16 g_VAh[ACT_ELEMS], g_VAl[ACT_ELEMS];
__device__ __nv_bfloat16 g_WQh[W_ELEMS], g_WQl[W_ELEMS];
__device__ __nv_bfloat16 g_WKh[W_ELEMS], g_WKl[W_ELEMS];
__device__ __nv_bfloat16 g_WVh[W_ELEMS], g_WVl[W_ELEMS];
__device__ __nv_bfloat16 g_WOh[W_ELEMS], g_WOl[W_ELEMS];
__device__ __half       g_Qf[ACT_ELEMS], g_Kf[ACT_ELEMS];     // single f16
__device__ __half       g_Vth[ACT_ELEMS], g_Vtl[ACT_ELEMS];   // [bh*64+d][1024] f16 hi/lo
__device__ __nv_bfloat16 g_Ch[ACT_ELEMS], g_Cl[ACT_ELEMS];
__device__ float        g_projf[ACT_ELEMS];
__device__ unsigned     g_am[MASK_WORDS], g_sm[MASK_WORDS];
__device__ int          g_mask_mode;

// ---------------- helpers ----------------
__device__ __forceinline__ uint32_t smem_u32(const void* p) {
    uint32_t a;
    asm("{ .reg .u64 t; cvta.to.shared.u64 t, %1; cvt.u32.u64 %0, t; }" : "=r"(a) : "l"(p));
    return a;
}
__device__ __forceinline__ void ldm_x4(unsigned r[4], uint32_t a) {
    asm volatile("ldmatrix.sync.aligned.m8n8.x4.shared.b16 {%0,%1,%2,%3}, [%4];"
                 : "=r"(r[0]), "=r"(r[1]), "=r"(r[2]), "=r"(r[3]) : "r"(a) : "memory");
}
#define MMA(c, a, b) \
    asm volatile("mma.sync.aligned.m16n8k16.row.col.f32.bf16.bf16.f32 " \
                 "{%0,%1,%2,%3},{%4,%5,%6,%7},{%8,%9},{%0,%1,%2,%3};" \
                 : "+f"((c)[0]), "+f"((c)[1]), "+f"((c)[2]), "+f"((c)[3]) \
                 : "r"((a)[0]), "r"((a)[1]), "r"((a)[2]), "r"((a)[3]), \
                   "r"((b)[0]), "r"((b)[1]))
#define MMAH(c, a, b) \
    asm volatile("mma.sync.aligned.m16n8k16.row.col.f32.f16.f16.f32 " \
                 "{%0,%1,%2,%3},{%4,%5,%6,%7},{%8,%9},{%0,%1,%2,%3};" \
                 : "+f"((c)[0]), "+f"((c)[1]), "+f"((c)[2]), "+f"((c)[3]) \
                 : "r"((a)[0]), "r"((a)[1]), "r"((a)[2]), "r"((a)[3]), \
                   "r"((b)[0]), "r"((b)[1]))

#define CP16(dst, src) \
    asm volatile("cp.async.cg.shared.global [%0], [%1], 16;" :: "r"(dst), "l"(src) : "memory")
#define CP_COMMIT() asm volatile("cp.async.commit_group;" ::: "memory")
#define CP_WAIT(n)  asm volatile("cp.async.wait_group %0;" :: "n"(n) : "memory")

__device__ __forceinline__ void split2(float f0, float f1, unsigned& hp, unsigned& lp) {
    __nv_bfloat16 h0 = __float2bfloat16_rn(f0), h1 = __float2bfloat16_rn(f1);
    __nv_bfloat16 l0 = __float2bfloat16_rn(f0 - __bfloat162float(h0));
    __nv_bfloat16 l1 = __float2bfloat16_rn(f1 - __bfloat162float(h1));
    hp = (unsigned)__bfloat16_as_ushort(h0) | ((unsigned)__bfloat16_as_ushort(h1) << 16);
    lp = (unsigned)__bfloat16_as_ushort(l0) | ((unsigned)__bfloat16_as_ushort(l1) << 16);
}
__device__ __forceinline__ void split2h(float f0, float f1, unsigned& hp, unsigned& lp) {
    __half h0 = __float2half_rn(f0), h1 = __float2half_rn(f1);
    __half l0 = __float2half_rn(f0 - __half2float(h0));
    __half l1 = __float2half_rn(f1 - __half2float(h1));
    hp = (unsigned)__half_as_ushort(h0) | ((unsigned)__half_as_ushort(h1) << 16);
    lp = (unsigned)__half_as_ushort(l0) | ((unsigned)__half_as_ushort(l1) << 16);
}

// degree-4 exp2 on fma pipe; rel err ~3e-6
__device__ __forceinline__ float fexp2(float x) {
    x = fmaxf(fminf(x, 120.0f), -126.0f);
    float fl = floorf(x);
    float f = x - fl;
    float p = 1.35557472e-2f;
    p = fmaf(p, f, 5.20323690e-2f);
    p = fmaf(p, f, 2.41379774e-1f);
    p = fmaf(p, f, 6.93018210e-1f);
    p = fmaf(p, f, 1.00000370f);
    return __int_as_float(__float_as_int(p) + (((int)fl) << 23));
}

// ---------------- prep kernels ----------------
__global__ void detect_mask_kernel(const unsigned* __restrict__ m) {
    __shared__ int f32flag, u8flag;
    if (threadIdx.x == 0) { f32flag = 0; u8flag = 0; }
    __syncthreads();
    int lf = 0, lu = 0;
    for (int i = threadIdx.x; i < 4096; i += blockDim.x) {
        unsigned w = m[i];
        if (w == 0x3f800000u) lf = 1;
        else if (w > 1u) lu = 1;
    }
    if (lf) atomicOr(&f32flag, 1);
    if (lu) atomicOr(&u8flag, 1);
    __syncthreads();
    if (threadIdx.x == 0) g_mask_mode = f32flag ? 2 : (u8flag ? 0 : 1);
}

__global__ void pack_mask_kernel(const void* __restrict__ m, unsigned* __restrict__ out) {
    int w = blockIdx.x * 256 + threadIdx.x;
    if (w >= (int)MASK_WORDS) return;
    int mode = g_mask_mode;
    unsigned bits = 0;
    if (mode == 0) {
        const unsigned* p = (const unsigned*)m + (size_t)w * 8;
#pragma unroll
        for (int j = 0; j < 8; j++) {
            unsigned v = __vcmpne4(p[j], 0u);
            bits |= ((((v & 0x01010101u) * 0x01020408u) >> 24) & 0xFu) << (j * 4);
        }
    } else if (mode == 1) {
        const int* p = (const int*)m + (size_t)w * 32;
#pragma unroll
        for (int j = 0; j < 32; j++) bits |= (unsigned)(p[j] != 0) << j;
    } else {
        const float* p = (const float*)m + (size_t)w * 32;
#pragma unroll
        for (int j = 0; j < 32; j++) bits |= (unsigned)(p[j] != 0.0f) << j;
    }
    out[w] = bits;
}

__global__ void conv_split_kernel(const float4* __restrict__ x,
                                  __nv_bfloat16* __restrict__ hi,
                                  __nv_bfloat16* __restrict__ lo, int n4) {
    int i = blockIdx.x * 256 + threadIdx.x;
    if (i >= n4) return;
    float4 v = x[i];
    unsigned h0, l0, h1, l1;
    split2(v.x, v.y, h0, l0);
    split2(v.z, v.w, h1, l1);
    ((uint2*)hi)[i] = make_uint2(h0, h1);
    ((uint2*)lo)[i] = make_uint2(l0, l1);
}

// ---------------- projection GEMM (mma.sync, 3-term split bf16) ------------
// mode 0: f16 single row-major out; 1: V head-transposed f16 hi/lo; 2: f32.
#define SPD 72
#define PJ_AH 0
#define PJ_AL 18432
#define PJ_BH 36864
#define PJ_BL 55296
#define PJ_SMEM 73728

__global__ void __launch_bounds__(256) proj_kernel(
    const __nv_bfloat16* __restrict__ Ah, const __nv_bfloat16* __restrict__ Al,
    const __nv_bfloat16* __restrict__ Bh, const __nv_bfloat16* __restrict__ Bl,
    float* __restrict__ Cf, __half* __restrict__ Oh, __half* __restrict__ Ol,
    int mode)
{
    extern __shared__ char smem[];
    const uint32_t sb = smem_u32(smem);
    const int tid = threadIdx.x, w = tid >> 5, lane = tid & 31;
    const int gid = lane >> 2, tig = lane & 3;
    const int m0 = blockIdx.x * 128, n0 = blockIdx.y * 128;
    const int wm = (w >> 2) * 64, wn = (w & 3) * 32;
    const int rowsel = (lane & 7) + ((lane >> 4) << 3);
    const int colsel = ((lane >> 3) & 1) * 8;

    float c[4][4][4];
#pragma unroll
    for (int mt = 0; mt < 4; mt++)
#pragma unroll
        for (int nt = 0; nt < 4; nt++)
#pragma unroll
            for (int j = 0; j < 4; j++) c[mt][nt][j] = 0.0f;

    const uint32_t aAddr = sb + ((unsigned)(wm + (lane & 15)) * SPD + (lane >> 4) * 8) * 2;
    const uint32_t bAddr4 = sb + ((unsigned)(wn + rowsel) * SPD + colsel) * 2;

    for (int kc = 0; kc < 512; kc += 64) {
#pragma unroll
        for (int it = 0; it < 4; it++) {
            int idx = it * 256 + tid, row = idx >> 3, cu = idx & 7;
            *(uint4*)(smem + PJ_AH + row * 144 + cu * 16) =
                *(const uint4*)(Ah + (size_t)(m0 + row) * 512 + kc + cu * 8);
            *(uint4*)(smem + PJ_AL + row * 144 + cu * 16) =
                *(const uint4*)(Al + (size_t)(m0 + row) * 512 + kc + cu * 8);
            *(uint4*)(smem + PJ_BH + row * 144 + cu * 16) =
                *(const uint4*)(Bh + (size_t)(n0 + row) * 512 + kc + cu * 8);
            *(uint4*)(smem + PJ_BL + row * 144 + cu * 16) =
                *(const uint4*)(Bl + (size_t)(n0 + row) * 512 + kc + cu * 8);
        }
        __syncthreads();
#pragma unroll
        for (int ks = 0; ks < 4; ks++) {
            unsigned ah[4][4], al[4][4], bh4[2][4], bl4[2][4];
#pragma unroll
            for (int mt = 0; mt < 4; mt++) {
                ldm_x4(ah[mt], aAddr + PJ_AH + (mt * 16 * SPD + ks * 16) * 2);
                ldm_x4(al[mt], aAddr + PJ_AL + (mt * 16 * SPD + ks * 16) * 2);
            }
#pragma unroll
            for (int p = 0; p < 2; p++) {
                ldm_x4(bh4[p], bAddr4 + PJ_BH + (p * 16 * SPD + ks * 16) * 2);
                ldm_x4(bl4[p], bAddr4 + PJ_BL + (p * 16 * SPD + ks * 16) * 2);
            }
#pragma unroll
            for (int mt = 0; mt < 4; mt++)
#pragma unroll
                for (int nt = 0; nt < 4; nt++) {
                    unsigned* bh = &bh4[nt >> 1][(nt & 1) * 2];
                    unsigned* bl = &bl4[nt >> 1][(nt & 1) * 2];
                    MMA(c[mt][nt], ah[mt], bh);
                    MMA(c[mt][nt], ah[mt], bl);
                    MMA(c[mt][nt], al[mt], bh);
                }
        }
        __syncthreads();
    }

    if (mode == 1) {
        float* stage = (float*)smem;  // 128 x 129 f32
#pragma unroll
        for (int mt = 0; mt < 4; mt++)
#pragma unroll
            for (int nt = 0; nt < 4; nt++) {
                int r0 = wm + mt * 16 + gid, cc0 = wn + nt * 8 + 2 * tig;
                stage[r0 * 129 + cc0] = c[mt][nt][0];
                stage[r0 * 129 + cc0 + 1] = c[mt][nt][1];
                stage[(r0 + 8) * 129 + cc0] = c[mt][nt][2];
                stage[(r0 + 8) * 129 + cc0 + 1] = c[mt][nt][3];
            }
        __syncthreads();
        const int bb = m0 >> 10, seq0 = m0 & 1023;
        const int m_local = tid & 127, nsel = tid >> 7;
#pragma unroll 8
        for (int rep = 0; rep < 64; rep++) {
            int n_local = rep * 2 + nsel;
            int n = n0 + n_local;
            int hh = n >> 6, dh = n & 63;
            size_t ob = ((size_t)((bb * 8 + hh) * 64 + dh)) * 1024 + seq0 + m_local;
            float f = stage[m_local * 129 + n_local];
            __half hv = __float2half_rn(f);
            Oh[ob] = hv;
            Ol[ob] = __float2half_rn(f - __half2float(hv));
        }
    } else if (mode == 2) {
#pragma unroll
        for (int mt = 0; mt < 4; mt++)
#pragma unroll
            for (int nt = 0; nt < 4; nt++) {
                int r0 = m0 + wm + mt * 16 + gid, cc0 = n0 + wn + nt * 8 + 2 * tig;
                *(float2*)(Cf + (size_t)r0 * 512 + cc0) =
                    make_float2(c[mt][nt][0], c[mt][nt][1]);
                *(float2*)(Cf + (size_t)(r0 + 8) * 512 + cc0) =
                    make_float2(c[mt][nt][2], c[mt][nt][3]);
            }
    } else {
        // mode 0: single f16 row-major
#pragma unroll
        for (int mt = 0; mt < 4; mt++)
#pragma unroll
            for (int nt = 0; nt < 4; nt++) {
                int r0 = m0 + wm + mt * 16 + gid, cc0 = n0 + wn + nt * 8 + 2 * tig;
                __half2 p0 = __floats2half2_rn(c[mt][nt][0], c[mt][nt][1]);
                __half2 p1 = __floats2half2_rn(c[mt][nt][2], c[mt][nt][3]);
                *(__half2*)(Oh + (size_t)r0 * 512 + cc0) = p0;
                *(__half2*)(Oh + (size_t)(r0 + 8) * 512 + cc0) = p1;
            }
    }
}

// ---------------- fused single-pass attention (f16 QK single-term) --------
// smem: sums 1024 | Q f16 18432 | 2 x (K 9216 + VH 9216 + VL 9216)
#define AT_Q 1024
#define AT_BUF0 19456
#define AT_BUFSZ 27648
#define K_OFF 0
#define VH_OFF 9216
#define VL_OFF 18432
#define AT_SMEM 74752

__global__ void __launch_bounds__(256, 2) attn_kernel(float* __restrict__ att)
{
    extern __shared__ char smem[];
    const uint32_t sb = smem_u32(smem);
    float* sums = (float*)smem;
    const int tid = threadIdx.x, w = tid >> 5, lane = tid & 31;
    const int gid = lane >> 2, tig = lane & 3;
    const int bh = blockIdx.x, b = bh >> 3, h = bh & 7;
    const int q0 = blockIdx.y * 128;
    const float SCL = 0.18033688011112042f; // 0.125 * log2(e)
    const int rowsel = (lane & 7) + ((lane >> 4) << 3);
    const int colsel = ((lane >> 3) & 1) * 8;
    const unsigned klane = ((unsigned)rowsel * SPD + colsel) * 2;

    {
        const size_t qoff = ((size_t)(b * 1024 + q0)) * 512 + h * 64;
#pragma unroll
        for (int it = 0; it < 4; it++) {
            int idx = it * 256 + tid, row = idx >> 3, cu = idx & 7;
            *(uint4*)(smem + AT_Q + row * 144 + cu * 16) =
                *(const uint4*)(g_Qf + qoff + (size_t)row * 512 + cu * 8);
        }
    }
    __syncthreads();
    unsigned aq[4][4];
    {
        const uint32_t qa = sb + AT_Q + ((unsigned)(w * 16 + (lane & 15)) * SPD + (lane >> 4) * 8) * 2;
#pragma unroll
        for (int ks = 0; ks < 4; ks++) ldm_x4(aq[ks], qa + ks * 32);
    }
    __syncthreads();

    const size_t rb0 = (size_t)(b * 1024 + q0 + w * 16 + gid) * 32;
    const size_t rb1 = rb0 + 8 * 32;
    const size_t vbase = (size_t)(bh * 64) * 1024;
    const size_t kbase = (size_t)(b * 1024) * 512 + h * 64;

    float rs0 = 0.0f, rs1 = 0.0f;
    float ctx[8][4];
#pragma unroll
    for (int dt = 0; dt < 8; dt++)
#pragma unroll
        for (int j = 0; j < 4; j++) ctx[dt][j] = 0.0f;

    float* arow0 = att ? att + ((size_t)(bh * 1024 + q0 + w * 16 + gid)) * 1024 : (float*)0;
    float* arow1 = arow0 ? arow0 + (size_t)8 * 1024 : (float*)0;

    // prologue: chunk 0
    {
        const uint32_t kb = sb + AT_BUF0;
#pragma unroll
        for (int it = 0; it < 2; it++) {
            int idx = it * 256 + tid, row = idx >> 3, cu = idx & 7;
            CP16(kb + K_OFF + row * 144 + cu * 16, g_Kf + kbase + (size_t)row * 512 + cu * 8);
            CP16(kb + VH_OFF + row * 144 + cu * 16, g_Vth + vbase + (size_t)row * 1024 + cu * 8);
            CP16(kb + VL_OFF + row * 144 + cu * 16, g_Vtl + vbase + (size_t)row * 1024 + cu * 8);
        }
        CP_COMMIT();
    }

    for (int c = 0; c < 16; c++) {
        const int kc = c * 64;
        if (c < 15) {
            const uint32_t kb = sb + AT_BUF0 + ((c + 1) & 1) * AT_BUFSZ;
            const size_t koff = kbase + (size_t)(kc + 64) * 512;
#pragma unroll
            for (int it = 0; it < 2; it++) {
                int idx = it * 256 + tid, row = idx >> 3, cu = idx & 7;
                CP16(kb + K_OFF + row * 144 + cu * 16, g_Kf + koff + (size_t)row * 512 + cu * 8);
                CP16(kb + VH_OFF + row * 144 + cu * 16,
                     g_Vth + vbase + (size_t)row * 1024 + kc + 64 + cu * 8);
                CP16(kb + VL_OFF + row * 144 + cu * 16,
                     g_Vtl + vbase + (size_t)row * 1024 + kc + 64 + cu * 8);
            }
            CP_COMMIT();
            CP_WAIT(1);
        } else {
            CP_WAIT(0);
        }
        __syncthreads();

        const uint32_t bb = sb + AT_BUF0 + (c & 1) * AT_BUFSZ;
        unsigned aw0[2], aw1[2], sw0[2], sw1[2];
#pragma unroll
        for (int j = 0; j < 2; j++) {
            aw0[j] = g_am[rb0 + (kc >> 5) + j];
            aw1[j] = g_am[rb1 + (kc >> 5) + j];
            sw0[j] = g_sm[rb0 + (kc >> 5) + j];
            sw1[j] = g_sm[rb1 + (kc >> 5) + j];
        }
#pragma unroll
        for (int nt2 = 0; nt2 < 4; nt2++) {
            float cc[2][4];
#pragma unroll
            for (int hh2 = 0; hh2 < 2; hh2++)
#pragma unroll
                for (int j = 0; j < 4; j++) cc[hh2][j] = 0.0f;
#pragma unroll
            for (int ks = 0; ks < 4; ks++) {
                unsigned kh4[4];
                ldm_x4(kh4, bb + K_OFF + klane + (nt2 * 16 * SPD + ks * 16) * 2);
                MMAH(cc[0], aq[ks], &kh4[0]);
                MMAH(cc[1], aq[ks], &kh4[2]);
            }
            unsigned ph[4], pl[4];
#pragma unroll
            for (int half = 0; half < 2; half++) {
                int nt = nt2 * 2 + half;
                int bidx = nt * 8 + 2 * tig;
                unsigned w0 = aw0[bidx >> 5], w1 = aw1[bidx >> 5];
                unsigned s0 = sw0[bidx >> 5], s1 = sw1[bidx >> 5];
                int bo = bidx & 31;
                float t0 = cc[half][0] * SCL, t1 = cc[half][1] * SCL;
                float t2 = cc[half][2] * SCL, t3 = cc[half][3] * SCL;
                if ((w0 >> bo) & 1u) t0 = -1e30f;
                if ((w0 >> (bo + 1)) & 1u) t1 = -1e30f;
                if ((w1 >> bo) & 1u) t2 = -1e30f;
                if ((w1 >> (bo + 1)) & 1u) t3 = -1e30f;
                float p0 = fexp2(t0), p1 = fexp2(t1);
                float p2 = fexp2(t2), p3 = fexp2(t3);
                rs0 += p0 + p1;
                rs1 += p2 + p3;
                if ((s0 >> bo) & 1u) p0 = 0.0f;
                if ((s0 >> (bo + 1)) & 1u) p1 = 0.0f;
                if ((s1 >> bo) & 1u) p2 = 0.0f;
                if ((s1 >> (bo + 1)) & 1u) p3 = 0.0f;
                if (arow0) {
                    *(float2*)(arow0 + kc + bidx) = make_float2(p0, p1);
                    *(float2*)(arow1 + kc + bidx) = make_float2(p2, p3);
                }
                unsigned hp, lp;
                split2h(p0, p1, hp, lp);
                ph[half * 2] = hp; pl[half * 2] = lp;
                split2h(p2, p3, hp, lp);
                ph[half * 2 + 1] = hp; pl[half * 2 + 1] = lp;
            }
#pragma unroll
            for (int dt2 = 0; dt2 < 4; dt2++) {
                unsigned bvh[4], bvl[4];
                ldm_x4(bvh, bb + VH_OFF + klane + (dt2 * 16 * SPD + nt2 * 16) * 2);
                ldm_x4(bvl, bb + VL_OFF + klane + (dt2 * 16 * SPD + nt2 * 16) * 2);
                MMAH(ctx[dt2 * 2], ph, &bvh[0]);
                MMAH(ctx[dt2 * 2], ph, &bvl[0]);
                MMAH(ctx[dt2 * 2], pl, &bvh[0]);
                MMAH(ctx[dt2 * 2 + 1], ph, &bvh[2]);
                MMAH(ctx[dt2 * 2 + 1], ph, &bvl[2]);
                MMAH(ctx[dt2 * 2 + 1], pl, &bvh[2]);
            }
        }
        __syncthreads();
    }

    rs0 += __shfl_xor_sync(0xffffffffu, rs0, 1);
    rs0 += __shfl_xor_sync(0xffffffffu, rs0, 2);
    rs1 += __shfl_xor_sync(0xffffffffu, rs1, 1);
    rs1 += __shfl_xor_sync(0xffffffffu, rs1, 2);
    if (tig == 0) {
        sums[w * 16 + gid] = rs0;
        sums[w * 16 + gid + 8] = rs1;
    }
    __syncthreads();
    if (tid < 128) sums[tid] = 1.0f / sums[tid];
    __syncthreads();
    const float inv0 = sums[w * 16 + gid];
    const float inv1 = sums[w * 16 + gid + 8];

    // ctx epilogue (normalized, bf16 hi/lo for Wo projection)
    {
        size_t r0 = (size_t)(b * 1024 + q0 + w * 16 + gid) * 512 + h * 64;
        size_t r1 = r0 + (size_t)8 * 512;
#pragma unroll
        for (int dt = 0; dt < 8; dt++) {
            int cc0 = dt * 8 + 2 * tig;
            unsigned hp, lp;
            split2(ctx[dt][0] * inv0, ctx[dt][1] * inv0, hp, lp);
            *(unsigned*)(g_Ch + r0 + cc0) = hp;
            *(unsigned*)(g_Cl + r0 + cc0) = lp;
            split2(ctx[dt][2] * inv1, ctx[dt][3] * inv1, hp, lp);
            *(unsigned*)(g_Ch + r1 + cc0) = hp;
            *(unsigned*)(g_Cl + r1 + cc0) = lp;
        }
    }

    // self-normalize this CTA's att rows (512 KB, mostly L2-resident)
    if (att) {
        float4* ab = (float4*)(att + ((size_t)(bh * 1024 + q0)) * 1024);
#pragma unroll 4
        for (int i = tid; i < 128 * 256; i += 256) {
            float s = sums[i >> 8];
            float4 v = ab[i];
            v.x *= s; v.y *= s; v.z *= s; v.w *= s;
            ab[i] = v;
        }
    }
}

// ---------------- residual + LayerNorm ----------------
__global__ void __launch_bounds__(256) ln_kernel(
    const float* __restrict__ proj, const float* __restrict__ res,
    float* __restrict__ out)
{
    __shared__ float reds[8], redq[8];
    const int row = blockIdx.x, tid = threadIdx.x;
    const float* p = proj + (size_t)row * ND;
    const float* rr = res + (size_t)row * ND;
    float x0 = rr[tid] + p[tid];
    float x1 = rr[tid + 256] + p[tid + 256];
    float s = x0 + x1, q = x0 * x0 + x1 * x1;
#pragma unroll
    for (int o = 16; o > 0; o >>= 1) {
        s += __shfl_xor_sync(0xffffffffu, s, o);
        q += __shfl_xor_sync(0xffffffffu, q, o);
    }
    if ((tid & 31) == 0) { reds[tid >> 5] = s; redq[tid >> 5] = q; }
    __syncthreads();
    float ts = 0, tq = 0;
#pragma unroll
    for (int i = 0; i < 8; i++) { ts += reds[i]; tq += redq[i]; }
    float mean = ts * (1.0f / ND);
    float var = tq * (1.0f / ND) - mean * mean;
    float rsv = rsqrtf(var + 1e-5f);
    out[(size_t)row * ND + tid] = (x0 - mean) * rsv;
    out[(size_t)row * ND + tid + 256] = (x1 - mean) * rsv;
}

// ---------------------------------------------------------------------------
extern "C" void kernel_launch(void* const* d_in, const int* in_sizes, int n_in,
                              void* d_out, int out_size)
{
    const float* query = (const float*)d_in[0];
    const float* key   = (const float*)d_in[1];
    const float* value = (const float*)d_in[2];
    const void*  amask = d_in[3];
    const void*  smask = d_in[4];
    const float* Wq = (const float*)d_in[5];
    const float* Wk = (const float*)d_in[6];
    const float* Wv = (const float*)d_in[7];
    const float* Wo = (const float*)d_in[8];

    float* out = (float*)d_out;
    float* att = ((size_t)out_size >= ACT_ELEMS + ATT_ELEMS) ? out + ACT_ELEMS : (float*)0;

    void *pQAh,*pQAl,*pKAh,*pKAl,*pVAh,*pVAl;
    void *pWQh,*pWQl,*pWKh,*pWKl,*pWVh,*pWVl,*pWOh,*pWOl;
    void *pQf,*pKf,*pVth,*pVtl,*pCh,*pCl,*pPf,*pAm,*pSm;
    cudaGetSymbolAddress(&pQAh, g_QAh); cudaGetSymbolAddress(&pQAl, g_QAl);
    cudaGetSymbolAddress(&pKAh, g_KAh); cudaGetSymbolAddress(&pKAl, g_KAl);
    cudaGetSymbolAddress(&pVAh, g_VAh); cudaGetSymbolAddress(&pVAl, g_VAl);
    cudaGetSymbolAddress(&pWQh, g_WQh); cudaGetSymbolAddress(&pWQl, g_WQl);
    cudaGetSymbolAddress(&pWKh, g_WKh); cudaGetSymbolAddress(&pWKl, g_WKl);
    cudaGetSymbolAddress(&pWVh, g_WVh); cudaGetSymbolAddress(&pWVl, g_WVl);
    cudaGetSymbolAddress(&pWOh, g_WOh); cudaGetSymbolAddress(&pWOl, g_WOl);
    cudaGetSymbolAddress(&pQf, g_Qf);   cudaGetSymbolAddress(&pKf, g_Kf);
    cudaGetSymbolAddress(&pVth, g_Vth); cudaGetSymbolAddress(&pVtl, g_Vtl);
    cudaGetSymbolAddress(&pCh, g_Ch);   cudaGetSymbolAddress(&pCl, g_Cl);
    cudaGetSymbolAddress(&pPf, g_projf);
    cudaGetSymbolAddress(&pAm, g_am);   cudaGetSymbolAddress(&pSm, g_sm);

    cudaFuncSetAttribute(proj_kernel, cudaFuncAttributeMaxDynamicSharedMemorySize, PJ_SMEM);
    cudaFuncSetAttribute(attn_kernel, cudaFuncAttributeMaxDynamicSharedMemorySize, AT_SMEM);

    cudaStream_t s1, s2, s3;
    cudaEvent_t evA, evB, evK, evV;
    cudaStreamCreateWithFlags(&s1, cudaStreamNonBlocking);
    cudaStreamCreateWithFlags(&s2, cudaStreamNonBlocking);
    cudaStreamCreateWithFlags(&s3, cudaStreamNonBlocking);
    cudaEventCreateWithFlags(&evA, cudaEventDisableTiming);
    cudaEventCreateWithFlags(&evB, cudaEventDisableTiming);
    cudaEventCreateWithFlags(&evK, cudaEventDisableTiming);
    cudaEventCreateWithFlags(&evV, cudaEventDisableTiming);

    const int nA4 = (int)(ACT_ELEMS / 4), nW4 = (int)(W_ELEMS / 4);
    dim3 pgrid(TOK / 128, ND / 128);

    detect_mask_kernel<<<1, 256>>>((const unsigned*)amask);
    cudaEventRecord(evA, 0);

    // s1: masks + Wo conversion
    cudaStreamWaitEvent(s1, evA, 0);
    pack_mask_kernel<<<MASK_WORDS / 256, 256, 0, s1>>>(amask, (unsigned*)pAm);
    pack_mask_kernel<<<MASK_WORDS / 256, 256, 0, s1>>>(smask, (unsigned*)pSm);
    conv_split_kernel<<<nW4 / 256, 256, 0, s1>>>((const float4*)Wo,
        (__nv_bfloat16*)pWOh, (__nv_bfloat16*)pWOl, nW4);
    cudaEventRecord(evB, s1);

    // s2: K pipeline
    cudaStreamWaitEvent(s2, evA, 0);
    conv_split_kernel<<<nA4 / 256, 256, 0, s2>>>((const float4*)key,
        (__nv_bfloat16*)pKAh, (__nv_bfloat16*)pKAl, nA4);
    conv_split_kernel<<<nW4 / 256, 256, 0, s2>>>((const float4*)Wk,
        (__nv_bfloat16*)pWKh, (__nv_bfloat16*)pWKl, nW4);
    proj_kernel<<<pgrid, 256, PJ_SMEM, s2>>>((const __nv_bfloat16*)pKAh, (const __nv_bfloat16*)pKAl,
        (const __nv_bfloat16*)pWKh, (const __nv_bfloat16*)pWKl,
        (float*)0, (__half*)pKf, (__half*)0, 0);
    cudaEventRecord(evK, s2);

    // s3: V pipeline
    cudaStreamWaitEvent(s3, evA, 0);
    conv_split_kernel<<<nA4 / 256, 256, 0, s3>>>((const float4*)value,
        (__nv_bfloat16*)pVAh, (__nv_bfloat16*)pVAl, nA4);
    conv_split_kernel<<<nW4 / 256, 256, 0, s3>>>((const float4*)Wv,
        (__nv_bfloat16*)pWVh, (__nv_bfloat16*)pWVl, nW4);
    proj_kernel<<<pgrid, 256, PJ_SMEM, s3>>>((const __nv_bfloat16*)pVAh, (const __nv_bfloat16*)pVAl,
        (const __nv_bfloat16*)pWVh, (const __nv_bfloat16*)pWVl,
        (float*)0, (__half*)pVth, (__half*)pVtl, 1);
    cudaEventRecord(evV, s3);

    // main: Q pipeline
    conv_split_kernel<<<nA4 / 256, 256>>>((const float4*)query,
        (__nv_bfloat16*)pQAh, (__nv_bfloat16*)pQAl, nA4);
    conv_split_kernel<<<nW4 / 256, 256>>>((const float4*)Wq,
        (__nv_bfloat16*)pWQh, (__nv_bfloat16*)pWQl, nW4);
    proj_kernel<<<pgrid, 256, PJ_SMEM>>>((const __nv_bfloat16*)pQAh, (const __nv_bfloat16*)pQAl,
        (const __nv_bfloat16*)pWQh, (const __nv_bfloat16*)pWQl,
        (float*)0, (__half*)pQf, (__half*)0, 0);

    cudaStreamWaitEvent(0, evB, 0);
    cudaStreamWaitEvent(0, evK, 0);
    cudaStreamWaitEvent(0, evV, 0);
    attn_kernel<<<dim3(NB * NH, NL / 128), 256, AT_SMEM>>>(att);

    proj_kernel<<<pgrid, 256, PJ_SMEM>>>((const __nv_bfloat16*)pCh, (const __nv_bfloat16*)pCl,
        (const __nv_bfloat16*)pWOh, (const __nv_bfloat16*)pWOl,
        (float*)pPf, (__half*)0, (__half*)0, 2);
    ln_kernel<<<TOK, 256>>>((const float*)pPf, query, out);

    cudaEventDestroy(evA); cudaEventDestroy(evB);
    cudaEventDestroy(evK); cudaEventDestroy(evV);
    cudaStreamDestroy(s1); cudaStreamDestroy(s2); cudaStreamDestroy(s3);
}